// round 8
// baseline (speedup 1.0000x reference)
#include <cuda_runtime.h>
#include <cuda_bf16.h>
#include <math.h>
#include <stdint.h>

// Problem constants (fixed shapes for this bench)
constexpr int Bc  = 4;
constexpr int Lc  = 2048;
constexpr int Dc  = 512;
constexpr int Hc  = 8;
constexpr int DKc = 64;
constexpr int UMAX = 64;   // safety cap for top-k storage (actual U = 40)
constexpr int NX  = Bc * Lc * Dc;     // elements in one (B,L,D) tensor

// ---------------- scratch (device globals; no allocation allowed) ------------
__device__ float g_Q[Bc*Hc*Lc*DKc];      // (b,h,l,d)  16 MB
__device__ float g_K[Bc*Hc*Lc*DKc];      // 16 MB
__device__ float g_V[Bc*Hc*Lc*DKc];      // 16 MB
__device__ float g_ctx[Bc*Lc*Dc];        // (b,l,h,d) = (b,l,D)  16 MB
__device__ float g_M[Bc*Hc*Lc];          // sparsity measure
__device__ int   g_top[Bc*Hc*UMAX];      // top-u indices per (b,h)
__device__ float g_vmean[Bc*Hc*DKc];     // V mean over L
__device__ float g_vpart[Bc*Hc*8*DKc];   // partial V sums

// hi/lo tf32 planes (pre-split, stored as fp32 bit patterns)
__device__ uint32_t g_hiQ[NX], g_loQ[NX];
__device__ uint32_t g_hiK[NX], g_loK[NX];
__device__ uint32_t g_hiV[NX], g_loV[NX];
__device__ uint32_t g_hiC[NX], g_loC[NX];
__device__ uint32_t g_hiW[4*Dc*Dc], g_loW[4*Dc*Dc];

// ---------------- tf32 helpers ------------------------------------------------
__device__ __forceinline__ uint32_t f2tf32(float x) {
    uint32_t u;
    asm("cvt.rna.tf32.f32 %0, %1;" : "=r"(u) : "f"(x));
    return u;
}

__device__ __forceinline__ void mma_tf32(float (&d)[4], const uint32_t (&a)[4],
                                         const uint32_t (&b)[2]) {
    asm volatile(
        "mma.sync.aligned.m16n8k8.row.col.f32.tf32.tf32.f32 "
        "{%0,%1,%2,%3}, {%4,%5,%6,%7}, {%8,%9}, {%0,%1,%2,%3};"
        : "+f"(d[0]), "+f"(d[1]), "+f"(d[2]), "+f"(d[3])
        : "r"(a[0]), "r"(a[1]), "r"(a[2]), "r"(a[3]), "r"(b[0]), "r"(b[1]));
}

__device__ __forceinline__ void split2(float x, uint32_t& hi, uint32_t& lo) {
    hi = f2tf32(x);
    lo = f2tf32(x - __uint_as_float(hi));
}

__device__ __forceinline__ void cp16(void* smem, const void* gmem) {
    uint32_t s = (uint32_t)__cvta_generic_to_shared(smem);
    asm volatile("cp.async.cg.shared.global [%0], [%1], 16;" :: "r"(s), "l"(gmem));
}
__device__ __forceinline__ void cp_commit() {
    asm volatile("cp.async.commit_group;" ::: "memory");
}
template<int N>
__device__ __forceinline__ void cp_wait() {
    asm volatile("cp.async.wait_group %0;" :: "n"(N) : "memory");
}

// ---------------- pre-split kernels ------------------------------------------
__global__ __launch_bounds__(256) void presplit_x_kernel(
    const float* __restrict__ src, uint32_t* __restrict__ hi,
    uint32_t* __restrict__ lo, int n4)
{
    int i = blockIdx.x * 256 + threadIdx.x;
    if (i >= n4) return;
    float4 v = reinterpret_cast<const float4*>(src)[i];
    uint4 h, l;
    split2(v.x, h.x, l.x); split2(v.y, h.y, l.y);
    split2(v.z, h.z, l.z); split2(v.w, h.w, l.w);
    reinterpret_cast<uint4*>(hi)[i] = h;
    reinterpret_cast<uint4*>(lo)[i] = l;
}

__global__ __launch_bounds__(256) void presplit_w4_kernel(
    const float* __restrict__ w0, const float* __restrict__ w1,
    const float* __restrict__ w2, const float* __restrict__ w3)
{
    const float* srcs[4] = {w0, w1, w2, w3};
    int wsel = blockIdx.y;
    const float* src = srcs[wsel];
    int i = blockIdx.x * 256 + threadIdx.x;    // over Dc*Dc/4 float4s
    float4 v = reinterpret_cast<const float4*>(src)[i];
    uint4 h, l;
    split2(v.x, h.x, l.x); split2(v.y, h.y, l.y);
    split2(v.z, h.z, l.z); split2(v.w, h.w, l.w);
    size_t off = (size_t)wsel * (Dc * Dc / 4) + i;
    reinterpret_cast<uint4*>(g_hiW)[off] = h;
    reinterpret_cast<uint4*>(g_loW)[off] = l;
}

// ---------------- Split-TF32 GEMM on pre-split planes ------------------------
// out = X[M,512] @ W[512,512]^T + bias, X/W given as hi/lo tf32 planes.
// acc += aL*bH + aH*bL + aH*bH (3 MMAs). Hot loop: LDS + MMA only.
// BM=128, BN=64, BK=16, 256 threads (8 warps, 4x2), warp tile 32x32.
// cp.async double buffered, 1 syncthreads per k-tile.
constexpr int GK  = 512;
constexpr int GBM = 128, GBN = 64, GBK = 16;
constexpr int GLDA = 20;                       // conflict-free, float4-aligned
constexpr int G_ASZ = GBM * GLDA;              // 2560 u32
constexpr int G_WSZ = GBN * GLDA;              // 1280 u32
constexpr int G_SMEM_BYTES = (4 * G_ASZ + 4 * G_WSZ) * 4;   // 61440 B

__global__ __launch_bounds__(256) void tf32x2_gemm_kernel(
    const uint32_t* __restrict__ Xh, const uint32_t* __restrict__ Xl,
    const uint32_t* __restrict__ Wh, const uint32_t* __restrict__ Wl,
    const float* __restrict__ bias, float* __restrict__ out, int permute)
{
    extern __shared__ uint32_t sm_[];
    uint32_t* AsH = sm_;                          // [2][G_ASZ]
    uint32_t* AsL = sm_ + 2 * G_ASZ;
    uint32_t* WsH = sm_ + 4 * G_ASZ;              // [2][G_WSZ]
    uint32_t* WsL = sm_ + 4 * G_ASZ + 2 * G_WSZ;

    const int tid  = threadIdx.x;
    const int warp = tid >> 5, lane = tid & 31;
    const int wm = warp & 3;        // 0..3 -> m offset
    const int wn = warp >> 2;       // 0..1 -> n offset
    const int m0 = blockIdx.y * GBM;
    const int n0 = blockIdx.x * GBN;
    const int gr = lane >> 2, gc = lane & 3;

    float acc[2][4][4];
    #pragma unroll
    for (int i = 0; i < 2; i++)
        #pragma unroll
        for (int j = 0; j < 4; j++)
            #pragma unroll
            for (int q = 0; q < 4; q++) acc[i][j][q] = 0.0f;

    // per-thread staging coords
    const int ar = tid >> 1, ac = (tid & 1) * 8;     // A: row, col (2x 16B/plane)
    const int wr = tid >> 2, wc = (tid & 3) * 4;     // W: row, col (1x 16B/plane)
    const uint32_t* XhP = Xh + (size_t)(m0 + ar) * GK + ac;
    const uint32_t* XlP = Xl + (size_t)(m0 + ar) * GK + ac;
    const uint32_t* WhP = Wh + (size_t)(n0 + wr) * GK + wc;
    const uint32_t* WlP = Wl + (size_t)(n0 + wr) * GK + wc;

    // stage tile 0 into buffer 0
    cp16(&AsH[ar * GLDA + ac],     XhP);
    cp16(&AsH[ar * GLDA + ac + 4], XhP + 4);
    cp16(&AsL[ar * GLDA + ac],     XlP);
    cp16(&AsL[ar * GLDA + ac + 4], XlP + 4);
    cp16(&WsH[wr * GLDA + wc],     WhP);
    cp16(&WsL[wr * GLDA + wc],     WlP);
    cp_commit();

    constexpr int NT = GK / GBK;   // 32 tiles
    for (int t = 0; t < NT; ++t) {
        const int buf = t & 1;
        if (t + 1 < NT) {
            const int nxt = 1 - buf;
            const int o = (t + 1) * GBK;
            cp16(&AsH[nxt * G_ASZ + ar * GLDA + ac],     XhP + o);
            cp16(&AsH[nxt * G_ASZ + ar * GLDA + ac + 4], XhP + o + 4);
            cp16(&AsL[nxt * G_ASZ + ar * GLDA + ac],     XlP + o);
            cp16(&AsL[nxt * G_ASZ + ar * GLDA + ac + 4], XlP + o + 4);
            cp16(&WsH[nxt * G_WSZ + wr * GLDA + wc],     WhP + o);
            cp16(&WsL[nxt * G_WSZ + wr * GLDA + wc],     WlP + o);
            cp_commit();
            cp_wait<1>();   // tile t landed; t+1 still streaming
        } else {
            cp_wait<0>();
        }
        __syncthreads();

        const uint32_t* aHs = AsH + buf * G_ASZ;
        const uint32_t* aLs = AsL + buf * G_ASZ;
        const uint32_t* wHs = WsH + buf * G_WSZ;
        const uint32_t* wLs = WsL + buf * G_WSZ;

        #pragma unroll
        for (int ks = 0; ks < 2; ks++) {
            const int kb = ks * 8;
            uint32_t aH[2][4], aL[2][4];
            #pragma unroll
            for (int ti = 0; ti < 2; ti++) {
                int mb = wm * 32 + ti * 16;
                int i0 = (mb + gr)     * GLDA + kb + gc;
                int i1 = (mb + gr + 8) * GLDA + kb + gc;
                aH[ti][0] = aHs[i0];     aH[ti][1] = aHs[i1];
                aH[ti][2] = aHs[i0 + 4]; aH[ti][3] = aHs[i1 + 4];
                aL[ti][0] = aLs[i0];     aL[ti][1] = aLs[i1];
                aL[ti][2] = aLs[i0 + 4]; aL[ti][3] = aLs[i1 + 4];
            }
            uint32_t bH[4][2], bL[4][2];
            #pragma unroll
            for (int tj = 0; tj < 4; tj++) {
                int nb = (wn * 32 + tj * 8 + gr) * GLDA + kb + gc;
                bH[tj][0] = wHs[nb]; bH[tj][1] = wHs[nb + 4];
                bL[tj][0] = wLs[nb]; bL[tj][1] = wLs[nb + 4];
            }
            #pragma unroll
            for (int ti = 0; ti < 2; ti++)
                #pragma unroll
                for (int tj = 0; tj < 4; tj++) {
                    mma_tf32(acc[ti][tj], aL[ti], bH[tj]);
                    mma_tf32(acc[ti][tj], aH[ti], bL[tj]);
                    mma_tf32(acc[ti][tj], aH[ti], bH[tj]);
                }
        }
        __syncthreads();
    }

    // ---- epilogue: bias + (optional) head permute, float2 stores ----
    #pragma unroll
    for (int ti = 0; ti < 2; ti++) {
        #pragma unroll
        for (int tj = 0; tj < 4; tj++) {
            int n = n0 + wn * 32 + tj * 8 + gc * 2;
            float b0 = bias[n], b1 = bias[n + 1];
            #pragma unroll
            for (int half = 0; half < 2; half++) {   // rows gr and gr+8
                int m = m0 + wm * 32 + ti * 16 + gr + half * 8;
                float2 v;
                v.x = acc[ti][tj][half * 2 + 0] + b0;
                v.y = acc[ti][tj][half * 2 + 1] + b1;
                if (!permute) {
                    *reinterpret_cast<float2*>(out + (size_t)m * Dc + n) = v;
                } else {
                    int b = m >> 11, l = m & 2047;
                    int h = n >> 6, d = n & 63;
                    *reinterpret_cast<float2*>(
                        out + (((size_t)(b * Hc + h)) * Lc + l) * DKc + d) = v;
                }
            }
        }
    }
}

// ---------------- V mean over L per (b,h,d): two-stage ----------------------
__global__ __launch_bounds__(256) void vmean1_kernel()
{
    int blk = blockIdx.x;             // 0..255
    int bh = blk >> 3, seg = blk & 7; // 8 segments of 256 rows
    int tid = threadIdx.x;
    int d = tid & 63, part = tid >> 6;  // 4 parts of 64 rows
    const float* Vb = g_V + ((size_t)bh * Lc + seg * 256 + part * 64) * DKc;
    float acc = 0.0f;
    for (int l = 0; l < 64; ++l) acc += Vb[(size_t)l * 64 + d];
    __shared__ float red[256];
    red[tid] = acc;
    __syncthreads();
    if (part == 0)
        g_vpart[(bh * 8 + seg) * 64 + d] =
            red[d] + red[d + 64] + red[d + 128] + red[d + 192];
}

__global__ __launch_bounds__(64) void vmean2_kernel()
{
    int bh = blockIdx.x, d = threadIdx.x;
    float s = 0.0f;
    #pragma unroll
    for (int i = 0; i < 8; i++) s += g_vpart[(bh * 8 + i) * 64 + d];
    g_vmean[bh * 64 + d] = s * (1.0f / Lc);
}

// ---------------- QK_sample + M measure (warp per (b,h,q), unrolled) ---------
template<int UT>
__global__ __launch_bounds__(256) void qk_sample_kernel_u(const int* __restrict__ idxs)
{
    int warp = (blockIdx.x * blockDim.x + threadIdx.x) >> 5;
    int lane = threadIdx.x & 31;
    if (warp >= Bc * Hc * Lc) return;
    int q  = warp % Lc;
    int bh = warp / Lc;

    const float* Qr = g_Q + ((size_t)bh * Lc + q) * 64;
    float q0 = Qr[lane], q1 = Qr[lane + 32];

    const int* ip = idxs + (size_t)q * UT;
    int idx0 = (lane < UT) ? ip[lane] : 0;
    int idx1 = (UT > 32 && lane < UT - 32) ? ip[32 + lane] : 0;

    const float* Kb = g_K + (size_t)bh * Lc * 64;
    float mx = -1e30f, sm = 0.0f;
    #pragma unroll
    for (int j = 0; j < UT; j++) {
        int ki = (j < 32) ? __shfl_sync(0xFFFFFFFFu, idx0, j)
                          : __shfl_sync(0xFFFFFFFFu, idx1, j - 32);
        const float* Kr = Kb + (size_t)ki * 64;
        float p = q0 * Kr[lane] + q1 * Kr[lane + 32];
        #pragma unroll
        for (int o = 16; o > 0; o >>= 1) p += __shfl_xor_sync(0xFFFFFFFFu, p, o);
        mx = fmaxf(mx, p);
        sm += p;
    }
    if (lane == 0) g_M[(size_t)bh * Lc + q] = mx - sm * (1.0f / (float)Lc);
}

// generic fallback (runtime U)
__global__ __launch_bounds__(256) void qk_sample_kernel(const int* __restrict__ idxs, int U)
{
    int warp = (blockIdx.x * blockDim.x + threadIdx.x) >> 5;
    int lane = threadIdx.x & 31;
    if (warp >= Bc * Hc * Lc) return;
    int q  = warp % Lc;
    int bh = warp / Lc;

    const float* Qr = g_Q + ((size_t)bh * Lc + q) * 64;
    float q0 = Qr[lane], q1 = Qr[lane + 32];

    float mx = -1e30f, sm = 0.0f;
    for (int j = 0; j < U; j++) {
        int ki = idxs[q * U + j];
        const float* Kr = g_K + ((size_t)bh * Lc + ki) * 64;
        float p = q0 * Kr[lane] + q1 * Kr[lane + 32];
        #pragma unroll
        for (int o = 16; o > 0; o >>= 1) p += __shfl_xor_sync(0xFFFFFFFFu, p, o);
        mx = fmaxf(mx, p);
        sm += p;
    }
    if (lane == 0) g_M[(size_t)bh * Lc + q] = mx - sm * (1.0f / (float)Lc);
}

// ---------------- top-U per (b,h): iterative argmax over 2048 ----------------
__global__ __launch_bounds__(256) void topk_kernel(int U)
{
    int bh  = blockIdx.x;
    int tid = threadIdx.x;
    __shared__ float vals[Lc];
    __shared__ float rmax[256];
    __shared__ int   ridx[256];

    for (int i = tid; i < Lc; i += 256) vals[i] = g_M[(size_t)bh * Lc + i];
    __syncthreads();

    for (int it = 0; it < U; it++) {
        float best = -1e30f; int bi = Lc;
        for (int i = tid; i < Lc; i += 256) {
            float v = vals[i];
            if (v > best) { best = v; bi = i; }
        }
        rmax[tid] = best; ridx[tid] = bi;
        __syncthreads();
        for (int s = 128; s > 0; s >>= 1) {
            if (tid < s) {
                if (rmax[tid + s] > rmax[tid] ||
                    (rmax[tid + s] == rmax[tid] && ridx[tid + s] < ridx[tid])) {
                    rmax[tid] = rmax[tid + s];
                    ridx[tid] = ridx[tid + s];
                }
            }
            __syncthreads();
        }
        if (tid == 0) {
            g_top[bh * UMAX + it] = ridx[0];
            vals[ridx[0]] = -1e30f;
        }
        __syncthreads();
    }
}

// ---------------- fill context with broadcast V-mean -------------------------
__global__ __launch_bounds__(256) void fill_ctx_kernel()
{
    size_t i = (size_t)blockIdx.x * 256 + threadIdx.x;  // over B*L*D
    int d = (int)(i & 63);
    int h = (int)((i >> 6) & 7);
    int b = (int)(i >> 20);                              // L*H*64 = 2^20
    g_ctx[i] = g_vmean[(b * Hc + h) * 64 + d];
}

// ---------------- flash-style attention for top-u queries (8 per block) ------
// grid (Bc*Hc, ceil(U/8)); warp w handles query index blockIdx.y*8 + w.
// Online softmax over K chunks of 64 rows staged in smem; V applied per chunk.
__global__ __launch_bounds__(256) void sparse_attn2_kernel(int U)
{
    int bh = blockIdx.x;
    int b  = bh >> 3, h = bh & 7;
    int tid = threadIdx.x, w = tid >> 5, lane = tid & 31;
    int ui = blockIdx.y * 8 + w;
    bool active = ui < U;
    int lq = active ? g_top[bh * UMAX + ui] : 0;

    __shared__ float qv[8][64];
    __shared__ float Ks[64][65];
    __shared__ float Vs[64][65];

    // each warp loads its own (scaled) query row
    const float* Qr = g_Q + ((size_t)bh * Lc + lq) * 64;
    qv[w][lane]      = Qr[lane]      * 0.125f;   // 1/sqrt(64)
    qv[w][lane + 32] = Qr[lane + 32] * 0.125f;
    __syncthreads();

    float m = -1e30f, l = 0.0f, acc0 = 0.0f, acc1 = 0.0f;

    const float* Kb = g_K + (size_t)bh * Lc * 64;
    const float* Vb = g_V + (size_t)bh * Lc * 64;
    const int row = tid >> 2;           // 0..63
    const int cb  = (tid & 3) * 4;      // col base; strided +16

    for (int kc = 0; kc < Lc / 64; ++kc) {
        // ---- stage K,V chunk (64 x 64), padded rows (65) ----
        #pragma unroll
        for (int s = 0; s < 4; ++s) {
            int c = cb + s * 16;
            const float* kp = Kb + ((size_t)(kc * 64 + row)) * 64 + c;
            const float* vp = Vb + ((size_t)(kc * 64 + row)) * 64 + c;
            float4 kv = *reinterpret_cast<const float4*>(kp);
            float4 vv = *reinterpret_cast<const float4*>(vp);
            Ks[row][c] = kv.x; Ks[row][c+1] = kv.y; Ks[row][c+2] = kv.z; Ks[row][c+3] = kv.w;
            Vs[row][c] = vv.x; Vs[row][c+1] = vv.y; Vs[row][c+2] = vv.z; Vs[row][c+3] = vv.w;
        }
        __syncthreads();

        // ---- scores for rows lane and lane+32 ----
        float s0 = 0.0f, s1 = 0.0f;
        #pragma unroll 16
        for (int c = 0; c < 64; ++c) {
            float qc = qv[w][c];
            s0 = fmaf(qc, Ks[lane][c],      s0);
            s1 = fmaf(qc, Ks[lane + 32][c], s1);
        }

        // ---- online softmax update ----
        float cm = fmaxf(s0, s1);
        #pragma unroll
        for (int o = 16; o > 0; o >>= 1)
            cm = fmaxf(cm, __shfl_xor_sync(0xFFFFFFFFu, cm, o));
        float mn = fmaxf(m, cm);
        float corr = expf(m - mn);
        l *= corr; acc0 *= corr; acc1 *= corr;
        float p0 = expf(s0 - mn), p1 = expf(s1 - mn);
        float ps = p0 + p1;
        #pragma unroll
        for (int o = 16; o > 0; o >>= 1)
            ps += __shfl_xor_sync(0xFFFFFFFFu, ps, o);
        l += ps;
        m = mn;

        // ---- accumulate P @ V for dims lane, lane+32 ----
        #pragma unroll 8
        for (int r = 0; r < 32; ++r) {
            float pa = __shfl_sync(0xFFFFFFFFu, p0, r);
            float pb = __shfl_sync(0xFFFFFFFFu, p1, r);
            acc0 = fmaf(pa, Vs[r][lane],           acc0);
            acc1 = fmaf(pa, Vs[r][lane + 32],      acc1);
            acc0 = fmaf(pb, Vs[r + 32][lane],      acc0);
            acc1 = fmaf(pb, Vs[r + 32][lane + 32], acc1);
        }
        __syncthreads();
    }

    if (active) {
        float inv = 1.0f / l;
        float* dst = g_ctx + (((size_t)(b * Lc + lq)) * Hc + h) * 64;
        dst[lane]      = acc0 * inv;
        dst[lane + 32] = acc1 * inv;
    }
}

// ---------------- launch ------------------------------------------------------
extern "C" void kernel_launch(void* const* d_in, const int* in_sizes, int n_in,
                              void* d_out, int out_size)
{
    const float* queries = (const float*)d_in[0];
    const float* keys    = (const float*)d_in[1];
    const float* values  = (const float*)d_in[2];
    const float* Wq = (const float*)d_in[3];
    const float* bq = (const float*)d_in[4];
    const float* Wk = (const float*)d_in[5];
    const float* bk = (const float*)d_in[6];
    const float* Wv = (const float*)d_in[7];
    const float* bv = (const float*)d_in[8];
    const float* Wo = (const float*)d_in[9];
    const float* bo = (const float*)d_in[10];
    const int* index_sample = (const int*)d_in[11];

    int U = in_sizes[11] / Lc;   // 40 for this bench
    if (U > UMAX) U = UMAX;

    float *qp, *kp, *vp, *ctx;
    cudaGetSymbolAddress((void**)&qp,  g_Q);
    cudaGetSymbolAddress((void**)&kp,  g_K);
    cudaGetSymbolAddress((void**)&vp,  g_V);
    cudaGetSymbolAddress((void**)&ctx, g_ctx);
    uint32_t *hiQ, *loQ, *hiK, *loK, *hiV, *loV, *hiC, *loC, *hiW, *loW;
    cudaGetSymbolAddress((void**)&hiQ, g_hiQ); cudaGetSymbolAddress((void**)&loQ, g_loQ);
    cudaGetSymbolAddress((void**)&hiK, g_hiK); cudaGetSymbolAddress((void**)&loK, g_loK);
    cudaGetSymbolAddress((void**)&hiV, g_hiV); cudaGetSymbolAddress((void**)&loV, g_loV);
    cudaGetSymbolAddress((void**)&hiC, g_hiC); cudaGetSymbolAddress((void**)&loC, g_loC);
    cudaGetSymbolAddress((void**)&hiW, g_hiW); cudaGetSymbolAddress((void**)&loW, g_loW);

    cudaFuncSetAttribute(tf32x2_gemm_kernel,
                         cudaFuncAttributeMaxDynamicSharedMemorySize,
                         G_SMEM_BYTES);

    const int WSZ = Dc * Dc;          // 262144 elements per W
    dim3 ggrid(Dc / 64, (Bc * Lc) / 128);  // (8, 64)
    int warps = Bc * Hc * Lc;
    int n4x = NX / 4;                 // float4s per (B,L,D) tensor

    // index 3 (the ncu-captured launch) is the Q-projection GEMM.
    presplit_x_kernel<<<(n4x + 255) / 256, 256>>>(queries, hiQ, loQ, n4x);    // 0
    presplit_x_kernel<<<(n4x + 255) / 256, 256>>>(keys,    hiK, loK, n4x);    // 1
    presplit_w4_kernel<<<dim3(WSZ / 4 / 256, 4), 256>>>(Wq, Wk, Wv, Wo);      // 2

    tf32x2_gemm_kernel<<<ggrid, 256, G_SMEM_BYTES>>>(                         // 3
        hiQ, loQ, hiW + 0 * WSZ, loW + 0 * WSZ, bq, qp, 1);
    tf32x2_gemm_kernel<<<ggrid, 256, G_SMEM_BYTES>>>(                         // 4
        hiK, loK, hiW + 1 * WSZ, loW + 1 * WSZ, bk, kp, 1);

    presplit_x_kernel<<<(n4x + 255) / 256, 256>>>(values, hiV, loV, n4x);     // 5

    if (U == 40)                                                              // 6
        qk_sample_kernel_u<40><<<(warps * 32) / 256, 256>>>(index_sample);
    else
        qk_sample_kernel<<<(warps * 32) / 256, 256>>>(index_sample, U);

    tf32x2_gemm_kernel<<<ggrid, 256, G_SMEM_BYTES>>>(                         // 7
        hiV, loV, hiW + 2 * WSZ, loW + 2 * WSZ, bv, vp, 1);

    vmean1_kernel<<<Bc * Hc * 8, 256>>>();                                    // 8
    vmean2_kernel<<<Bc * Hc, 64>>>();                                         // 9

    topk_kernel<<<Bc * Hc, 256>>>(U);                                         // 10

    fill_ctx_kernel<<<(Bc * Lc * Dc) / 256, 256>>>();                         // 11

    sparse_attn2_kernel<<<dim3(Bc * Hc, (U + 7) / 8), 256>>>(U);              // 12

    presplit_x_kernel<<<(n4x + 255) / 256, 256>>>(ctx, hiC, loC, n4x);        // 13

    tf32x2_gemm_kernel<<<ggrid, 256, G_SMEM_BYTES>>>(                         // 14
        hiC, loC, hiW + 3 * WSZ, loW + 3 * WSZ, bo, (float*)d_out, 0);
}

// round 9
// speedup vs baseline: 1.0958x; 1.0958x over previous
#include <cuda_runtime.h>
#include <cuda_bf16.h>
#include <math.h>
#include <stdint.h>

// Problem constants (fixed shapes for this bench)
constexpr int Bc  = 4;
constexpr int Lc  = 2048;
constexpr int Dc  = 512;
constexpr int Hc  = 8;
constexpr int DKc = 64;
constexpr int UMAX = 64;   // safety cap for top-k storage (actual U = 40)
constexpr int NX  = Bc * Lc * Dc;     // elements in one (B,L,D) tensor

// ---------------- scratch (device globals; no allocation allowed) ------------
__device__ float g_Q[Bc*Hc*Lc*DKc];      // (b,h,l,d)  16 MB
__device__ float g_K[Bc*Hc*Lc*DKc];      // 16 MB
__device__ float g_V[Bc*Hc*Lc*DKc];      // 16 MB
__device__ float g_ctx[Bc*Lc*Dc];        // (b,l,h,d) = (b,l,D)  16 MB
__device__ float g_M[Bc*Hc*Lc];          // sparsity measure
__device__ int   g_top[Bc*Hc*UMAX];      // top-u indices per (b,h)
__device__ float g_vmean[Bc*Hc*DKc];     // V mean over L
__device__ float g_vpart[Bc*Hc*8*DKc];   // partial V sums

// pre-split hi/lo tf32 planes of the 4 weight matrices only (small, L2-resident)
__device__ uint32_t g_hiW[4*Dc*Dc], g_loW[4*Dc*Dc];

// ---------------- tf32 helpers ------------------------------------------------
__device__ __forceinline__ uint32_t f2tf32(float x) {
    uint32_t u;
    asm("cvt.rna.tf32.f32 %0, %1;" : "=r"(u) : "f"(x));
    return u;
}

__device__ __forceinline__ void mma_tf32(float (&d)[4], const uint32_t (&a)[4],
                                         const uint32_t (&b)[2]) {
    asm volatile(
        "mma.sync.aligned.m16n8k8.row.col.f32.tf32.tf32.f32 "
        "{%0,%1,%2,%3}, {%4,%5,%6,%7}, {%8,%9}, {%0,%1,%2,%3};"
        : "+f"(d[0]), "+f"(d[1]), "+f"(d[2]), "+f"(d[3])
        : "r"(a[0]), "r"(a[1]), "r"(a[2]), "r"(a[3]), "r"(b[0]), "r"(b[1]));
}

__device__ __forceinline__ void split2(float x, uint32_t& hi, uint32_t& lo) {
    hi = f2tf32(x);
    lo = f2tf32(x - __uint_as_float(hi));
}

__device__ __forceinline__ void cp16(void* smem, const void* gmem) {
    uint32_t s = (uint32_t)__cvta_generic_to_shared(smem);
    asm volatile("cp.async.cg.shared.global [%0], [%1], 16;" :: "r"(s), "l"(gmem));
}
__device__ __forceinline__ void cp_commit() {
    asm volatile("cp.async.commit_group;" ::: "memory");
}
template<int N>
__device__ __forceinline__ void cp_wait() {
    asm volatile("cp.async.wait_group %0;" :: "n"(N) : "memory");
}

// ---------------- weight pre-split kernel ------------------------------------
__global__ __launch_bounds__(256) void presplit_w4_kernel(
    const float* __restrict__ w0, const float* __restrict__ w1,
    const float* __restrict__ w2, const float* __restrict__ w3)
{
    const float* srcs[4] = {w0, w1, w2, w3};
    int wsel = blockIdx.y;
    const float* src = srcs[wsel];
    int i = blockIdx.x * 256 + threadIdx.x;    // over Dc*Dc/4 float4s
    float4 v = reinterpret_cast<const float4*>(src)[i];
    uint4 h, l;
    split2(v.x, h.x, l.x); split2(v.y, h.y, l.y);
    split2(v.z, h.z, l.z); split2(v.w, h.w, l.w);
    size_t off = (size_t)wsel * (Dc * Dc / 4) + i;
    reinterpret_cast<uint4*>(g_hiW)[off] = h;
    reinterpret_cast<uint4*>(g_loW)[off] = l;
}

// ---------------- Split-TF32 GEMM (A raw + in-register split, W pre-split) ---
// out = X[M,512] @ W[512,512]^T + bias.
// A staged raw fp32 (cp.async), split at fragment-load; W hi/lo planes staged.
// acc += aL*bH + aH*bL + aH*bH (3 MMAs).
// BM=128, BN=64, BK=16, 256 threads (8 warps, 4x2), warp tile 32x32.
// permute=0: out[m*512+n] ; permute=1: out[((b*H+h)*L+l)*64+d], m=(b,l), n=(h,d)
constexpr int GK  = 512;
constexpr int GBM = 128, GBN = 64, GBK = 16;
constexpr int GLDA = 20;                       // conflict-free, float4-aligned
constexpr int G_ASZ = GBM * GLDA;              // 2560 floats
constexpr int G_WSZ = GBN * GLDA;              // 1280 u32

__global__ __launch_bounds__(256) void tf32x2_gemm_kernel(
    const float* __restrict__ X,
    const uint32_t* __restrict__ Wh, const uint32_t* __restrict__ Wl,
    const float* __restrict__ bias, float* __restrict__ out, int permute)
{
    __shared__ float    As[2][G_ASZ];
    __shared__ uint32_t WsH[2][G_WSZ];
    __shared__ uint32_t WsL[2][G_WSZ];

    const int tid  = threadIdx.x;
    const int warp = tid >> 5, lane = tid & 31;
    const int wm = warp & 3;        // 0..3 -> m offset
    const int wn = warp >> 2;       // 0..1 -> n offset
    const int m0 = blockIdx.y * GBM;
    const int n0 = blockIdx.x * GBN;
    const int gr = lane >> 2, gc = lane & 3;

    float acc[2][4][4];
    #pragma unroll
    for (int i = 0; i < 2; i++)
        #pragma unroll
        for (int j = 0; j < 4; j++)
            #pragma unroll
            for (int q = 0; q < 4; q++) acc[i][j][q] = 0.0f;

    // per-thread staging coords
    const int ar = tid >> 1, ac = (tid & 1) * 8;     // A: row, col (2x 16B)
    const int wr = tid >> 2, wc = (tid & 3) * 4;     // W: row, col (1x 16B/plane)
    const float*    AP  = X  + (size_t)(m0 + ar) * GK + ac;
    const uint32_t* WhP = Wh + (size_t)(n0 + wr) * GK + wc;
    const uint32_t* WlP = Wl + (size_t)(n0 + wr) * GK + wc;

    // stage tile 0 into buffer 0
    cp16(&As[0][ar * GLDA + ac],     AP);
    cp16(&As[0][ar * GLDA + ac + 4], AP + 4);
    cp16(&WsH[0][wr * GLDA + wc],    WhP);
    cp16(&WsL[0][wr * GLDA + wc],    WlP);
    cp_commit();

    constexpr int NT = GK / GBK;   // 32 tiles
    for (int t = 0; t < NT; ++t) {
        const int buf = t & 1;
        if (t + 1 < NT) {
            const int nxt = 1 - buf;
            const int o = (t + 1) * GBK;
            cp16(&As[nxt][ar * GLDA + ac],     AP + o);
            cp16(&As[nxt][ar * GLDA + ac + 4], AP + o + 4);
            cp16(&WsH[nxt][wr * GLDA + wc],    WhP + o);
            cp16(&WsL[nxt][wr * GLDA + wc],    WlP + o);
            cp_commit();
            cp_wait<1>();   // tile t landed; t+1 still streaming
        } else {
            cp_wait<0>();
        }
        __syncthreads();

        const float*    aS  = As[buf];
        const uint32_t* wHs = WsH[buf];
        const uint32_t* wLs = WsL[buf];

        #pragma unroll
        for (int ks = 0; ks < 2; ks++) {
            const int kb = ks * 8;
            uint32_t aH[2][4], aL[2][4];
            #pragma unroll
            for (int ti = 0; ti < 2; ti++) {
                int mb = wm * 32 + ti * 16;
                int i0 = (mb + gr)     * GLDA + kb + gc;
                int i1 = (mb + gr + 8) * GLDA + kb + gc;
                split2(aS[i0],     aH[ti][0], aL[ti][0]);
                split2(aS[i1],     aH[ti][1], aL[ti][1]);
                split2(aS[i0 + 4], aH[ti][2], aL[ti][2]);
                split2(aS[i1 + 4], aH[ti][3], aL[ti][3]);
            }
            uint32_t bH[4][2], bL[4][2];
            #pragma unroll
            for (int tj = 0; tj < 4; tj++) {
                int nb = (wn * 32 + tj * 8 + gr) * GLDA + kb + gc;
                bH[tj][0] = wHs[nb]; bH[tj][1] = wHs[nb + 4];
                bL[tj][0] = wLs[nb]; bL[tj][1] = wLs[nb + 4];
            }
            #pragma unroll
            for (int ti = 0; ti < 2; ti++)
                #pragma unroll
                for (int tj = 0; tj < 4; tj++) {
                    mma_tf32(acc[ti][tj], aL[ti], bH[tj]);
                    mma_tf32(acc[ti][tj], aH[ti], bL[tj]);
                    mma_tf32(acc[ti][tj], aH[ti], bH[tj]);
                }
        }
        __syncthreads();
    }

    // ---- epilogue: bias + (optional) head permute, float2 stores ----
    #pragma unroll
    for (int ti = 0; ti < 2; ti++) {
        #pragma unroll
        for (int tj = 0; tj < 4; tj++) {
            int n = n0 + wn * 32 + tj * 8 + gc * 2;
            float b0 = bias[n], b1 = bias[n + 1];
            #pragma unroll
            for (int half = 0; half < 2; half++) {   // rows gr and gr+8
                int m = m0 + wm * 32 + ti * 16 + gr + half * 8;
                float2 v;
                v.x = acc[ti][tj][half * 2 + 0] + b0;
                v.y = acc[ti][tj][half * 2 + 1] + b1;
                if (!permute) {
                    *reinterpret_cast<float2*>(out + (size_t)m * Dc + n) = v;
                } else {
                    int b = m >> 11, l = m & 2047;
                    int h = n >> 6, d = n & 63;
                    *reinterpret_cast<float2*>(
                        out + (((size_t)(b * Hc + h)) * Lc + l) * DKc + d) = v;
                }
            }
        }
    }
}

// ---------------- V mean over L per (b,h,d): two-stage ----------------------
__global__ __launch_bounds__(256) void vmean1_kernel()
{
    int blk = blockIdx.x;             // 0..255
    int bh = blk >> 3, seg = blk & 7; // 8 segments of 256 rows
    int tid = threadIdx.x;
    int d = tid & 63, part = tid >> 6;  // 4 parts of 64 rows
    const float* Vb = g_V + ((size_t)bh * Lc + seg * 256 + part * 64) * DKc;
    float acc = 0.0f;
    for (int l = 0; l < 64; ++l) acc += Vb[(size_t)l * 64 + d];
    __shared__ float red[256];
    red[tid] = acc;
    __syncthreads();
    if (part == 0)
        g_vpart[(bh * 8 + seg) * 64 + d] =
            red[d] + red[d + 64] + red[d + 128] + red[d + 192];
}

__global__ __launch_bounds__(64) void vmean2_kernel()
{
    int bh = blockIdx.x, d = threadIdx.x;
    float s = 0.0f;
    #pragma unroll
    for (int i = 0; i < 8; i++) s += g_vpart[(bh * 8 + i) * 64 + d];
    g_vmean[bh * 64 + d] = s * (1.0f / Lc);
}

// ---------------- QK_sample + M measure (warp per (b,h,q), unrolled) ---------
template<int UT>
__global__ __launch_bounds__(256) void qk_sample_kernel_u(const int* __restrict__ idxs)
{
    int warp = (blockIdx.x * blockDim.x + threadIdx.x) >> 5;
    int lane = threadIdx.x & 31;
    if (warp >= Bc * Hc * Lc) return;
    int q  = warp % Lc;
    int bh = warp / Lc;

    const float* Qr = g_Q + ((size_t)bh * Lc + q) * 64;
    float q0 = Qr[lane], q1 = Qr[lane + 32];

    const int* ip = idxs + (size_t)q * UT;
    int idx0 = (lane < UT) ? ip[lane] : 0;
    int idx1 = (UT > 32 && lane < UT - 32) ? ip[32 + lane] : 0;

    const float* Kb = g_K + (size_t)bh * Lc * 64;
    float mx = -1e30f, sm = 0.0f;
    #pragma unroll
    for (int j = 0; j < UT; j++) {
        int ki = (j < 32) ? __shfl_sync(0xFFFFFFFFu, idx0, j)
                          : __shfl_sync(0xFFFFFFFFu, idx1, j - 32);
        const float* Kr = Kb + (size_t)ki * 64;
        float p = q0 * Kr[lane] + q1 * Kr[lane + 32];
        #pragma unroll
        for (int o = 16; o > 0; o >>= 1) p += __shfl_xor_sync(0xFFFFFFFFu, p, o);
        mx = fmaxf(mx, p);
        sm += p;
    }
    if (lane == 0) g_M[(size_t)bh * Lc + q] = mx - sm * (1.0f / (float)Lc);
}

// generic fallback (runtime U)
__global__ __launch_bounds__(256) void qk_sample_kernel(const int* __restrict__ idxs, int U)
{
    int warp = (blockIdx.x * blockDim.x + threadIdx.x) >> 5;
    int lane = threadIdx.x & 31;
    if (warp >= Bc * Hc * Lc) return;
    int q  = warp % Lc;
    int bh = warp / Lc;

    const float* Qr = g_Q + ((size_t)bh * Lc + q) * 64;
    float q0 = Qr[lane], q1 = Qr[lane + 32];

    float mx = -1e30f, sm = 0.0f;
    for (int j = 0; j < U; j++) {
        int ki = idxs[q * U + j];
        const float* Kr = g_K + ((size_t)bh * Lc + ki) * 64;
        float p = q0 * Kr[lane] + q1 * Kr[lane + 32];
        #pragma unroll
        for (int o = 16; o > 0; o >>= 1) p += __shfl_xor_sync(0xFFFFFFFFu, p, o);
        mx = fmaxf(mx, p);
        sm += p;
    }
    if (lane == 0) g_M[(size_t)bh * Lc + q] = mx - sm * (1.0f / (float)Lc);
}

// ---------------- top-U per (b,h): iterative argmax over 2048 ----------------
__global__ __launch_bounds__(256) void topk_kernel(int U)
{
    int bh  = blockIdx.x;
    int tid = threadIdx.x;
    __shared__ float vals[Lc];
    __shared__ float rmax[256];
    __shared__ int   ridx[256];

    for (int i = tid; i < Lc; i += 256) vals[i] = g_M[(size_t)bh * Lc + i];
    __syncthreads();

    for (int it = 0; it < U; it++) {
        float best = -1e30f; int bi = Lc;
        for (int i = tid; i < Lc; i += 256) {
            float v = vals[i];
            if (v > best) { best = v; bi = i; }
        }
        rmax[tid] = best; ridx[tid] = bi;
        __syncthreads();
        for (int s = 128; s > 0; s >>= 1) {
            if (tid < s) {
                if (rmax[tid + s] > rmax[tid] ||
                    (rmax[tid + s] == rmax[tid] && ridx[tid + s] < ridx[tid])) {
                    rmax[tid] = rmax[tid + s];
                    ridx[tid] = ridx[tid + s];
                }
            }
            __syncthreads();
        }
        if (tid == 0) {
            g_top[bh * UMAX + it] = ridx[0];
            vals[ridx[0]] = -1e30f;
        }
        __syncthreads();
    }
}

// ---------------- fill context with broadcast V-mean -------------------------
__global__ __launch_bounds__(256) void fill_ctx_kernel()
{
    size_t i = (size_t)blockIdx.x * 256 + threadIdx.x;  // over B*L*D
    int d = (int)(i & 63);
    int h = (int)((i >> 6) & 7);
    int b = (int)(i >> 20);                              // L*H*64 = 2^20
    g_ctx[i] = g_vmean[(b * Hc + h) * 64 + d];
}

// ---------------- flash-style attention for top-u queries (8 per block) ------
// grid (Bc*Hc, ceil(U/8)); warp w handles query index blockIdx.y*8 + w.
// Online softmax over K chunks of 64 rows staged in smem; V applied per chunk.
__global__ __launch_bounds__(256) void sparse_attn2_kernel(int U)
{
    int bh = blockIdx.x;
    int b  = bh >> 3, h = bh & 7;
    int tid = threadIdx.x, w = tid >> 5, lane = tid & 31;
    int ui = blockIdx.y * 8 + w;
    bool active = ui < U;
    int lq = active ? g_top[bh * UMAX + ui] : 0;

    __shared__ float qv[8][64];
    __shared__ float Ks[64][65];
    __shared__ float Vs[64][65];

    // each warp loads its own (scaled) query row
    const float* Qr = g_Q + ((size_t)bh * Lc + lq) * 64;
    qv[w][lane]      = Qr[lane]      * 0.125f;   // 1/sqrt(64)
    qv[w][lane + 32] = Qr[lane + 32] * 0.125f;
    __syncthreads();

    float m = -1e30f, l = 0.0f, acc0 = 0.0f, acc1 = 0.0f;

    const float* Kb = g_K + (size_t)bh * Lc * 64;
    const float* Vb = g_V + (size_t)bh * Lc * 64;
    const int row = tid >> 2;           // 0..63
    const int cb  = (tid & 3) * 4;      // col base; strided +16

    for (int kc = 0; kc < Lc / 64; ++kc) {
        // ---- stage K,V chunk (64 x 64), padded rows (65) ----
        #pragma unroll
        for (int s = 0; s < 4; ++s) {
            int c = cb + s * 16;
            const float* kp = Kb + ((size_t)(kc * 64 + row)) * 64 + c;
            const float* vp = Vb + ((size_t)(kc * 64 + row)) * 64 + c;
            float4 kv = *reinterpret_cast<const float4*>(kp);
            float4 vv = *reinterpret_cast<const float4*>(vp);
            Ks[row][c] = kv.x; Ks[row][c+1] = kv.y; Ks[row][c+2] = kv.z; Ks[row][c+3] = kv.w;
            Vs[row][c] = vv.x; Vs[row][c+1] = vv.y; Vs[row][c+2] = vv.z; Vs[row][c+3] = vv.w;
        }
        __syncthreads();

        // ---- scores for rows lane and lane+32 ----
        float s0 = 0.0f, s1 = 0.0f;
        #pragma unroll 16
        for (int c = 0; c < 64; ++c) {
            float qc = qv[w][c];
            s0 = fmaf(qc, Ks[lane][c],      s0);
            s1 = fmaf(qc, Ks[lane + 32][c], s1);
        }

        // ---- online softmax update ----
        float cm = fmaxf(s0, s1);
        #pragma unroll
        for (int o = 16; o > 0; o >>= 1)
            cm = fmaxf(cm, __shfl_xor_sync(0xFFFFFFFFu, cm, o));
        float mn = fmaxf(m, cm);
        float corr = expf(m - mn);
        l *= corr; acc0 *= corr; acc1 *= corr;
        float p0 = expf(s0 - mn), p1 = expf(s1 - mn);
        float ps = p0 + p1;
        #pragma unroll
        for (int o = 16; o > 0; o >>= 1)
            ps += __shfl_xor_sync(0xFFFFFFFFu, ps, o);
        l += ps;
        m = mn;

        // ---- accumulate P @ V for dims lane, lane+32 ----
        #pragma unroll 8
        for (int r = 0; r < 32; ++r) {
            float pa = __shfl_sync(0xFFFFFFFFu, p0, r);
            float pb = __shfl_sync(0xFFFFFFFFu, p1, r);
            acc0 = fmaf(pa, Vs[r][lane],           acc0);
            acc1 = fmaf(pa, Vs[r][lane + 32],      acc1);
            acc0 = fmaf(pb, Vs[r + 32][lane],      acc0);
            acc1 = fmaf(pb, Vs[r + 32][lane + 32], acc1);
        }
        __syncthreads();
    }

    if (active) {
        float inv = 1.0f / l;
        float* dst = g_ctx + (((size_t)(b * Lc + lq)) * Hc + h) * 64;
        dst[lane]      = acc0 * inv;
        dst[lane + 32] = acc1 * inv;
    }
}

// ---------------- launch ------------------------------------------------------
extern "C" void kernel_launch(void* const* d_in, const int* in_sizes, int n_in,
                              void* d_out, int out_size)
{
    const float* queries = (const float*)d_in[0];
    const float* keys    = (const float*)d_in[1];
    const float* values  = (const float*)d_in[2];
    const float* Wq = (const float*)d_in[3];
    const float* bq = (const float*)d_in[4];
    const float* Wk = (const float*)d_in[5];
    const float* bk = (const float*)d_in[6];
    const float* Wv = (const float*)d_in[7];
    const float* bv = (const float*)d_in[8];
    const float* Wo = (const float*)d_in[9];
    const float* bo = (const float*)d_in[10];
    const int* index_sample = (const int*)d_in[11];

    int U = in_sizes[11] / Lc;   // 40 for this bench
    if (U > UMAX) U = UMAX;

    float *qp, *kp, *vp, *ctx;
    cudaGetSymbolAddress((void**)&qp,  g_Q);
    cudaGetSymbolAddress((void**)&kp,  g_K);
    cudaGetSymbolAddress((void**)&vp,  g_V);
    cudaGetSymbolAddress((void**)&ctx, g_ctx);
    uint32_t *hiW, *loW;
    cudaGetSymbolAddress((void**)&hiW, g_hiW);
    cudaGetSymbolAddress((void**)&loW, g_loW);

    const int WSZ = Dc * Dc;               // 262144 elements per W
    dim3 ggrid(Dc / 64, (Bc * Lc) / 128);  // (8, 64)
    int warps = Bc * Hc * Lc;

    // index 3 (the ncu-captured launch) is the V-projection GEMM.
    presplit_w4_kernel<<<dim3(WSZ / 4 / 256, 4), 256>>>(Wq, Wk, Wv, Wo);      // 0

    tf32x2_gemm_kernel<<<ggrid, 256>>>(queries, hiW + 0 * WSZ, loW + 0 * WSZ, // 1
                                       bq, qp, 1);
    tf32x2_gemm_kernel<<<ggrid, 256>>>(keys,    hiW + 1 * WSZ, loW + 1 * WSZ, // 2
                                       bk, kp, 1);
    tf32x2_gemm_kernel<<<ggrid, 256>>>(values,  hiW + 2 * WSZ, loW + 2 * WSZ, // 3 <- profiled
                                       bv, vp, 1);

    if (U == 40)                                                              // 4
        qk_sample_kernel_u<40><<<(warps * 32) / 256, 256>>>(index_sample);
    else
        qk_sample_kernel<<<(warps * 32) / 256, 256>>>(index_sample, U);

    vmean1_kernel<<<Bc * Hc * 8, 256>>>();                                    // 5
    vmean2_kernel<<<Bc * Hc, 64>>>();                                         // 6

    topk_kernel<<<Bc * Hc, 256>>>(U);                                         // 7

    fill_ctx_kernel<<<(Bc * Lc * Dc) / 256, 256>>>();                         // 8

    sparse_attn2_kernel<<<dim3(Bc * Hc, (U + 7) / 8), 256>>>(U);              // 9

    tf32x2_gemm_kernel<<<ggrid, 256>>>(ctx, hiW + 3 * WSZ, loW + 3 * WSZ,     // 10
                                       bo, (float*)d_out, 0);
}

// round 10
// speedup vs baseline: 1.3884x; 1.2670x over previous
#include <cuda_runtime.h>
#include <cuda_bf16.h>
#include <math.h>
#include <stdint.h>

// Problem constants (fixed shapes for this bench)
constexpr int Bc  = 4;
constexpr int Lc  = 2048;
constexpr int Dc  = 512;
constexpr int Hc  = 8;
constexpr int DKc = 64;
constexpr int UMAX = 64;   // safety cap for top-k storage (actual U = 40)
constexpr int NX  = Bc * Lc * Dc;     // elements in one (B,L,D) tensor

// ---------------- scratch (device globals; no allocation allowed) ------------
__device__ float g_Q[Bc*Hc*Lc*DKc];      // (b,h,l,d)  16 MB
__device__ float g_K[Bc*Hc*Lc*DKc];      // 16 MB
__device__ float g_V[Bc*Hc*Lc*DKc];      // 16 MB
__device__ float g_ctx[Bc*Lc*Dc];        // (b,l,h,d) = (b,l,D)  16 MB
__device__ float g_M[Bc*Hc*Lc];          // sparsity measure
__device__ int   g_top[Bc*Hc*UMAX];      // top-u indices per (b,h)
__device__ float g_vmean[Bc*Hc*DKc];     // V mean over L
__device__ float g_vpart[Bc*Hc*8*DKc];   // partial V sums

// bf16 hi/lo planes, packed 2 consecutive-k bf16 per u32 (low half = even k)
__device__ uint32_t g_hiX[3*NX/2], g_loX[3*NX/2];   // 3 input slots (Q/K/V or ctx in slot 0)
__device__ uint32_t g_hiW[4*Dc*Dc/2], g_loW[4*Dc*Dc/2];

// ---------------- bf16 split helpers ------------------------------------------
__device__ __forceinline__ void split_pack2(float a, float b,
                                            uint32_t& hi, uint32_t& lo) {
    __nv_bfloat16 ha = __float2bfloat16_rn(a);
    __nv_bfloat16 hb = __float2bfloat16_rn(b);
    float ra = a - __bfloat162float(ha);
    float rb = b - __bfloat162float(hb);
    __nv_bfloat162 hv = __floats2bfloat162_rn(__bfloat162float(ha), __bfloat162float(hb));
    __nv_bfloat162 lv = __floats2bfloat162_rn(ra, rb);
    hi = *reinterpret_cast<uint32_t*>(&hv);
    lo = *reinterpret_cast<uint32_t*>(&lv);
}

__device__ __forceinline__ void mma_bf16(float (&d)[4], const uint32_t (&a)[4],
                                         const uint32_t (&b)[2]) {
    asm volatile(
        "mma.sync.aligned.m16n8k16.row.col.f32.bf16.bf16.f32 "
        "{%0,%1,%2,%3}, {%4,%5,%6,%7}, {%8,%9}, {%0,%1,%2,%3};"
        : "+f"(d[0]), "+f"(d[1]), "+f"(d[2]), "+f"(d[3])
        : "r"(a[0]), "r"(a[1]), "r"(a[2]), "r"(a[3]), "r"(b[0]), "r"(b[1]));
}

__device__ __forceinline__ void cp16(void* smem, const void* gmem) {
    uint32_t s = (uint32_t)__cvta_generic_to_shared(smem);
    asm volatile("cp.async.cg.shared.global [%0], [%1], 16;" :: "r"(s), "l"(gmem));
}
__device__ __forceinline__ void cp_commit() {
    asm volatile("cp.async.commit_group;" ::: "memory");
}
template<int N>
__device__ __forceinline__ void cp_wait() {
    asm volatile("cp.async.wait_group %0;" :: "n"(N) : "memory");
}

// ---------------- pre-split kernels -------------------------------------------
// X inputs: blockIdx.y selects tensor, writes slot y of g_hiX/g_loX.
__global__ __launch_bounds__(256) void presplit_x3_kernel(
    const float* __restrict__ x0, const float* __restrict__ x1,
    const float* __restrict__ x2)
{
    const float* srcs[3] = {x0, x1, x2};
    int z = blockIdx.y;
    const float* src = srcs[z];
    int i = blockIdx.x * 256 + threadIdx.x;    // over NX/4 float4s
    if (i >= NX / 4) return;
    float4 v = reinterpret_cast<const float4*>(src)[i];
    uint32_t h0, l0, h1, l1;
    split_pack2(v.x, v.y, h0, l0);
    split_pack2(v.z, v.w, h1, l1);
    size_t o = (size_t)z * (NX / 2) + i * 2;
    g_hiX[o] = h0; g_hiX[o + 1] = h1;
    g_loX[o] = l0; g_loX[o + 1] = l1;
}

__global__ __launch_bounds__(256) void presplit_w4_kernel(
    const float* __restrict__ w0, const float* __restrict__ w1,
    const float* __restrict__ w2, const float* __restrict__ w3)
{
    const float* srcs[4] = {w0, w1, w2, w3};
    int wsel = blockIdx.y;
    const float* src = srcs[wsel];
    int i = blockIdx.x * 256 + threadIdx.x;    // over Dc*Dc/4 float4s
    float4 v = reinterpret_cast<const float4*>(src)[i];
    uint32_t h0, l0, h1, l1;
    split_pack2(v.x, v.y, h0, l0);
    split_pack2(v.z, v.w, h1, l1);
    size_t o = (size_t)wsel * (Dc * Dc / 2) + i * 2;
    g_hiW[o] = h0; g_hiW[o + 1] = h1;
    g_loW[o] = l0; g_loW[o + 1] = l1;
}

// ---------------- Split-bf16 GEMM on packed planes ----------------------------
// out_z = X_z[M,512] @ W_z[512,512]^T + bias_z    (z = blockIdx.z)
// acc += aL*bH + aH*bL + aH*bH (3 bf16 m16n8k16 MMAs). Hot loop: LDS+MMA only.
// BM=128, BN=64, BK=16, 256 threads (8 warps, 4x2), warp tile 32x32.
// permute=0: out[m*512+n] ; permute=1: out[((b*H+h)*L+l)*64+d], m=(b,l), n=(h,d)
constexpr int GK  = 512;
constexpr int KW  = GK / 2;                    // 256 u32 per row (packed)
constexpr int GBM = 128, GBN = 64, GBK = 16;
constexpr int TW  = GBK / 2;                   // 8 u32 per row per tile
constexpr int LDW = 12;                        // padded row stride (conflict-free)
constexpr int A_SZ = GBM * LDW;                // 1536 u32
constexpr int W_SZ = GBN * LDW;                // 768 u32

__global__ __launch_bounds__(256) void bf16x2_gemm_kernel(
    const uint32_t* __restrict__ hiX, const uint32_t* __restrict__ loX,
    const uint32_t* __restrict__ hiW, const uint32_t* __restrict__ loW,
    const float* __restrict__ b0, const float* __restrict__ b1,
    const float* __restrict__ b2,
    float* __restrict__ o0, float* __restrict__ o1, float* __restrict__ o2,
    int permute)
{
    __shared__ uint32_t AsH[2][A_SZ];
    __shared__ uint32_t AsL[2][A_SZ];
    __shared__ uint32_t WsH[2][W_SZ];
    __shared__ uint32_t WsL[2][W_SZ];

    const int z = blockIdx.z;
    const float* bias = (z == 0) ? b0 : (z == 1) ? b1 : b2;
    float* out = (z == 0) ? o0 : (z == 1) ? o1 : o2;

    const int tid  = threadIdx.x;
    const int warp = tid >> 5, lane = tid & 31;
    const int wm = warp & 3;        // 0..3 -> m offset
    const int wn = warp >> 2;       // 0..1 -> n offset
    const int m0 = blockIdx.y * GBM;
    const int n0 = blockIdx.x * GBN;
    const int gr = lane >> 2, gc = lane & 3;

    float acc[2][4][4];
    #pragma unroll
    for (int i = 0; i < 2; i++)
        #pragma unroll
        for (int j = 0; j < 4; j++)
            #pragma unroll
            for (int q = 0; q < 4; q++) acc[i][j][q] = 0.0f;

    // per-thread staging coords (all packed u32 units)
    const int arow = tid >> 1, aoff = (tid & 1) * 4;          // A: 1 cp16/plane
    const int wpl  = tid >> 7;                                 // 0=hi, 1=lo
    const int wrow = (tid & 127) >> 1, woff = (tid & 1) * 4;  // W: 1 cp16 total
    const uint32_t* AhP = hiX + (size_t)z * (NX / 2) + (size_t)(m0 + arow) * KW + aoff;
    const uint32_t* AlP = loX + (size_t)z * (NX / 2) + (size_t)(m0 + arow) * KW + aoff;
    const uint32_t* WP  = (wpl ? loW : hiW) + (size_t)z * (Dc * Dc / 2)
                          + (size_t)(n0 + wrow) * KW + woff;
    uint32_t* WsD0 = wpl ? &WsL[0][wrow * LDW + woff] : &WsH[0][wrow * LDW + woff];
    uint32_t* WsD1 = wpl ? &WsL[1][wrow * LDW + woff] : &WsH[1][wrow * LDW + woff];

    // stage tile 0 into buffer 0
    cp16(&AsH[0][arow * LDW + aoff], AhP);
    cp16(&AsL[0][arow * LDW + aoff], AlP);
    cp16(WsD0, WP);
    cp_commit();

    constexpr int NT = GK / GBK;   // 32 tiles
    for (int t = 0; t < NT; ++t) {
        const int buf = t & 1;
        if (t + 1 < NT) {
            const int o = (t + 1) * TW;
            cp16(&AsH[1 - buf][arow * LDW + aoff], AhP + o);
            cp16(&AsL[1 - buf][arow * LDW + aoff], AlP + o);
            cp16((1 - buf) ? WsD1 : WsD0, WP + o);
            cp_commit();
            cp_wait<1>();   // tile t landed; t+1 still streaming
        } else {
            cp_wait<0>();
        }
        __syncthreads();

        const uint32_t* aHs = AsH[buf];
        const uint32_t* aLs = AsL[buf];
        const uint32_t* wHs = WsH[buf];
        const uint32_t* wLs = WsL[buf];

        uint32_t aH[2][4], aL[2][4];
        #pragma unroll
        for (int ti = 0; ti < 2; ti++) {
            int mb = wm * 32 + ti * 16;
            int i0 = (mb + gr)     * LDW + gc;
            int i1 = (mb + gr + 8) * LDW + gc;
            aH[ti][0] = aHs[i0];     aH[ti][1] = aHs[i1];
            aH[ti][2] = aHs[i0 + 4]; aH[ti][3] = aHs[i1 + 4];
            aL[ti][0] = aLs[i0];     aL[ti][1] = aLs[i1];
            aL[ti][2] = aLs[i0 + 4]; aL[ti][3] = aLs[i1 + 4];
        }
        uint32_t bH[4][2], bL[4][2];
        #pragma unroll
        for (int tj = 0; tj < 4; tj++) {
            int nb = (wn * 32 + tj * 8 + gr) * LDW + gc;
            bH[tj][0] = wHs[nb]; bH[tj][1] = wHs[nb + 4];
            bL[tj][0] = wLs[nb]; bL[tj][1] = wLs[nb + 4];
        }
        #pragma unroll
        for (int ti = 0; ti < 2; ti++)
            #pragma unroll
            for (int tj = 0; tj < 4; tj++) {
                mma_bf16(acc[ti][tj], aL[ti], bH[tj]);
                mma_bf16(acc[ti][tj], aH[ti], bL[tj]);
                mma_bf16(acc[ti][tj], aH[ti], bH[tj]);
            }
        __syncthreads();
    }

    // ---- epilogue: bias + (optional) head permute, float2 stores ----
    #pragma unroll
    for (int ti = 0; ti < 2; ti++) {
        #pragma unroll
        for (int tj = 0; tj < 4; tj++) {
            int n = n0 + wn * 32 + tj * 8 + gc * 2;
            float bb0 = bias[n], bb1 = bias[n + 1];
            #pragma unroll
            for (int half = 0; half < 2; half++) {   // rows gr and gr+8
                int m = m0 + wm * 32 + ti * 16 + gr + half * 8;
                float2 v;
                v.x = acc[ti][tj][half * 2 + 0] + bb0;
                v.y = acc[ti][tj][half * 2 + 1] + bb1;
                if (!permute) {
                    *reinterpret_cast<float2*>(out + (size_t)m * Dc + n) = v;
                } else {
                    int b = m >> 11, l = m & 2047;
                    int h = n >> 6, d = n & 63;
                    *reinterpret_cast<float2*>(
                        out + (((size_t)(b * Hc + h)) * Lc + l) * DKc + d) = v;
                }
            }
        }
    }
}

// ---------------- V mean over L per (b,h,d): two-stage ----------------------
__global__ __launch_bounds__(256) void vmean1_kernel()
{
    int blk = blockIdx.x;             // 0..255
    int bh = blk >> 3, seg = blk & 7; // 8 segments of 256 rows
    int tid = threadIdx.x;
    int d = tid & 63, part = tid >> 6;  // 4 parts of 64 rows
    const float* Vb = g_V + ((size_t)bh * Lc + seg * 256 + part * 64) * DKc;
    float acc = 0.0f;
    for (int l = 0; l < 64; ++l) acc += Vb[(size_t)l * 64 + d];
    __shared__ float red[256];
    red[tid] = acc;
    __syncthreads();
    if (part == 0)
        g_vpart[(bh * 8 + seg) * 64 + d] =
            red[d] + red[d + 64] + red[d + 128] + red[d + 192];
}

__global__ __launch_bounds__(64) void vmean2_kernel()
{
    int bh = blockIdx.x, d = threadIdx.x;
    float s = 0.0f;
    #pragma unroll
    for (int i = 0; i < 8; i++) s += g_vpart[(bh * 8 + i) * 64 + d];
    g_vmean[bh * 64 + d] = s * (1.0f / Lc);
}

// ---------------- QK_sample + M measure (warp per (b,h,q), unrolled) ---------
template<int UT>
__global__ __launch_bounds__(256) void qk_sample_kernel_u(const int* __restrict__ idxs)
{
    int warp = (blockIdx.x * blockDim.x + threadIdx.x) >> 5;
    int lane = threadIdx.x & 31;
    if (warp >= Bc * Hc * Lc) return;
    int q  = warp % Lc;
    int bh = warp / Lc;

    const float* Qr = g_Q + ((size_t)bh * Lc + q) * 64;
    float q0 = Qr[lane], q1 = Qr[lane + 32];

    const int* ip = idxs + (size_t)q * UT;
    int idx0 = (lane < UT) ? ip[lane] : 0;
    int idx1 = (UT > 32 && lane < UT - 32) ? ip[32 + lane] : 0;

    const float* Kb = g_K + (size_t)bh * Lc * 64;
    float mx = -1e30f, sm = 0.0f;
    #pragma unroll
    for (int j = 0; j < UT; j++) {
        int ki = (j < 32) ? __shfl_sync(0xFFFFFFFFu, idx0, j)
                          : __shfl_sync(0xFFFFFFFFu, idx1, j - 32);
        const float* Kr = Kb + (size_t)ki * 64;
        float p = q0 * Kr[lane] + q1 * Kr[lane + 32];
        #pragma unroll
        for (int o = 16; o > 0; o >>= 1) p += __shfl_xor_sync(0xFFFFFFFFu, p, o);
        mx = fmaxf(mx, p);
        sm += p;
    }
    if (lane == 0) g_M[(size_t)bh * Lc + q] = mx - sm * (1.0f / (float)Lc);
}

// generic fallback (runtime U)
__global__ __launch_bounds__(256) void qk_sample_kernel(const int* __restrict__ idxs, int U)
{
    int warp = (blockIdx.x * blockDim.x + threadIdx.x) >> 5;
    int lane = threadIdx.x & 31;
    if (warp >= Bc * Hc * Lc) return;
    int q  = warp % Lc;
    int bh = warp / Lc;

    const float* Qr = g_Q + ((size_t)bh * Lc + q) * 64;
    float q0 = Qr[lane], q1 = Qr[lane + 32];

    float mx = -1e30f, sm = 0.0f;
    for (int j = 0; j < U; j++) {
        int ki = idxs[q * U + j];
        const float* Kr = g_K + ((size_t)bh * Lc + ki) * 64;
        float p = q0 * Kr[lane] + q1 * Kr[lane + 32];
        #pragma unroll
        for (int o = 16; o > 0; o >>= 1) p += __shfl_xor_sync(0xFFFFFFFFu, p, o);
        mx = fmaxf(mx, p);
        sm += p;
    }
    if (lane == 0) g_M[(size_t)bh * Lc + q] = mx - sm * (1.0f / (float)Lc);
}

// ---------------- top-U per (b,h): iterative argmax over 2048 ----------------
__global__ __launch_bounds__(256) void topk_kernel(int U)
{
    int bh  = blockIdx.x;
    int tid = threadIdx.x;
    __shared__ float vals[Lc];
    __shared__ float rmax[256];
    __shared__ int   ridx[256];

    for (int i = tid; i < Lc; i += 256) vals[i] = g_M[(size_t)bh * Lc + i];
    __syncthreads();

    for (int it = 0; it < U; it++) {
        float best = -1e30f; int bi = Lc;
        for (int i = tid; i < Lc; i += 256) {
            float v = vals[i];
            if (v > best) { best = v; bi = i; }
        }
        rmax[tid] = best; ridx[tid] = bi;
        __syncthreads();
        for (int s = 128; s > 0; s >>= 1) {
            if (tid < s) {
                if (rmax[tid + s] > rmax[tid] ||
                    (rmax[tid + s] == rmax[tid] && ridx[tid + s] < ridx[tid])) {
                    rmax[tid] = rmax[tid + s];
                    ridx[tid] = ridx[tid + s];
                }
            }
            __syncthreads();
        }
        if (tid == 0) {
            g_top[bh * UMAX + it] = ridx[0];
            vals[ridx[0]] = -1e30f;
        }
        __syncthreads();
    }
}

// ---------------- fill context with broadcast V-mean -------------------------
__global__ __launch_bounds__(256) void fill_ctx_kernel()
{
    size_t i = (size_t)blockIdx.x * 256 + threadIdx.x;  // over B*L*D
    int d = (int)(i & 63);
    int h = (int)((i >> 6) & 7);
    int b = (int)(i >> 20);                              // L*H*64 = 2^20
    g_ctx[i] = g_vmean[(b * Hc + h) * 64 + d];
}

// ---------------- flash-style attention for top-u queries (8 per block) ------
__global__ __launch_bounds__(256) void sparse_attn2_kernel(int U)
{
    int bh = blockIdx.x;
    int b  = bh >> 3, h = bh & 7;
    int tid = threadIdx.x, w = tid >> 5, lane = tid & 31;
    int ui = blockIdx.y * 8 + w;
    bool active = ui < U;
    int lq = active ? g_top[bh * UMAX + ui] : 0;

    __shared__ float qv[8][64];
    __shared__ float Ks[64][65];
    __shared__ float Vs[64][65];

    const float* Qr = g_Q + ((size_t)bh * Lc + lq) * 64;
    qv[w][lane]      = Qr[lane]      * 0.125f;   // 1/sqrt(64)
    qv[w][lane + 32] = Qr[lane + 32] * 0.125f;
    __syncthreads();

    float m = -1e30f, l = 0.0f, acc0 = 0.0f, acc1 = 0.0f;

    const float* Kb = g_K + (size_t)bh * Lc * 64;
    const float* Vb = g_V + (size_t)bh * Lc * 64;
    const int row = tid >> 2;           // 0..63
    const int cb  = (tid & 3) * 4;      // col base; strided +16

    for (int kc = 0; kc < Lc / 64; ++kc) {
        #pragma unroll
        for (int s = 0; s < 4; ++s) {
            int c = cb + s * 16;
            const float* kp = Kb + ((size_t)(kc * 64 + row)) * 64 + c;
            const float* vp = Vb + ((size_t)(kc * 64 + row)) * 64 + c;
            float4 kv = *reinterpret_cast<const float4*>(kp);
            float4 vv = *reinterpret_cast<const float4*>(vp);
            Ks[row][c] = kv.x; Ks[row][c+1] = kv.y; Ks[row][c+2] = kv.z; Ks[row][c+3] = kv.w;
            Vs[row][c] = vv.x; Vs[row][c+1] = vv.y; Vs[row][c+2] = vv.z; Vs[row][c+3] = vv.w;
        }
        __syncthreads();

        float s0 = 0.0f, s1 = 0.0f;
        #pragma unroll 16
        for (int c = 0; c < 64; ++c) {
            float qc = qv[w][c];
            s0 = fmaf(qc, Ks[lane][c],      s0);
            s1 = fmaf(qc, Ks[lane + 32][c], s1);
        }

        float cm = fmaxf(s0, s1);
        #pragma unroll
        for (int o = 16; o > 0; o >>= 1)
            cm = fmaxf(cm, __shfl_xor_sync(0xFFFFFFFFu, cm, o));
        float mn = fmaxf(m, cm);
        float corr = expf(m - mn);
        l *= corr; acc0 *= corr; acc1 *= corr;
        float p0 = expf(s0 - mn), p1 = expf(s1 - mn);
        float ps = p0 + p1;
        #pragma unroll
        for (int o = 16; o > 0; o >>= 1)
            ps += __shfl_xor_sync(0xFFFFFFFFu, ps, o);
        l += ps;
        m = mn;

        #pragma unroll 8
        for (int r = 0; r < 32; ++r) {
            float pa = __shfl_sync(0xFFFFFFFFu, p0, r);
            float pb = __shfl_sync(0xFFFFFFFFu, p1, r);
            acc0 = fmaf(pa, Vs[r][lane],           acc0);
            acc1 = fmaf(pa, Vs[r][lane + 32],      acc1);
            acc0 = fmaf(pb, Vs[r + 32][lane],      acc0);
            acc1 = fmaf(pb, Vs[r + 32][lane + 32], acc1);
        }
        __syncthreads();
    }

    if (active) {
        float inv = 1.0f / l;
        float* dst = g_ctx + (((size_t)(b * Lc + lq)) * Hc + h) * 64;
        dst[lane]      = acc0 * inv;
        dst[lane + 32] = acc1 * inv;
    }
}

// ---------------- launch ------------------------------------------------------
extern "C" void kernel_launch(void* const* d_in, const int* in_sizes, int n_in,
                              void* d_out, int out_size)
{
    const float* queries = (const float*)d_in[0];
    const float* keys    = (const float*)d_in[1];
    const float* values  = (const float*)d_in[2];
    const float* Wq = (const float*)d_in[3];
    const float* bq = (const float*)d_in[4];
    const float* Wk = (const float*)d_in[5];
    const float* bk = (const float*)d_in[6];
    const float* Wv = (const float*)d_in[7];
    const float* bv = (const float*)d_in[8];
    const float* Wo = (const float*)d_in[9];
    const float* bo = (const float*)d_in[10];
    const int* index_sample = (const int*)d_in[11];

    int U = in_sizes[11] / Lc;   // 40 for this bench
    if (U > UMAX) U = UMAX;

    float *qp, *kp, *vp, *ctx;
    cudaGetSymbolAddress((void**)&qp,  g_Q);
    cudaGetSymbolAddress((void**)&kp,  g_K);
    cudaGetSymbolAddress((void**)&vp,  g_V);
    cudaGetSymbolAddress((void**)&ctx, g_ctx);
    uint32_t *hiX, *loX, *hiW, *loW;
    cudaGetSymbolAddress((void**)&hiX, g_hiX);
    cudaGetSymbolAddress((void**)&loX, g_loX);
    cudaGetSymbolAddress((void**)&hiW, g_hiW);
    cudaGetSymbolAddress((void**)&loW, g_loW);

    const int WSZ2 = Dc * Dc / 2;          // packed u32 per W plane
    dim3 ggrid3(Dc / 64, (Bc * Lc) / 128, 3);  // merged Q/K/V projections
    dim3 ggrid1(Dc / 64, (Bc * Lc) / 128, 1);
    int warps = Bc * Hc * Lc;
    int n4x = NX / 4;

    // launch idx 3 (the ncu-captured launch) is qk_sample this round.
    presplit_w4_kernel<<<dim3(Dc * Dc / 4 / 256, 4), 256>>>(Wq, Wk, Wv, Wo);  // 0
    presplit_x3_kernel<<<dim3((n4x + 255) / 256, 3), 256>>>(queries, keys, values); // 1

    bf16x2_gemm_kernel<<<ggrid3, 256>>>(hiX, loX, hiW, loW,                   // 2
                                        bq, bk, bv, qp, kp, vp, 1);

    if (U == 40)                                                              // 3 <- profiled
        qk_sample_kernel_u<40><<<(warps * 32) / 256, 256>>>(index_sample);
    else
        qk_sample_kernel<<<(warps * 32) / 256, 256>>>(index_sample, U);

    vmean1_kernel<<<Bc * Hc * 8, 256>>>();                                    // 4
    vmean2_kernel<<<Bc * Hc, 64>>>();                                         // 5

    topk_kernel<<<Bc * Hc, 256>>>(U);                                         // 6

    fill_ctx_kernel<<<(Bc * Lc * Dc) / 256, 256>>>();                         // 7

    sparse_attn2_kernel<<<dim3(Bc * Hc, (U + 7) / 8), 256>>>(U);              // 8

    // ctx planes reuse slot 0
    presplit_x3_kernel<<<dim3((n4x + 255) / 256, 1), 256>>>(ctx, ctx, ctx);   // 9

    bf16x2_gemm_kernel<<<ggrid1, 256>>>(hiX, loX, hiW + 3 * WSZ2,             // 10
                                        loW + 3 * WSZ2, bo, bo, bo,
                                        (float*)d_out, nullptr, nullptr, 0);
}

// round 11
// speedup vs baseline: 1.4165x; 1.0203x over previous
#include <cuda_runtime.h>
#include <cuda_bf16.h>
#include <math.h>
#include <stdint.h>

// Problem constants (fixed shapes for this bench)
constexpr int Bc  = 4;
constexpr int Lc  = 2048;
constexpr int Dc  = 512;
constexpr int Hc  = 8;
constexpr int DKc = 64;
constexpr int UMAX = 64;   // safety cap for top-k storage (actual U = 40)
constexpr int NX  = Bc * Lc * Dc;     // elements in one (B,L,D) tensor

// ---------------- scratch (device globals; no allocation allowed) ------------
__device__ float g_Q[Bc*Hc*Lc*DKc];      // (b,h,l,d)  16 MB
__device__ float g_K[Bc*Hc*Lc*DKc];      // 16 MB
__device__ float g_V[Bc*Hc*Lc*DKc];      // 16 MB
__device__ float g_ctx[Bc*Lc*Dc];        // (b,l,h,d) = (b,l,D)  16 MB
__device__ float g_M[Bc*Hc*Lc];          // sparsity measure
__device__ int   g_top[Bc*Hc*UMAX];      // top-u indices per (b,h)
__device__ float g_vmean[Bc*Hc*DKc];     // V mean over L
__device__ float g_vpart[Bc*Hc*8*DKc];   // partial V sums

// bf16 hi/lo planes, packed 2 consecutive-k bf16 per u32 (low half = even k)
__device__ uint32_t g_hiX[3*NX/2], g_loX[3*NX/2];   // 3 input slots (Q/K/V or ctx in slot 0)
__device__ uint32_t g_hiW[4*Dc*Dc/2], g_loW[4*Dc*Dc/2];

// ---------------- bf16 split helpers ------------------------------------------
__device__ __forceinline__ void split_pack2(float a, float b,
                                            uint32_t& hi, uint32_t& lo) {
    __nv_bfloat16 ha = __float2bfloat16_rn(a);
    __nv_bfloat16 hb = __float2bfloat16_rn(b);
    float ra = a - __bfloat162float(ha);
    float rb = b - __bfloat162float(hb);
    __nv_bfloat162 hv = __floats2bfloat162_rn(__bfloat162float(ha), __bfloat162float(hb));
    __nv_bfloat162 lv = __floats2bfloat162_rn(ra, rb);
    hi = *reinterpret_cast<uint32_t*>(&hv);
    lo = *reinterpret_cast<uint32_t*>(&lv);
}

__device__ __forceinline__ void mma_bf16(float (&d)[4], const uint32_t (&a)[4],
                                         const uint32_t (&b)[2]) {
    asm volatile(
        "mma.sync.aligned.m16n8k16.row.col.f32.bf16.bf16.f32 "
        "{%0,%1,%2,%3}, {%4,%5,%6,%7}, {%8,%9}, {%0,%1,%2,%3};"
        : "+f"(d[0]), "+f"(d[1]), "+f"(d[2]), "+f"(d[3])
        : "r"(a[0]), "r"(a[1]), "r"(a[2]), "r"(a[3]), "r"(b[0]), "r"(b[1]));
}

__device__ __forceinline__ void cp16(void* smem, const void* gmem) {
    uint32_t s = (uint32_t)__cvta_generic_to_shared(smem);
    asm volatile("cp.async.cg.shared.global [%0], [%1], 16;" :: "r"(s), "l"(gmem));
}
__device__ __forceinline__ void cp_commit() {
    asm volatile("cp.async.commit_group;" ::: "memory");
}
template<int N>
__device__ __forceinline__ void cp_wait() {
    asm volatile("cp.async.wait_group %0;" :: "n"(N) : "memory");
}

// ---------------- pre-split kernels -------------------------------------------
// X inputs: blockIdx.y selects tensor, writes slot y of g_hiX/g_loX.
__global__ __launch_bounds__(256) void presplit_x3_kernel(
    const float* __restrict__ x0, const float* __restrict__ x1,
    const float* __restrict__ x2)
{
    const float* srcs[3] = {x0, x1, x2};
    int z = blockIdx.y;
    const float* src = srcs[z];
    int i = blockIdx.x * 256 + threadIdx.x;    // over NX/4 float4s
    if (i >= NX / 4) return;
    float4 v = reinterpret_cast<const float4*>(src)[i];
    uint32_t h0, l0, h1, l1;
    split_pack2(v.x, v.y, h0, l0);
    split_pack2(v.z, v.w, h1, l1);
    size_t o = (size_t)z * (NX / 2) + i * 2;
    g_hiX[o] = h0; g_hiX[o + 1] = h1;
    g_loX[o] = l0; g_loX[o + 1] = l1;
}

// two weights per launch (so the W pre-split occupies 2 launch slots)
__global__ __launch_bounds__(256) void presplit_w2_kernel(
    const float* __restrict__ w0, const float* __restrict__ w1, int slot0)
{
    const float* srcs[2] = {w0, w1};
    int wsel = slot0 + blockIdx.y;
    const float* src = srcs[blockIdx.y];
    int i = blockIdx.x * 256 + threadIdx.x;    // over Dc*Dc/4 float4s
    float4 v = reinterpret_cast<const float4*>(src)[i];
    uint32_t h0, l0, h1, l1;
    split_pack2(v.x, v.y, h0, l0);
    split_pack2(v.z, v.w, h1, l1);
    size_t o = (size_t)wsel * (Dc * Dc / 2) + i * 2;
    g_hiW[o] = h0; g_hiW[o + 1] = h1;
    g_loW[o] = l0; g_loW[o + 1] = l1;
}

// ---------------- Split-bf16 GEMM on packed planes ----------------------------
// out_z = X_z[M,512] @ W_z[512,512]^T + bias_z    (z = blockIdx.z)
// acc += aL*bH + aH*bL + aH*bH (3 bf16 m16n8k16 MMAs). Hot loop: LDS+MMA only.
// BM=128, BN=64, BK=16, 256 threads (8 warps, 4x2), warp tile 32x32.
// permute=0: out[m*512+n] ; permute=1: out[((b*H+h)*L+l)*64+d], m=(b,l), n=(h,d)
constexpr int GK  = 512;
constexpr int KW  = GK / 2;                    // 256 u32 per row (packed)
constexpr int GBM = 128, GBN = 64, GBK = 16;
constexpr int TW  = GBK / 2;                   // 8 u32 per row per tile
constexpr int LDW = 12;                        // padded row stride (conflict-free)
constexpr int A_SZ = GBM * LDW;                // 1536 u32
constexpr int W_SZ = GBN * LDW;                // 768 u32

__global__ __launch_bounds__(256) void bf16x2_gemm_kernel(
    const uint32_t* __restrict__ hiX, const uint32_t* __restrict__ loX,
    const uint32_t* __restrict__ hiW, const uint32_t* __restrict__ loW,
    const float* __restrict__ b0, const float* __restrict__ b1,
    const float* __restrict__ b2,
    float* __restrict__ o0, float* __restrict__ o1, float* __restrict__ o2,
    int permute)
{
    __shared__ uint32_t AsH[2][A_SZ];
    __shared__ uint32_t AsL[2][A_SZ];
    __shared__ uint32_t WsH[2][W_SZ];
    __shared__ uint32_t WsL[2][W_SZ];

    const int z = blockIdx.z;
    const float* bias = (z == 0) ? b0 : (z == 1) ? b1 : b2;
    float* out = (z == 0) ? o0 : (z == 1) ? o1 : o2;

    const int tid  = threadIdx.x;
    const int warp = tid >> 5, lane = tid & 31;
    const int wm = warp & 3;        // 0..3 -> m offset
    const int wn = warp >> 2;       // 0..1 -> n offset
    const int m0 = blockIdx.y * GBM;
    const int n0 = blockIdx.x * GBN;
    const int gr = lane >> 2, gc = lane & 3;

    float acc[2][4][4];
    #pragma unroll
    for (int i = 0; i < 2; i++)
        #pragma unroll
        for (int j = 0; j < 4; j++)
            #pragma unroll
            for (int q = 0; q < 4; q++) acc[i][j][q] = 0.0f;

    // per-thread staging coords (all packed u32 units)
    const int arow = tid >> 1, aoff = (tid & 1) * 4;          // A: 1 cp16/plane
    const int wpl  = tid >> 7;                                 // 0=hi, 1=lo
    const int wrow = (tid & 127) >> 1, woff = (tid & 1) * 4;  // W: 1 cp16 total
    const uint32_t* AhP = hiX + (size_t)z * (NX / 2) + (size_t)(m0 + arow) * KW + aoff;
    const uint32_t* AlP = loX + (size_t)z * (NX / 2) + (size_t)(m0 + arow) * KW + aoff;
    const uint32_t* WP  = (wpl ? loW : hiW) + (size_t)z * (Dc * Dc / 2)
                          + (size_t)(n0 + wrow) * KW + woff;
    uint32_t* WsD0 = wpl ? &WsL[0][wrow * LDW + woff] : &WsH[0][wrow * LDW + woff];
    uint32_t* WsD1 = wpl ? &WsL[1][wrow * LDW + woff] : &WsH[1][wrow * LDW + woff];

    // stage tile 0 into buffer 0
    cp16(&AsH[0][arow * LDW + aoff], AhP);
    cp16(&AsL[0][arow * LDW + aoff], AlP);
    cp16(WsD0, WP);
    cp_commit();

    constexpr int NT = GK / GBK;   // 32 tiles
    for (int t = 0; t < NT; ++t) {
        const int buf = t & 1;
        if (t + 1 < NT) {
            const int o = (t + 1) * TW;
            cp16(&AsH[1 - buf][arow * LDW + aoff], AhP + o);
            cp16(&AsL[1 - buf][arow * LDW + aoff], AlP + o);
            cp16((1 - buf) ? WsD1 : WsD0, WP + o);
            cp_commit();
            cp_wait<1>();   // tile t landed; t+1 still streaming
        } else {
            cp_wait<0>();
        }
        __syncthreads();

        const uint32_t* aHs = AsH[buf];
        const uint32_t* aLs = AsL[buf];
        const uint32_t* wHs = WsH[buf];
        const uint32_t* wLs = WsL[buf];

        uint32_t aH[2][4], aL[2][4];
        #pragma unroll
        for (int ti = 0; ti < 2; ti++) {
            int mb = wm * 32 + ti * 16;
            int i0 = (mb + gr)     * LDW + gc;
            int i1 = (mb + gr + 8) * LDW + gc;
            aH[ti][0] = aHs[i0];     aH[ti][1] = aHs[i1];
            aH[ti][2] = aHs[i0 + 4]; aH[ti][3] = aHs[i1 + 4];
            aL[ti][0] = aLs[i0];     aL[ti][1] = aLs[i1];
            aL[ti][2] = aLs[i0 + 4]; aL[ti][3] = aLs[i1 + 4];
        }
        uint32_t bH[4][2], bL[4][2];
        #pragma unroll
        for (int tj = 0; tj < 4; tj++) {
            int nb = (wn * 32 + tj * 8 + gr) * LDW + gc;
            bH[tj][0] = wHs[nb]; bH[tj][1] = wHs[nb + 4];
            bL[tj][0] = wLs[nb]; bL[tj][1] = wLs[nb + 4];
        }
        #pragma unroll
        for (int ti = 0; ti < 2; ti++)
            #pragma unroll
            for (int tj = 0; tj < 4; tj++) {
                mma_bf16(acc[ti][tj], aL[ti], bH[tj]);
                mma_bf16(acc[ti][tj], aH[ti], bL[tj]);
                mma_bf16(acc[ti][tj], aH[ti], bH[tj]);
            }
        __syncthreads();
    }

    // ---- epilogue: bias + (optional) head permute, float2 stores ----
    #pragma unroll
    for (int ti = 0; ti < 2; ti++) {
        #pragma unroll
        for (int tj = 0; tj < 4; tj++) {
            int n = n0 + wn * 32 + tj * 8 + gc * 2;
            float bb0 = bias[n], bb1 = bias[n + 1];
            #pragma unroll
            for (int half = 0; half < 2; half++) {   // rows gr and gr+8
                int m = m0 + wm * 32 + ti * 16 + gr + half * 8;
                float2 v;
                v.x = acc[ti][tj][half * 2 + 0] + bb0;
                v.y = acc[ti][tj][half * 2 + 1] + bb1;
                if (!permute) {
                    *reinterpret_cast<float2*>(out + (size_t)m * Dc + n) = v;
                } else {
                    int b = m >> 11, l = m & 2047;
                    int h = n >> 6, d = n & 63;
                    *reinterpret_cast<float2*>(
                        out + (((size_t)(b * Hc + h)) * Lc + l) * DKc + d) = v;
                }
            }
        }
    }
}

// ---------------- V mean over L per (b,h,d): two-stage ----------------------
__global__ __launch_bounds__(256) void vmean1_kernel()
{
    int blk = blockIdx.x;             // 0..255
    int bh = blk >> 3, seg = blk & 7; // 8 segments of 256 rows
    int tid = threadIdx.x;
    int d = tid & 63, part = tid >> 6;  // 4 parts of 64 rows
    const float* Vb = g_V + ((size_t)bh * Lc + seg * 256 + part * 64) * DKc;
    float acc = 0.0f;
    for (int l = 0; l < 64; ++l) acc += Vb[(size_t)l * 64 + d];
    __shared__ float red[256];
    red[tid] = acc;
    __syncthreads();
    if (part == 0)
        g_vpart[(bh * 8 + seg) * 64 + d] =
            red[d] + red[d + 64] + red[d + 128] + red[d + 192];
}

__global__ __launch_bounds__(64) void vmean2_kernel()
{
    int bh = blockIdx.x, d = threadIdx.x;
    float s = 0.0f;
    #pragma unroll
    for (int i = 0; i < 8; i++) s += g_vpart[(bh * 8 + i) * 64 + d];
    g_vmean[bh * 64 + d] = s * (1.0f / Lc);
}

// ---------------- QK_sample + M (warp per query, butterfly multi-reduce) -----
// Batch of 32 keys: lane computes partial dot p[j] for all 32 j, then a
// 31-shfl xor-butterfly leaves lane L holding the COMPLETE dot of key j=L.
template<int UT>
__global__ __launch_bounds__(256) void qk_sample_kernel_u(const int* __restrict__ idxs)
{
    static_assert(UT > 32 && UT <= 64, "expects 32 < UT <= 64");
    int warp = (blockIdx.x * blockDim.x + threadIdx.x) >> 5;
    int lane = threadIdx.x & 31;
    if (warp >= Bc * Hc * Lc) return;
    int q  = warp % Lc;
    int bh = warp / Lc;

    const float* Qr = g_Q + ((size_t)bh * Lc + q) * 64;
    float q0 = Qr[lane], q1 = Qr[lane + 32];

    const int* ip = idxs + (size_t)q * UT;
    int idx0 = ip[lane];                                      // j = lane
    int idx1 = (lane < UT - 32) ? ip[32 + lane] : ip[UT - 1]; // pad dups last row

    const float* Kb = g_K + (size_t)bh * Lc * 64;

    float tot0, tot1;
    #pragma unroll
    for (int batch = 0; batch < 2; batch++) {
        int src = batch ? idx1 : idx0;
        float p[32];
        #pragma unroll
        for (int j = 0; j < 32; j++) {
            int ki = __shfl_sync(0xFFFFFFFFu, src, j);
            const float* Kr = Kb + (size_t)ki * 64;
            p[j] = fmaf(q0, Kr[lane], q1 * Kr[lane + 32]);
        }
        // xor-butterfly multi-reduce: lane ends with full sum of p[lane]
        #pragma unroll
        for (int o = 16; o >= 1; o >>= 1) {
            bool hi = (lane & o) != 0;
            #pragma unroll
            for (int j = 0; j < o; j++) {
                float a = p[j], b = p[j + o];
                float mine = hi ? b : a;
                float send = hi ? a : b;
                float theirs = __shfl_xor_sync(0xFFFFFFFFu, send, o);
                p[j] = mine + theirs;
            }
        }
        if (batch == 0) tot0 = p[0]; else tot1 = p[0];
    }

    bool v1 = (lane < UT - 32);
    float mx = fmaxf(tot0, v1 ? tot1 : -1e30f);
    float sm = tot0 + (v1 ? tot1 : 0.0f);
    #pragma unroll
    for (int o = 16; o > 0; o >>= 1) {
        mx = fmaxf(mx, __shfl_xor_sync(0xFFFFFFFFu, mx, o));
        sm += __shfl_xor_sync(0xFFFFFFFFu, sm, o);
    }
    if (lane == 0) g_M[(size_t)bh * Lc + q] = mx - sm * (1.0f / (float)Lc);
}

// generic fallback (runtime U)
__global__ __launch_bounds__(256) void qk_sample_kernel(const int* __restrict__ idxs, int U)
{
    int warp = (blockIdx.x * blockDim.x + threadIdx.x) >> 5;
    int lane = threadIdx.x & 31;
    if (warp >= Bc * Hc * Lc) return;
    int q  = warp % Lc;
    int bh = warp / Lc;

    const float* Qr = g_Q + ((size_t)bh * Lc + q) * 64;
    float q0 = Qr[lane], q1 = Qr[lane + 32];

    float mx = -1e30f, sm = 0.0f;
    for (int j = 0; j < U; j++) {
        int ki = idxs[q * U + j];
        const float* Kr = g_K + ((size_t)bh * Lc + ki) * 64;
        float p = q0 * Kr[lane] + q1 * Kr[lane + 32];
        #pragma unroll
        for (int o = 16; o > 0; o >>= 1) p += __shfl_xor_sync(0xFFFFFFFFu, p, o);
        mx = fmaxf(mx, p);
        sm += p;
    }
    if (lane == 0) g_M[(size_t)bh * Lc + q] = mx - sm * (1.0f / (float)Lc);
}

// ---------------- top-U per (b,h): iterative argmax over 2048 ----------------
__global__ __launch_bounds__(256) void topk_kernel(int U)
{
    int bh  = blockIdx.x;
    int tid = threadIdx.x;
    __shared__ float vals[Lc];
    __shared__ float rmax[256];
    __shared__ int   ridx[256];

    for (int i = tid; i < Lc; i += 256) vals[i] = g_M[(size_t)bh * Lc + i];
    __syncthreads();

    for (int it = 0; it < U; it++) {
        float best = -1e30f; int bi = Lc;
        for (int i = tid; i < Lc; i += 256) {
            float v = vals[i];
            if (v > best) { best = v; bi = i; }
        }
        rmax[tid] = best; ridx[tid] = bi;
        __syncthreads();
        for (int s = 128; s > 0; s >>= 1) {
            if (tid < s) {
                if (rmax[tid + s] > rmax[tid] ||
                    (rmax[tid + s] == rmax[tid] && ridx[tid + s] < ridx[tid])) {
                    rmax[tid] = rmax[tid + s];
                    ridx[tid] = ridx[tid + s];
                }
            }
            __syncthreads();
        }
        if (tid == 0) {
            g_top[bh * UMAX + it] = ridx[0];
            vals[ridx[0]] = -1e30f;
        }
        __syncthreads();
    }
}

// ---------------- fill context with broadcast V-mean -------------------------
__global__ __launch_bounds__(256) void fill_ctx_kernel()
{
    size_t i = (size_t)blockIdx.x * 256 + threadIdx.x;  // over B*L*D
    int d = (int)(i & 63);
    int h = (int)((i >> 6) & 7);
    int b = (int)(i >> 20);                              // L*H*64 = 2^20
    g_ctx[i] = g_vmean[(b * Hc + h) * 64 + d];
}

// ---------------- flash-style attention for top-u queries (8 per block) ------
__global__ __launch_bounds__(256) void sparse_attn2_kernel(int U)
{
    int bh = blockIdx.x;
    int b  = bh >> 3, h = bh & 7;
    int tid = threadIdx.x, w = tid >> 5, lane = tid & 31;
    int ui = blockIdx.y * 8 + w;
    bool active = ui < U;
    int lq = active ? g_top[bh * UMAX + ui] : 0;

    __shared__ float qv[8][64];
    __shared__ float Ks[64][65];
    __shared__ float Vs[64][65];

    const float* Qr = g_Q + ((size_t)bh * Lc + lq) * 64;
    qv[w][lane]      = Qr[lane]      * 0.125f;   // 1/sqrt(64)
    qv[w][lane + 32] = Qr[lane + 32] * 0.125f;
    __syncthreads();

    float m = -1e30f, l = 0.0f, acc0 = 0.0f, acc1 = 0.0f;

    const float* Kb = g_K + (size_t)bh * Lc * 64;
    const float* Vb = g_V + (size_t)bh * Lc * 64;
    const int row = tid >> 2;           // 0..63
    const int cb  = (tid & 3) * 4;      // col base; strided +16

    for (int kc = 0; kc < Lc / 64; ++kc) {
        #pragma unroll
        for (int s = 0; s < 4; ++s) {
            int c = cb + s * 16;
            const float* kp = Kb + ((size_t)(kc * 64 + row)) * 64 + c;
            const float* vp = Vb + ((size_t)(kc * 64 + row)) * 64 + c;
            float4 kv = *reinterpret_cast<const float4*>(kp);
            float4 vv = *reinterpret_cast<const float4*>(vp);
            Ks[row][c] = kv.x; Ks[row][c+1] = kv.y; Ks[row][c+2] = kv.z; Ks[row][c+3] = kv.w;
            Vs[row][c] = vv.x; Vs[row][c+1] = vv.y; Vs[row][c+2] = vv.z; Vs[row][c+3] = vv.w;
        }
        __syncthreads();

        float s0 = 0.0f, s1 = 0.0f;
        #pragma unroll 16
        for (int c = 0; c < 64; ++c) {
            float qc = qv[w][c];
            s0 = fmaf(qc, Ks[lane][c],      s0);
            s1 = fmaf(qc, Ks[lane + 32][c], s1);
        }

        float cm = fmaxf(s0, s1);
        #pragma unroll
        for (int o = 16; o > 0; o >>= 1)
            cm = fmaxf(cm, __shfl_xor_sync(0xFFFFFFFFu, cm, o));
        float mn = fmaxf(m, cm);
        float corr = expf(m - mn);
        l *= corr; acc0 *= corr; acc1 *= corr;
        float p0 = expf(s0 - mn), p1 = expf(s1 - mn);
        float ps = p0 + p1;
        #pragma unroll
        for (int o = 16; o > 0; o >>= 1)
            ps += __shfl_xor_sync(0xFFFFFFFFu, ps, o);
        l += ps;
        m = mn;

        #pragma unroll 8
        for (int r = 0; r < 32; ++r) {
            float pa = __shfl_sync(0xFFFFFFFFu, p0, r);
            float pb = __shfl_sync(0xFFFFFFFFu, p1, r);
            acc0 = fmaf(pa, Vs[r][lane],           acc0);
            acc1 = fmaf(pa, Vs[r][lane + 32],      acc1);
            acc0 = fmaf(pb, Vs[r + 32][lane],      acc0);
            acc1 = fmaf(pb, Vs[r + 32][lane + 32], acc1);
        }
        __syncthreads();
    }

    if (active) {
        float inv = 1.0f / l;
        float* dst = g_ctx + (((size_t)(b * Lc + lq)) * Hc + h) * 64;
        dst[lane]      = acc0 * inv;
        dst[lane + 32] = acc1 * inv;
    }
}

// ---------------- launch ------------------------------------------------------
extern "C" void kernel_launch(void* const* d_in, const int* in_sizes, int n_in,
                              void* d_out, int out_size)
{
    const float* queries = (const float*)d_in[0];
    const float* keys    = (const float*)d_in[1];
    const float* values  = (const float*)d_in[2];
    const float* Wq = (const float*)d_in[3];
    const float* bq = (const float*)d_in[4];
    const float* Wk = (const float*)d_in[5];
    const float* bk = (const float*)d_in[6];
    const float* Wv = (const float*)d_in[7];
    const float* bv = (const float*)d_in[8];
    const float* Wo = (const float*)d_in[9];
    const float* bo = (const float*)d_in[10];
    const int* index_sample = (const int*)d_in[11];

    int U = in_sizes[11] / Lc;   // 40 for this bench
    if (U > UMAX) U = UMAX;

    float *qp, *kp, *vp, *ctx;
    cudaGetSymbolAddress((void**)&qp,  g_Q);
    cudaGetSymbolAddress((void**)&kp,  g_K);
    cudaGetSymbolAddress((void**)&vp,  g_V);
    cudaGetSymbolAddress((void**)&ctx, g_ctx);
    uint32_t *hiX, *loX, *hiW, *loW;
    cudaGetSymbolAddress((void**)&hiX, g_hiX);
    cudaGetSymbolAddress((void**)&loX, g_loX);
    cudaGetSymbolAddress((void**)&hiW, g_hiW);
    cudaGetSymbolAddress((void**)&loW, g_loW);

    const int WSZ2 = Dc * Dc / 2;          // packed u32 per W plane
    dim3 ggrid3(Dc / 64, (Bc * Lc) / 128, 3);  // merged Q/K/V projections
    dim3 ggrid1(Dc / 64, (Bc * Lc) / 128, 1);
    dim3 wgrid(Dc * Dc / 4 / 256, 2);
    int warps = Bc * Hc * Lc;
    int n4x = NX / 4;

    // launch idx 3 (the ncu-captured launch) is the merged QKV GEMM.
    presplit_w2_kernel<<<wgrid, 256>>>(Wq, Wk, 0);                            // 0
    presplit_w2_kernel<<<wgrid, 256>>>(Wv, Wo, 2);                            // 1
    presplit_x3_kernel<<<dim3((n4x + 255) / 256, 3), 256>>>(queries, keys, values); // 2

    bf16x2_gemm_kernel<<<ggrid3, 256>>>(hiX, loX, hiW, loW,                   // 3 <- profiled
                                        bq, bk, bv, qp, kp, vp, 1);

    if (U == 40)                                                              // 4
        qk_sample_kernel_u<40><<<(warps * 32) / 256, 256>>>(index_sample);
    else if (U > 32 && U <= 64)
        qk_sample_kernel_u<64><<<(warps * 32) / 256, 256>>>(index_sample);    // unused here
    else
        qk_sample_kernel<<<(warps * 32) / 256, 256>>>(index_sample, U);

    vmean1_kernel<<<Bc * Hc * 8, 256>>>();                                    // 5
    vmean2_kernel<<<Bc * Hc, 64>>>();                                         // 6

    topk_kernel<<<Bc * Hc, 256>>>(U);                                         // 7

    fill_ctx_kernel<<<(Bc * Lc * Dc) / 256, 256>>>();                         // 8

    sparse_attn2_kernel<<<dim3(Bc * Hc, (U + 7) / 8), 256>>>(U);              // 9

    // ctx planes reuse slot 0
    presplit_x3_kernel<<<dim3((n4x + 255) / 256, 1), 256>>>(ctx, ctx, ctx);   // 10

    bf16x2_gemm_kernel<<<ggrid1, 256>>>(hiX, loX, hiW + 3 * WSZ2,             // 11
                                        loW + 3 * WSZ2, bo, bo, bo,
                                        (float*)d_out, nullptr, nullptr, 0);
}

// round 12
// speedup vs baseline: 1.5412x; 1.0880x over previous
#include <cuda_runtime.h>
#include <cuda_bf16.h>
#include <math.h>
#include <stdint.h>

// Problem constants (fixed shapes for this bench)
constexpr int Bc  = 4;
constexpr int Lc  = 2048;
constexpr int Dc  = 512;
constexpr int Hc  = 8;
constexpr int DKc = 64;
constexpr int UMAX = 64;   // safety cap for top-k storage (actual U = 40)
constexpr int NX  = Bc * Lc * Dc;     // elements in one (B,L,D) tensor

// ---------------- scratch (device globals; no allocation allowed) ------------
__device__ float g_Q[Bc*Hc*Lc*DKc];      // (b,h,l,d)  16 MB
__device__ float g_K[Bc*Hc*Lc*DKc];      // 16 MB
__device__ float g_V[Bc*Hc*Lc*DKc];      // 16 MB
__device__ float g_M[Bc*Hc*Lc];          // sparsity measure
__device__ int   g_top[Bc*Hc*UMAX];      // top-u indices per (b,h)
__device__ float g_vmean[Bc*Hc*DKc];     // V mean over L
__device__ float g_vpart[Bc*Hc*8*DKc];   // partial V sums

// bf16 hi/lo planes, packed 2 consecutive-k bf16 per u32 (low half = even k)
// slot 0 doubles as the ctx planes for the output GEMM.
__device__ uint32_t g_hiX[3*NX/2], g_loX[3*NX/2];
__device__ uint32_t g_hiW[4*Dc*Dc/2], g_loW[4*Dc*Dc/2];

// ---------------- bf16 split helpers ------------------------------------------
__device__ __forceinline__ void split_pack2(float a, float b,
                                            uint32_t& hi, uint32_t& lo) {
    __nv_bfloat16 ha = __float2bfloat16_rn(a);
    __nv_bfloat16 hb = __float2bfloat16_rn(b);
    float ra = a - __bfloat162float(ha);
    float rb = b - __bfloat162float(hb);
    __nv_bfloat162 hv = __floats2bfloat162_rn(__bfloat162float(ha), __bfloat162float(hb));
    __nv_bfloat162 lv = __floats2bfloat162_rn(ra, rb);
    hi = *reinterpret_cast<uint32_t*>(&hv);
    lo = *reinterpret_cast<uint32_t*>(&lv);
}

__device__ __forceinline__ void mma_bf16(float (&d)[4], const uint32_t (&a)[4],
                                         const uint32_t (&b)[2]) {
    asm volatile(
        "mma.sync.aligned.m16n8k16.row.col.f32.bf16.bf16.f32 "
        "{%0,%1,%2,%3}, {%4,%5,%6,%7}, {%8,%9}, {%0,%1,%2,%3};"
        : "+f"(d[0]), "+f"(d[1]), "+f"(d[2]), "+f"(d[3])
        : "r"(a[0]), "r"(a[1]), "r"(a[2]), "r"(a[3]), "r"(b[0]), "r"(b[1]));
}

__device__ __forceinline__ void cp16(void* smem, const void* gmem) {
    uint32_t s = (uint32_t)__cvta_generic_to_shared(smem);
    asm volatile("cp.async.cg.shared.global [%0], [%1], 16;" :: "r"(s), "l"(gmem));
}
__device__ __forceinline__ void cp_commit() {
    asm volatile("cp.async.commit_group;" ::: "memory");
}
template<int N>
__device__ __forceinline__ void cp_wait() {
    asm volatile("cp.async.wait_group %0;" :: "n"(N) : "memory");
}

// ---------------- pre-split kernels -------------------------------------------
__global__ __launch_bounds__(256) void presplit_x3_kernel(
    const float* __restrict__ x0, const float* __restrict__ x1,
    const float* __restrict__ x2)
{
    const float* srcs[3] = {x0, x1, x2};
    int z = blockIdx.y;
    const float* src = srcs[z];
    int i = blockIdx.x * 256 + threadIdx.x;    // over NX/4 float4s
    if (i >= NX / 4) return;
    float4 v = reinterpret_cast<const float4*>(src)[i];
    uint32_t h0, l0, h1, l1;
    split_pack2(v.x, v.y, h0, l0);
    split_pack2(v.z, v.w, h1, l1);
    size_t o = (size_t)z * (NX / 2) + i * 2;
    g_hiX[o] = h0; g_hiX[o + 1] = h1;
    g_loX[o] = l0; g_loX[o + 1] = l1;
}

__global__ __launch_bounds__(256) void presplit_w2_kernel(
    const float* __restrict__ w0, const float* __restrict__ w1, int slot0)
{
    const float* srcs[2] = {w0, w1};
    int wsel = slot0 + blockIdx.y;
    const float* src = srcs[blockIdx.y];
    int i = blockIdx.x * 256 + threadIdx.x;    // over Dc*Dc/4 float4s
    float4 v = reinterpret_cast<const float4*>(src)[i];
    uint32_t h0, l0, h1, l1;
    split_pack2(v.x, v.y, h0, l0);
    split_pack2(v.z, v.w, h1, l1);
    size_t o = (size_t)wsel * (Dc * Dc / 2) + i * 2;
    g_hiW[o] = h0; g_hiW[o + 1] = h1;
    g_loW[o] = l0; g_loW[o + 1] = l1;
}

// ---------------- Split-bf16 GEMM, 128x128 block ------------------------------
// out_z = X_z[M,512] @ W_z[512,512]^T + bias_z    (z = blockIdx.z)
// acc += aL*bH + aH*bL + aH*bH (3 bf16 m16n8k16 MMAs).
// BM=128, BN=128, BK=16, 256 threads (8 warps, 4m x 2n), warp tile 32x64.
// 48 MMAs per warp per tile against 48 fragment LDS (ratio 1.0).
constexpr int GK  = 512;
constexpr int KW  = GK / 2;                    // 256 u32 per row (packed)
constexpr int GBM = 128, GBN = 128, GBK = 16;
constexpr int TW  = GBK / 2;                   // 8 u32 per row per tile
constexpr int LDW = 12;                        // padded row stride (conflict-free)
constexpr int A_SZ = GBM * LDW;                // 1536 u32
constexpr int W_SZ = GBN * LDW;                // 1536 u32

__global__ __launch_bounds__(256) void bf16x2_gemm_kernel(
    const uint32_t* __restrict__ hiX, const uint32_t* __restrict__ loX,
    const uint32_t* __restrict__ hiW, const uint32_t* __restrict__ loW,
    const float* __restrict__ b0, const float* __restrict__ b1,
    const float* __restrict__ b2,
    float* __restrict__ o0, float* __restrict__ o1, float* __restrict__ o2,
    int permute)
{
    __shared__ uint32_t AsH[2][A_SZ];
    __shared__ uint32_t AsL[2][A_SZ];
    __shared__ uint32_t WsH[2][W_SZ];
    __shared__ uint32_t WsL[2][W_SZ];

    const int z = blockIdx.z;
    const float* bias = (z == 0) ? b0 : (z == 1) ? b1 : b2;
    float* out = (z == 0) ? o0 : (z == 1) ? o1 : o2;

    const int tid  = threadIdx.x;
    const int warp = tid >> 5, lane = tid & 31;
    const int wm = warp & 3;        // 0..3 -> m offset (x32)
    const int wn = warp >> 2;       // 0..1 -> n offset (x64)
    const int m0 = blockIdx.y * GBM;
    const int n0 = blockIdx.x * GBN;
    const int gr = lane >> 2, gc = lane & 3;

    float acc[2][8][4];
    #pragma unroll
    for (int i = 0; i < 2; i++)
        #pragma unroll
        for (int j = 0; j < 8; j++)
            #pragma unroll
            for (int q = 0; q < 4; q++) acc[i][j][q] = 0.0f;

    // per-thread staging coords (packed u32 units); 2 cp16 each for A and W
    const int srow = tid >> 1, soff = (tid & 1) * 4;
    const uint32_t* AhP = hiX + (size_t)z * (NX / 2) + (size_t)(m0 + srow) * KW + soff;
    const uint32_t* AlP = loX + (size_t)z * (NX / 2) + (size_t)(m0 + srow) * KW + soff;
    const uint32_t* WhP = hiW + (size_t)z * (Dc * Dc / 2) + (size_t)(n0 + srow) * KW + soff;
    const uint32_t* WlP = loW + (size_t)z * (Dc * Dc / 2) + (size_t)(n0 + srow) * KW + soff;
    const int sidx = srow * LDW + soff;

    // stage tile 0 into buffer 0
    cp16(&AsH[0][sidx], AhP);
    cp16(&AsL[0][sidx], AlP);
    cp16(&WsH[0][sidx], WhP);
    cp16(&WsL[0][sidx], WlP);
    cp_commit();

    constexpr int NT = GK / GBK;   // 32 tiles
    for (int t = 0; t < NT; ++t) {
        const int buf = t & 1;
        if (t + 1 < NT) {
            const int o = (t + 1) * TW;
            cp16(&AsH[1 - buf][sidx], AhP + o);
            cp16(&AsL[1 - buf][sidx], AlP + o);
            cp16(&WsH[1 - buf][sidx], WhP + o);
            cp16(&WsL[1 - buf][sidx], WlP + o);
            cp_commit();
            cp_wait<1>();   // tile t landed; t+1 still streaming
        } else {
            cp_wait<0>();
        }
        __syncthreads();

        const uint32_t* aHs = AsH[buf];
        const uint32_t* aLs = AsL[buf];
        const uint32_t* wHs = WsH[buf];
        const uint32_t* wLs = WsL[buf];

        uint32_t aH[2][4], aL[2][4];
        #pragma unroll
        for (int ti = 0; ti < 2; ti++) {
            int mb = wm * 32 + ti * 16;
            int i0 = (mb + gr)     * LDW + gc;
            int i1 = (mb + gr + 8) * LDW + gc;
            aH[ti][0] = aHs[i0];     aH[ti][1] = aHs[i1];
            aH[ti][2] = aHs[i0 + 4]; aH[ti][3] = aHs[i1 + 4];
            aL[ti][0] = aLs[i0];     aL[ti][1] = aLs[i1];
            aL[ti][2] = aLs[i0 + 4]; aL[ti][3] = aLs[i1 + 4];
        }
        // tj processed in two halves of 4 to cap register pressure
        #pragma unroll
        for (int half = 0; half < 2; half++) {
            uint32_t bH[4][2], bL[4][2];
            #pragma unroll
            for (int tj = 0; tj < 4; tj++) {
                int nb = (wn * 64 + (half * 4 + tj) * 8 + gr) * LDW + gc;
                bH[tj][0] = wHs[nb]; bH[tj][1] = wHs[nb + 4];
                bL[tj][0] = wLs[nb]; bL[tj][1] = wLs[nb + 4];
            }
            #pragma unroll
            for (int ti = 0; ti < 2; ti++)
                #pragma unroll
                for (int tj = 0; tj < 4; tj++) {
                    mma_bf16(acc[ti][half * 4 + tj], aL[ti], bH[tj]);
                    mma_bf16(acc[ti][half * 4 + tj], aH[ti], bL[tj]);
                    mma_bf16(acc[ti][half * 4 + tj], aH[ti], bH[tj]);
                }
        }
        __syncthreads();
    }

    // ---- epilogue: bias + (optional) head permute, float2 stores ----
    #pragma unroll
    for (int ti = 0; ti < 2; ti++) {
        #pragma unroll
        for (int tj = 0; tj < 8; tj++) {
            int n = n0 + wn * 64 + tj * 8 + gc * 2;
            float bb0 = bias[n], bb1 = bias[n + 1];
            #pragma unroll
            for (int half = 0; half < 2; half++) {   // rows gr and gr+8
                int m = m0 + wm * 32 + ti * 16 + gr + half * 8;
                float2 v;
                v.x = acc[ti][tj][half * 2 + 0] + bb0;
                v.y = acc[ti][tj][half * 2 + 1] + bb1;
                if (!permute) {
                    *reinterpret_cast<float2*>(out + (size_t)m * Dc + n) = v;
                } else {
                    int b = m >> 11, l = m & 2047;
                    int h = n >> 6, d = n & 63;
                    *reinterpret_cast<float2*>(
                        out + (((size_t)(b * Hc + h)) * Lc + l) * DKc + d) = v;
                }
            }
        }
    }
}

// ---------------- V mean over L per (b,h,d): two-stage ----------------------
__global__ __launch_bounds__(256) void vmean1_kernel()
{
    int blk = blockIdx.x;             // 0..255
    int bh = blk >> 3, seg = blk & 7; // 8 segments of 256 rows
    int tid = threadIdx.x;
    int d = tid & 63, part = tid >> 6;  // 4 parts of 64 rows
    const float* Vb = g_V + ((size_t)bh * Lc + seg * 256 + part * 64) * DKc;
    float acc = 0.0f;
    for (int l = 0; l < 64; ++l) acc += Vb[(size_t)l * 64 + d];
    __shared__ float red[256];
    red[tid] = acc;
    __syncthreads();
    if (part == 0)
        g_vpart[(bh * 8 + seg) * 64 + d] =
            red[d] + red[d + 64] + red[d + 128] + red[d + 192];
}

__global__ __launch_bounds__(64) void vmean2_kernel()
{
    int bh = blockIdx.x, d = threadIdx.x;
    float s = 0.0f;
    #pragma unroll
    for (int i = 0; i < 8; i++) s += g_vpart[(bh * 8 + i) * 64 + d];
    g_vmean[bh * 64 + d] = s * (1.0f / Lc);
}

// ---------------- QK_sample + M (warp per query, butterfly multi-reduce) -----
template<int UT>
__global__ __launch_bounds__(256) void qk_sample_kernel_u(const int* __restrict__ idxs)
{
    static_assert(UT > 32 && UT <= 64, "expects 32 < UT <= 64");
    int warp = (blockIdx.x * blockDim.x + threadIdx.x) >> 5;
    int lane = threadIdx.x & 31;
    if (warp >= Bc * Hc * Lc) return;
    int q  = warp % Lc;
    int bh = warp / Lc;

    const float* Qr = g_Q + ((size_t)bh * Lc + q) * 64;
    float q0 = Qr[lane], q1 = Qr[lane + 32];

    const int* ip = idxs + (size_t)q * UT;
    int idx0 = ip[lane];                                      // j = lane
    int idx1 = (lane < UT - 32) ? ip[32 + lane] : ip[UT - 1]; // pad dups last row

    const float* Kb = g_K + (size_t)bh * Lc * 64;

    float tot0, tot1;
    #pragma unroll
    for (int batch = 0; batch < 2; batch++) {
        int src = batch ? idx1 : idx0;
        float p[32];
        #pragma unroll
        for (int j = 0; j < 32; j++) {
            int ki = __shfl_sync(0xFFFFFFFFu, src, j);
            const float* Kr = Kb + (size_t)ki * 64;
            p[j] = fmaf(q0, Kr[lane], q1 * Kr[lane + 32]);
        }
        #pragma unroll
        for (int o = 16; o >= 1; o >>= 1) {
            bool hi = (lane & o) != 0;
            #pragma unroll
            for (int j = 0; j < o; j++) {
                float a = p[j], b = p[j + o];
                float mine = hi ? b : a;
                float send = hi ? a : b;
                float theirs = __shfl_xor_sync(0xFFFFFFFFu, send, o);
                p[j] = mine + theirs;
            }
        }
        if (batch == 0) tot0 = p[0]; else tot1 = p[0];
    }

    bool v1 = (lane < UT - 32);
    float mx = fmaxf(tot0, v1 ? tot1 : -1e30f);
    float sm = tot0 + (v1 ? tot1 : 0.0f);
    #pragma unroll
    for (int o = 16; o > 0; o >>= 1) {
        mx = fmaxf(mx, __shfl_xor_sync(0xFFFFFFFFu, mx, o));
        sm += __shfl_xor_sync(0xFFFFFFFFu, sm, o);
    }
    if (lane == 0) g_M[(size_t)bh * Lc + q] = mx - sm * (1.0f / (float)Lc);
}

// generic fallback (runtime U)
__global__ __launch_bounds__(256) void qk_sample_kernel(const int* __restrict__ idxs, int U)
{
    int warp = (blockIdx.x * blockDim.x + threadIdx.x) >> 5;
    int lane = threadIdx.x & 31;
    if (warp >= Bc * Hc * Lc) return;
    int q  = warp % Lc;
    int bh = warp / Lc;

    const float* Qr = g_Q + ((size_t)bh * Lc + q) * 64;
    float q0 = Qr[lane], q1 = Qr[lane + 32];

    float mx = -1e30f, sm = 0.0f;
    for (int j = 0; j < U; j++) {
        int ki = idxs[q * U + j];
        const float* Kr = g_K + ((size_t)bh * Lc + ki) * 64;
        float p = q0 * Kr[lane] + q1 * Kr[lane + 32];
        #pragma unroll
        for (int o = 16; o > 0; o >>= 1) p += __shfl_xor_sync(0xFFFFFFFFu, p, o);
        mx = fmaxf(mx, p);
        sm += p;
    }
    if (lane == 0) g_M[(size_t)bh * Lc + q] = mx - sm * (1.0f / (float)Lc);
}

// ---------------- top-U per (b,h): iterative argmax over 2048 ----------------
__global__ __launch_bounds__(256) void topk_kernel(int U)
{
    int bh  = blockIdx.x;
    int tid = threadIdx.x;
    __shared__ float vals[Lc];
    __shared__ float rmax[256];
    __shared__ int   ridx[256];

    for (int i = tid; i < Lc; i += 256) vals[i] = g_M[(size_t)bh * Lc + i];
    __syncthreads();

    for (int it = 0; it < U; it++) {
        float best = -1e30f; int bi = Lc;
        for (int i = tid; i < Lc; i += 256) {
            float v = vals[i];
            if (v > best) { best = v; bi = i; }
        }
        rmax[tid] = best; ridx[tid] = bi;
        __syncthreads();
        for (int s = 128; s > 0; s >>= 1) {
            if (tid < s) {
                if (rmax[tid + s] > rmax[tid] ||
                    (rmax[tid + s] == rmax[tid] && ridx[tid + s] < ridx[tid])) {
                    rmax[tid] = rmax[tid + s];
                    ridx[tid] = ridx[tid + s];
                }
            }
            __syncthreads();
        }
        if (tid == 0) {
            g_top[bh * UMAX + it] = ridx[0];
            vals[ridx[0]] = -1e30f;
        }
        __syncthreads();
    }
}

// ---------------- fill ctx planes with bf16-split V-mean broadcast -----------
// writes slot 0 of g_hiX/g_loX directly (packed u32, 2 dims per unit)
__global__ __launch_bounds__(256) void fill_ctx_plane_kernel()
{
    int p = blockIdx.x * 256 + threadIdx.x;   // over NX/2 packed units
    int m = p >> 8;            // row (256 u32 per row)
    int j = p & 255;           // packed col
    int b = m >> 11;
    int h = j >> 5;
    int d0 = (j & 31) * 2;
    const float* vm = g_vmean + (b * Hc + h) * 64;
    uint32_t hi, lo;
    split_pack2(vm[d0], vm[d0 + 1], hi, lo);
    g_hiX[p] = hi;
    g_loX[p] = lo;
}

// ---------------- flash-style attention for top-u queries (8 per block) ------
// writes results straight into the ctx bf16 planes (slot 0)
__global__ __launch_bounds__(256) void sparse_attn2_kernel(int U)
{
    int bh = blockIdx.x;
    int b  = bh >> 3, h = bh & 7;
    int tid = threadIdx.x, w = tid >> 5, lane = tid & 31;
    int ui = blockIdx.y * 8 + w;
    bool active = ui < U;
    int lq = active ? g_top[bh * UMAX + ui] : 0;

    __shared__ float qv[8][64];
    __shared__ float Ks[64][65];
    __shared__ float Vs[64][65];

    const float* Qr = g_Q + ((size_t)bh * Lc + lq) * 64;
    qv[w][lane]      = Qr[lane]      * 0.125f;   // 1/sqrt(64)
    qv[w][lane + 32] = Qr[lane + 32] * 0.125f;
    __syncthreads();

    float m = -1e30f, l = 0.0f, acc0 = 0.0f, acc1 = 0.0f;

    const float* Kb = g_K + (size_t)bh * Lc * 64;
    const float* Vb = g_V + (size_t)bh * Lc * 64;
    const int row = tid >> 2;           // 0..63
    const int cb  = (tid & 3) * 4;      // col base; strided +16

    for (int kc = 0; kc < Lc / 64; ++kc) {
        #pragma unroll
        for (int s = 0; s < 4; ++s) {
            int c = cb + s * 16;
            const float* kp = Kb + ((size_t)(kc * 64 + row)) * 64 + c;
            const float* vp = Vb + ((size_t)(kc * 64 + row)) * 64 + c;
            float4 kv = *reinterpret_cast<const float4*>(kp);
            float4 vv = *reinterpret_cast<const float4*>(vp);
            Ks[row][c] = kv.x; Ks[row][c+1] = kv.y; Ks[row][c+2] = kv.z; Ks[row][c+3] = kv.w;
            Vs[row][c] = vv.x; Vs[row][c+1] = vv.y; Vs[row][c+2] = vv.z; Vs[row][c+3] = vv.w;
        }
        __syncthreads();

        float s0 = 0.0f, s1 = 0.0f;
        #pragma unroll 16
        for (int c = 0; c < 64; ++c) {
            float qc = qv[w][c];
            s0 = fmaf(qc, Ks[lane][c],      s0);
            s1 = fmaf(qc, Ks[lane + 32][c], s1);
        }

        float cm = fmaxf(s0, s1);
        #pragma unroll
        for (int o = 16; o > 0; o >>= 1)
            cm = fmaxf(cm, __shfl_xor_sync(0xFFFFFFFFu, cm, o));
        float mn = fmaxf(m, cm);
        float corr = expf(m - mn);
        l *= corr; acc0 *= corr; acc1 *= corr;
        float p0 = expf(s0 - mn), p1 = expf(s1 - mn);
        float ps = p0 + p1;
        #pragma unroll
        for (int o = 16; o > 0; o >>= 1)
            ps += __shfl_xor_sync(0xFFFFFFFFu, ps, o);
        l += ps;
        m = mn;

        #pragma unroll 8
        for (int r = 0; r < 32; ++r) {
            float pa = __shfl_sync(0xFFFFFFFFu, p0, r);
            float pb = __shfl_sync(0xFFFFFFFFu, p1, r);
            acc0 = fmaf(pa, Vs[r][lane],           acc0);
            acc1 = fmaf(pa, Vs[r][lane + 32],      acc1);
            acc0 = fmaf(pb, Vs[r + 32][lane],      acc0);
            acc1 = fmaf(pb, Vs[r + 32][lane + 32], acc1);
        }
        __syncthreads();
    }

    if (active) {
        float inv = 1.0f / l;
        // pack (2j, 2j+1) dims into plane u32 at packed col h*32 + lane.
        int srcA = (lane & 15) * 2, srcB = srcA + 1;
        float a0a = __shfl_sync(0xFFFFFFFFu, acc0, srcA);
        float a0b = __shfl_sync(0xFFFFFFFFu, acc0, srcB);
        float a1a = __shfl_sync(0xFFFFFFFFu, acc1, srcA);
        float a1b = __shfl_sync(0xFFFFFFFFu, acc1, srcB);
        float va = (lane < 16 ? a0a : a1a) * inv;
        float vb = (lane < 16 ? a0b : a1b) * inv;
        uint32_t hi, lo;
        split_pack2(va, vb, hi, lo);
        size_t idx = ((size_t)b * Lc + lq) * 256 + h * 32 + lane;
        g_hiX[idx] = hi;
        g_loX[idx] = lo;
    }
}

// ---------------- launch ------------------------------------------------------
extern "C" void kernel_launch(void* const* d_in, const int* in_sizes, int n_in,
                              void* d_out, int out_size)
{
    const float* queries = (const float*)d_in[0];
    const float* keys    = (const float*)d_in[1];
    const float* values  = (const float*)d_in[2];
    const float* Wq = (const float*)d_in[3];
    const float* bq = (const float*)d_in[4];
    const float* Wk = (const float*)d_in[5];
    const float* bk = (const float*)d_in[6];
    const float* Wv = (const float*)d_in[7];
    const float* bv = (const float*)d_in[8];
    const float* Wo = (const float*)d_in[9];
    const float* bo = (const float*)d_in[10];
    const int* index_sample = (const int*)d_in[11];

    int U = in_sizes[11] / Lc;   // 40 for this bench
    if (U > UMAX) U = UMAX;

    float *qp, *kp, *vp;
    cudaGetSymbolAddress((void**)&qp,  g_Q);
    cudaGetSymbolAddress((void**)&kp,  g_K);
    cudaGetSymbolAddress((void**)&vp,  g_V);
    uint32_t *hiX, *loX, *hiW, *loW;
    cudaGetSymbolAddress((void**)&hiX, g_hiX);
    cudaGetSymbolAddress((void**)&loX, g_loX);
    cudaGetSymbolAddress((void**)&hiW, g_hiW);
    cudaGetSymbolAddress((void**)&loW, g_loW);

    const int WSZ2 = Dc * Dc / 2;          // packed u32 per W plane
    dim3 ggrid3(Dc / GBN, (Bc * Lc) / GBM, 3);  // (4, 64, 3)
    dim3 ggrid1(Dc / GBN, (Bc * Lc) / GBM, 1);
    dim3 wgrid(Dc * Dc / 4 / 256, 2);
    int warps = Bc * Hc * Lc;
    int n4x = NX / 4;

    // launch idx 3 (the ncu-captured launch) is the merged QKV GEMM.
    presplit_w2_kernel<<<wgrid, 256>>>(Wq, Wk, 0);                            // 0
    presplit_w2_kernel<<<wgrid, 256>>>(Wv, Wo, 2);                            // 1
    presplit_x3_kernel<<<dim3((n4x + 255) / 256, 3), 256>>>(queries, keys, values); // 2

    bf16x2_gemm_kernel<<<ggrid3, 256>>>(hiX, loX, hiW, loW,                   // 3 <- profiled
                                        bq, bk, bv, qp, kp, vp, 1);

    if (U == 40)                                                              // 4
        qk_sample_kernel_u<40><<<(warps * 32) / 256, 256>>>(index_sample);
    else if (U > 32 && U <= 64)
        qk_sample_kernel_u<64><<<(warps * 32) / 256, 256>>>(index_sample);
    else
        qk_sample_kernel<<<(warps * 32) / 256, 256>>>(index_sample, U);

    vmean1_kernel<<<Bc * Hc * 8, 256>>>();                                    // 5
    vmean2_kernel<<<Bc * Hc, 64>>>();                                         // 6

    topk_kernel<<<Bc * Hc, 256>>>(U);                                         // 7

    fill_ctx_plane_kernel<<<NX / 2 / 256, 256>>>();                           // 8

    sparse_attn2_kernel<<<dim3(Bc * Hc, (U + 7) / 8), 256>>>(U);              // 9

    bf16x2_gemm_kernel<<<ggrid1, 256>>>(hiX, loX, hiW + 3 * WSZ2,             // 10
                                        loW + 3 * WSZ2, bo, bo, bo,
                                        (float*)d_out, nullptr, nullptr, 0);
}

// round 13
// speedup vs baseline: 1.5426x; 1.0009x over previous
#include <cuda_runtime.h>
#include <cuda_bf16.h>
#include <math.h>
#include <stdint.h>

// Problem constants (fixed shapes for this bench)
constexpr int Bc  = 4;
constexpr int Lc  = 2048;
constexpr int Dc  = 512;
constexpr int Hc  = 8;
constexpr int DKc = 64;
constexpr int UMAX = 64;   // safety cap for top-k storage (actual U = 40)
constexpr int NX  = Bc * Lc * Dc;     // elements in one (B,L,D) tensor

// ---------------- scratch (device globals; no allocation allowed) ------------
__device__ float g_Q[Bc*Hc*Lc*DKc];      // (b,h,l,d)  16 MB
__device__ float g_K[Bc*Hc*Lc*DKc];      // 16 MB
__device__ float g_V[Bc*Hc*Lc*DKc];      // 16 MB
__device__ float g_M[Bc*Hc*Lc];          // sparsity measure
__device__ int   g_top[Bc*Hc*UMAX];      // top-u indices per (b,h)
__device__ float g_vmean[Bc*Hc*DKc];     // V mean over L
__device__ float g_vpart[Bc*Hc*8*DKc];   // partial V sums

// bf16 hi/lo planes, packed 2 consecutive-k bf16 per u32 (low half = even k)
// slot 0 doubles as the ctx planes for the output GEMM.
__device__ uint32_t g_hiX[3*NX/2], g_loX[3*NX/2];
__device__ uint32_t g_hiW[4*Dc*Dc/2], g_loW[4*Dc*Dc/2];

// ---------------- bf16 split helpers ------------------------------------------
__device__ __forceinline__ void split_pack2(float a, float b,
                                            uint32_t& hi, uint32_t& lo) {
    __nv_bfloat16 ha = __float2bfloat16_rn(a);
    __nv_bfloat16 hb = __float2bfloat16_rn(b);
    float ra = a - __bfloat162float(ha);
    float rb = b - __bfloat162float(hb);
    __nv_bfloat162 hv = __floats2bfloat162_rn(__bfloat162float(ha), __bfloat162float(hb));
    __nv_bfloat162 lv = __floats2bfloat162_rn(ra, rb);
    hi = *reinterpret_cast<uint32_t*>(&hv);
    lo = *reinterpret_cast<uint32_t*>(&lv);
}

__device__ __forceinline__ void mma_bf16(float (&d)[4], const uint32_t (&a)[4],
                                         const uint32_t (&b)[2]) {
    asm volatile(
        "mma.sync.aligned.m16n8k16.row.col.f32.bf16.bf16.f32 "
        "{%0,%1,%2,%3}, {%4,%5,%6,%7}, {%8,%9}, {%0,%1,%2,%3};"
        : "+f"(d[0]), "+f"(d[1]), "+f"(d[2]), "+f"(d[3])
        : "r"(a[0]), "r"(a[1]), "r"(a[2]), "r"(a[3]), "r"(b[0]), "r"(b[1]));
}

__device__ __forceinline__ void cp16(void* smem, const void* gmem) {
    uint32_t s = (uint32_t)__cvta_generic_to_shared(smem);
    asm volatile("cp.async.cg.shared.global [%0], [%1], 16;" :: "r"(s), "l"(gmem));
}
__device__ __forceinline__ void cp_commit() {
    asm volatile("cp.async.commit_group;" ::: "memory");
}
template<int N>
__device__ __forceinline__ void cp_wait() {
    asm volatile("cp.async.wait_group %0;" :: "n"(N) : "memory");
}

// ---------------- pre-split kernels -------------------------------------------
__global__ __launch_bounds__(256) void presplit_x3_kernel(
    const float* __restrict__ x0, const float* __restrict__ x1,
    const float* __restrict__ x2)
{
    const float* srcs[3] = {x0, x1, x2};
    int z = blockIdx.y;
    const float* src = srcs[z];
    int i = blockIdx.x * 256 + threadIdx.x;    // over NX/4 float4s
    if (i >= NX / 4) return;
    float4 v = reinterpret_cast<const float4*>(src)[i];
    uint32_t h0, l0, h1, l1;
    split_pack2(v.x, v.y, h0, l0);
    split_pack2(v.z, v.w, h1, l1);
    size_t o = (size_t)z * (NX / 2) + i * 2;
    g_hiX[o] = h0; g_hiX[o + 1] = h1;
    g_loX[o] = l0; g_loX[o + 1] = l1;
}

__global__ __launch_bounds__(256) void presplit_w2_kernel(
    const float* __restrict__ w0, const float* __restrict__ w1, int slot0)
{
    const float* srcs[2] = {w0, w1};
    int wsel = slot0 + blockIdx.y;
    const float* src = srcs[blockIdx.y];
    int i = blockIdx.x * 256 + threadIdx.x;    // over Dc*Dc/4 float4s
    float4 v = reinterpret_cast<const float4*>(src)[i];
    uint32_t h0, l0, h1, l1;
    split_pack2(v.x, v.y, h0, l0);
    split_pack2(v.z, v.w, h1, l1);
    size_t o = (size_t)wsel * (Dc * Dc / 2) + i * 2;
    g_hiW[o] = h0; g_hiW[o + 1] = h1;
    g_loW[o] = l0; g_loW[o + 1] = l1;
}

// ---------------- Split-bf16 GEMM, 128x128 block, BK=32 ----------------------
// out_z = X_z[M,512] @ W_z[512,512]^T + bias_z    (z = blockIdx.z)
// acc += aL*bH + aH*bL + aH*bH (3 bf16 m16n8k16 MMAs per k-step).
// BM=128, BN=128, BK=32, 256 threads (8 warps, 4m x 2n), warp tile 32x64.
// 96 MMAs per warp between barriers; cp.async double buffered, dynamic smem.
constexpr int GK  = 512;
constexpr int KW  = GK / 2;                    // 256 u32 per row (packed)
constexpr int GBM = 128, GBN = 128, GBK = 32;
constexpr int TW  = GBK / 2;                   // 16 u32 per row per tile
constexpr int LDW = 20;                        // padded row stride (conflict-free)
constexpr int A_SZ = GBM * LDW;                // 2560 u32
constexpr int W_SZ = GBN * LDW;                // 2560 u32
constexpr int G_SMEM_BYTES = (2 * A_SZ + 2 * A_SZ + 2 * W_SZ + 2 * W_SZ) * 4; // 81920

__global__ __launch_bounds__(256) void bf16x2_gemm_kernel(
    const uint32_t* __restrict__ hiX, const uint32_t* __restrict__ loX,
    const uint32_t* __restrict__ hiW, const uint32_t* __restrict__ loW,
    const float* __restrict__ b0, const float* __restrict__ b1,
    const float* __restrict__ b2,
    float* __restrict__ o0, float* __restrict__ o1, float* __restrict__ o2,
    int permute)
{
    extern __shared__ uint32_t sm_[];
    uint32_t* AsH = sm_;                       // [2][A_SZ]
    uint32_t* AsL = sm_ + 2 * A_SZ;            // [2][A_SZ]
    uint32_t* WsH = sm_ + 4 * A_SZ;            // [2][W_SZ]
    uint32_t* WsL = sm_ + 4 * A_SZ + 2 * W_SZ; // [2][W_SZ]

    const int z = blockIdx.z;
    const float* bias = (z == 0) ? b0 : (z == 1) ? b1 : b2;
    float* out = (z == 0) ? o0 : (z == 1) ? o1 : o2;

    const int tid  = threadIdx.x;
    const int warp = tid >> 5, lane = tid & 31;
    const int wm = warp & 3;        // 0..3 -> m offset (x32)
    const int wn = warp >> 2;       // 0..1 -> n offset (x64)
    const int m0 = blockIdx.y * GBM;
    const int n0 = blockIdx.x * GBN;
    const int gr = lane >> 2, gc = lane & 3;

    float acc[2][8][4];
    #pragma unroll
    for (int i = 0; i < 2; i++)
        #pragma unroll
        for (int j = 0; j < 8; j++)
            #pragma unroll
            for (int q = 0; q < 4; q++) acc[i][j][q] = 0.0f;

    // per-thread staging coords: row tid>>1, col base (tid&1)*8; 2 cp16/plane
    const int srow = tid >> 1, soff = (tid & 1) * 8;
    const uint32_t* AhP = hiX + (size_t)z * (NX / 2) + (size_t)(m0 + srow) * KW + soff;
    const uint32_t* AlP = loX + (size_t)z * (NX / 2) + (size_t)(m0 + srow) * KW + soff;
    const uint32_t* WhP = hiW + (size_t)z * (Dc * Dc / 2) + (size_t)(n0 + srow) * KW + soff;
    const uint32_t* WlP = loW + (size_t)z * (Dc * Dc / 2) + (size_t)(n0 + srow) * KW + soff;
    const int sidx = srow * LDW + soff;

    // stage tile 0 into buffer 0
    cp16(&AsH[sidx],     AhP);     cp16(&AsH[sidx + 4],     AhP + 4);
    cp16(&AsL[sidx],     AlP);     cp16(&AsL[sidx + 4],     AlP + 4);
    cp16(&WsH[sidx],     WhP);     cp16(&WsH[sidx + 4],     WhP + 4);
    cp16(&WsL[sidx],     WlP);     cp16(&WsL[sidx + 4],     WlP + 4);
    cp_commit();

    constexpr int NT = GK / GBK;   // 16 tiles
    for (int t = 0; t < NT; ++t) {
        const int buf = t & 1;
        if (t + 1 < NT) {
            const int nb = 1 - buf;
            const int o = (t + 1) * TW;
            cp16(&AsH[nb * A_SZ + sidx],     AhP + o);
            cp16(&AsH[nb * A_SZ + sidx + 4], AhP + o + 4);
            cp16(&AsL[nb * A_SZ + sidx],     AlP + o);
            cp16(&AsL[nb * A_SZ + sidx + 4], AlP + o + 4);
            cp16(&WsH[nb * W_SZ + sidx],     WhP + o);
            cp16(&WsH[nb * W_SZ + sidx + 4], WhP + o + 4);
            cp16(&WsL[nb * W_SZ + sidx],     WlP + o);
            cp16(&WsL[nb * W_SZ + sidx + 4], WlP + o + 4);
            cp_commit();
            cp_wait<1>();   // tile t landed; t+1 still streaming
        } else {
            cp_wait<0>();
        }
        __syncthreads();

        const uint32_t* aHs = AsH + buf * A_SZ;
        const uint32_t* aLs = AsL + buf * A_SZ;
        const uint32_t* wHs = WsH + buf * W_SZ;
        const uint32_t* wLs = WsL + buf * W_SZ;

        #pragma unroll
        for (int ks = 0; ks < 2; ks++) {        // two 16-k steps per tile
            const int kb = ks * 8;
            uint32_t aH[2][4], aL[2][4];
            #pragma unroll
            for (int ti = 0; ti < 2; ti++) {
                int mb = wm * 32 + ti * 16;
                int i0 = (mb + gr)     * LDW + kb + gc;
                int i1 = (mb + gr + 8) * LDW + kb + gc;
                aH[ti][0] = aHs[i0];     aH[ti][1] = aHs[i1];
                aH[ti][2] = aHs[i0 + 4]; aH[ti][3] = aHs[i1 + 4];
                aL[ti][0] = aLs[i0];     aL[ti][1] = aLs[i1];
                aL[ti][2] = aLs[i0 + 4]; aL[ti][3] = aLs[i1 + 4];
            }
            // tj processed in two halves of 4 to cap register pressure
            #pragma unroll
            for (int half = 0; half < 2; half++) {
                uint32_t bH[4][2], bL[4][2];
                #pragma unroll
                for (int tj = 0; tj < 4; tj++) {
                    int nb2 = (wn * 64 + (half * 4 + tj) * 8 + gr) * LDW + kb + gc;
                    bH[tj][0] = wHs[nb2]; bH[tj][1] = wHs[nb2 + 4];
                    bL[tj][0] = wLs[nb2]; bL[tj][1] = wLs[nb2 + 4];
                }
                #pragma unroll
                for (int ti = 0; ti < 2; ti++)
                    #pragma unroll
                    for (int tj = 0; tj < 4; tj++) {
                        mma_bf16(acc[ti][half * 4 + tj], aL[ti], bH[tj]);
                        mma_bf16(acc[ti][half * 4 + tj], aH[ti], bL[tj]);
                        mma_bf16(acc[ti][half * 4 + tj], aH[ti], bH[tj]);
                    }
            }
        }
        __syncthreads();
    }

    // ---- epilogue: bias + (optional) head permute, float2 stores ----
    #pragma unroll
    for (int ti = 0; ti < 2; ti++) {
        #pragma unroll
        for (int tj = 0; tj < 8; tj++) {
            int n = n0 + wn * 64 + tj * 8 + gc * 2;
            float bb0 = bias[n], bb1 = bias[n + 1];
            #pragma unroll
            for (int half = 0; half < 2; half++) {   // rows gr and gr+8
                int m = m0 + wm * 32 + ti * 16 + gr + half * 8;
                float2 v;
                v.x = acc[ti][tj][half * 2 + 0] + bb0;
                v.y = acc[ti][tj][half * 2 + 1] + bb1;
                if (!permute) {
                    *reinterpret_cast<float2*>(out + (size_t)m * Dc + n) = v;
                } else {
                    int b = m >> 11, l = m & 2047;
                    int h = n >> 6, d = n & 63;
                    *reinterpret_cast<float2*>(
                        out + (((size_t)(b * Hc + h)) * Lc + l) * DKc + d) = v;
                }
            }
        }
    }
}

// ---------------- V mean over L per (b,h,d): two-stage ----------------------
__global__ __launch_bounds__(256) void vmean1_kernel()
{
    int blk = blockIdx.x;             // 0..255
    int bh = blk >> 3, seg = blk & 7; // 8 segments of 256 rows
    int tid = threadIdx.x;
    int d = tid & 63, part = tid >> 6;  // 4 parts of 64 rows
    const float* Vb = g_V + ((size_t)bh * Lc + seg * 256 + part * 64) * DKc;
    float acc = 0.0f;
    for (int l = 0; l < 64; ++l) acc += Vb[(size_t)l * 64 + d];
    __shared__ float red[256];
    red[tid] = acc;
    __syncthreads();
    if (part == 0)
        g_vpart[(bh * 8 + seg) * 64 + d] =
            red[d] + red[d + 64] + red[d + 128] + red[d + 192];
}

__global__ __launch_bounds__(64) void vmean2_kernel()
{
    int bh = blockIdx.x, d = threadIdx.x;
    float s = 0.0f;
    #pragma unroll
    for (int i = 0; i < 8; i++) s += g_vpart[(bh * 8 + i) * 64 + d];
    g_vmean[bh * 64 + d] = s * (1.0f / Lc);
}

// ---------------- QK_sample + M (warp per query, butterfly multi-reduce) -----
template<int UT>
__global__ __launch_bounds__(256) void qk_sample_kernel_u(const int* __restrict__ idxs)
{
    static_assert(UT > 32 && UT <= 64, "expects 32 < UT <= 64");
    int warp = (blockIdx.x * blockDim.x + threadIdx.x) >> 5;
    int lane = threadIdx.x & 31;
    if (warp >= Bc * Hc * Lc) return;
    int q  = warp % Lc;
    int bh = warp / Lc;

    const float* Qr = g_Q + ((size_t)bh * Lc + q) * 64;
    float q0 = Qr[lane], q1 = Qr[lane + 32];

    const int* ip = idxs + (size_t)q * UT;
    int idx0 = ip[lane];                                      // j = lane
    int idx1 = (lane < UT - 32) ? ip[32 + lane] : ip[UT - 1]; // pad dups last row

    const float* Kb = g_K + (size_t)bh * Lc * 64;

    float tot0, tot1;
    #pragma unroll
    for (int batch = 0; batch < 2; batch++) {
        int src = batch ? idx1 : idx0;
        float p[32];
        #pragma unroll
        for (int j = 0; j < 32; j++) {
            int ki = __shfl_sync(0xFFFFFFFFu, src, j);
            const float* Kr = Kb + (size_t)ki * 64;
            p[j] = fmaf(q0, Kr[lane], q1 * Kr[lane + 32]);
        }
        #pragma unroll
        for (int o = 16; o >= 1; o >>= 1) {
            bool hi = (lane & o) != 0;
            #pragma unroll
            for (int j = 0; j < o; j++) {
                float a = p[j], b = p[j + o];
                float mine = hi ? b : a;
                float send = hi ? a : b;
                float theirs = __shfl_xor_sync(0xFFFFFFFFu, send, o);
                p[j] = mine + theirs;
            }
        }
        if (batch == 0) tot0 = p[0]; else tot1 = p[0];
    }

    bool v1 = (lane < UT - 32);
    float mx = fmaxf(tot0, v1 ? tot1 : -1e30f);
    float sm = tot0 + (v1 ? tot1 : 0.0f);
    #pragma unroll
    for (int o = 16; o > 0; o >>= 1) {
        mx = fmaxf(mx, __shfl_xor_sync(0xFFFFFFFFu, mx, o));
        sm += __shfl_xor_sync(0xFFFFFFFFu, sm, o);
    }
    if (lane == 0) g_M[(size_t)bh * Lc + q] = mx - sm * (1.0f / (float)Lc);
}

// generic fallback (runtime U)
__global__ __launch_bounds__(256) void qk_sample_kernel(const int* __restrict__ idxs, int U)
{
    int warp = (blockIdx.x * blockDim.x + threadIdx.x) >> 5;
    int lane = threadIdx.x & 31;
    if (warp >= Bc * Hc * Lc) return;
    int q  = warp % Lc;
    int bh = warp / Lc;

    const float* Qr = g_Q + ((size_t)bh * Lc + q) * 64;
    float q0 = Qr[lane], q1 = Qr[lane + 32];

    float mx = -1e30f, sm = 0.0f;
    for (int j = 0; j < U; j++) {
        int ki = idxs[q * U + j];
        const float* Kr = g_K + ((size_t)bh * Lc + ki) * 64;
        float p = q0 * Kr[lane] + q1 * Kr[lane + 32];
        #pragma unroll
        for (int o = 16; o > 0; o >>= 1) p += __shfl_xor_sync(0xFFFFFFFFu, p, o);
        mx = fmaxf(mx, p);
        sm += p;
    }
    if (lane == 0) g_M[(size_t)bh * Lc + q] = mx - sm * (1.0f / (float)Lc);
}

// ---------------- top-U per (b,h): iterative argmax over 2048 ----------------
__global__ __launch_bounds__(256) void topk_kernel(int U)
{
    int bh  = blockIdx.x;
    int tid = threadIdx.x;
    __shared__ float vals[Lc];
    __shared__ float rmax[256];
    __shared__ int   ridx[256];

    for (int i = tid; i < Lc; i += 256) vals[i] = g_M[(size_t)bh * Lc + i];
    __syncthreads();

    for (int it = 0; it < U; it++) {
        float best = -1e30f; int bi = Lc;
        for (int i = tid; i < Lc; i += 256) {
            float v = vals[i];
            if (v > best) { best = v; bi = i; }
        }
        rmax[tid] = best; ridx[tid] = bi;
        __syncthreads();
        for (int s = 128; s > 0; s >>= 1) {
            if (tid < s) {
                if (rmax[tid + s] > rmax[tid] ||
                    (rmax[tid + s] == rmax[tid] && ridx[tid + s] < ridx[tid])) {
                    rmax[tid] = rmax[tid + s];
                    ridx[tid] = ridx[tid + s];
                }
            }
            __syncthreads();
        }
        if (tid == 0) {
            g_top[bh * UMAX + it] = ridx[0];
            vals[ridx[0]] = -1e30f;
        }
        __syncthreads();
    }
}

// ---------------- fill ctx planes with bf16-split V-mean broadcast -----------
__global__ __launch_bounds__(256) void fill_ctx_plane_kernel()
{
    int p = blockIdx.x * 256 + threadIdx.x;   // over NX/2 packed units
    int m = p >> 8;            // row (256 u32 per row)
    int j = p & 255;           // packed col
    int b = m >> 11;
    int h = j >> 5;
    int d0 = (j & 31) * 2;
    const float* vm = g_vmean + (b * Hc + h) * 64;
    uint32_t hi, lo;
    split_pack2(vm[d0], vm[d0 + 1], hi, lo);
    g_hiX[p] = hi;
    g_loX[p] = lo;
}

// ---------------- flash-style attention for top-u queries (8 per block) ------
// writes results straight into the ctx bf16 planes (slot 0)
__global__ __launch_bounds__(256) void sparse_attn2_kernel(int U)
{
    int bh = blockIdx.x;
    int b  = bh >> 3, h = bh & 7;
    int tid = threadIdx.x, w = tid >> 5, lane = tid & 31;
    int ui = blockIdx.y * 8 + w;
    bool active = ui < U;
    int lq = active ? g_top[bh * UMAX + ui] : 0;

    __shared__ float qv[8][64];
    __shared__ float Ks[64][65];
    __shared__ float Vs[64][65];

    const float* Qr = g_Q + ((size_t)bh * Lc + lq) * 64;
    qv[w][lane]      = Qr[lane]      * 0.125f;   // 1/sqrt(64)
    qv[w][lane + 32] = Qr[lane + 32] * 0.125f;
    __syncthreads();

    float m = -1e30f, l = 0.0f, acc0 = 0.0f, acc1 = 0.0f;

    const float* Kb = g_K + (size_t)bh * Lc * 64;
    const float* Vb = g_V + (size_t)bh * Lc * 64;
    const int row = tid >> 2;           // 0..63
    const int cb  = (tid & 3) * 4;      // col base; strided +16

    for (int kc = 0; kc < Lc / 64; ++kc) {
        #pragma unroll
        for (int s = 0; s < 4; ++s) {
            int c = cb + s * 16;
            const float* kp = Kb + ((size_t)(kc * 64 + row)) * 64 + c;
            const float* vp = Vb + ((size_t)(kc * 64 + row)) * 64 + c;
            float4 kv = *reinterpret_cast<const float4*>(kp);
            float4 vv = *reinterpret_cast<const float4*>(vp);
            Ks[row][c] = kv.x; Ks[row][c+1] = kv.y; Ks[row][c+2] = kv.z; Ks[row][c+3] = kv.w;
            Vs[row][c] = vv.x; Vs[row][c+1] = vv.y; Vs[row][c+2] = vv.z; Vs[row][c+3] = vv.w;
        }
        __syncthreads();

        float s0 = 0.0f, s1 = 0.0f;
        #pragma unroll 16
        for (int c = 0; c < 64; ++c) {
            float qc = qv[w][c];
            s0 = fmaf(qc, Ks[lane][c],      s0);
            s1 = fmaf(qc, Ks[lane + 32][c], s1);
        }

        float cm = fmaxf(s0, s1);
        #pragma unroll
        for (int o = 16; o > 0; o >>= 1)
            cm = fmaxf(cm, __shfl_xor_sync(0xFFFFFFFFu, cm, o));
        float mn = fmaxf(m, cm);
        float corr = expf(m - mn);
        l *= corr; acc0 *= corr; acc1 *= corr;
        float p0 = expf(s0 - mn), p1 = expf(s1 - mn);
        float ps = p0 + p1;
        #pragma unroll
        for (int o = 16; o > 0; o >>= 1)
            ps += __shfl_xor_sync(0xFFFFFFFFu, ps, o);
        l += ps;
        m = mn;

        #pragma unroll 8
        for (int r = 0; r < 32; ++r) {
            float pa = __shfl_sync(0xFFFFFFFFu, p0, r);
            float pb = __shfl_sync(0xFFFFFFFFu, p1, r);
            acc0 = fmaf(pa, Vs[r][lane],           acc0);
            acc1 = fmaf(pa, Vs[r][lane + 32],      acc1);
            acc0 = fmaf(pb, Vs[r + 32][lane],      acc0);
            acc1 = fmaf(pb, Vs[r + 32][lane + 32], acc1);
        }
        __syncthreads();
    }

    if (active) {
        float inv = 1.0f / l;
        int srcA = (lane & 15) * 2, srcB = srcA + 1;
        float a0a = __shfl_sync(0xFFFFFFFFu, acc0, srcA);
        float a0b = __shfl_sync(0xFFFFFFFFu, acc0, srcB);
        float a1a = __shfl_sync(0xFFFFFFFFu, acc1, srcA);
        float a1b = __shfl_sync(0xFFFFFFFFu, acc1, srcB);
        float va = (lane < 16 ? a0a : a1a) * inv;
        float vb = (lane < 16 ? a0b : a1b) * inv;
        uint32_t hi, lo;
        split_pack2(va, vb, hi, lo);
        size_t idx = ((size_t)b * Lc + lq) * 256 + h * 32 + lane;
        g_hiX[idx] = hi;
        g_loX[idx] = lo;
    }
}

// ---------------- launch ------------------------------------------------------
extern "C" void kernel_launch(void* const* d_in, const int* in_sizes, int n_in,
                              void* d_out, int out_size)
{
    const float* queries = (const float*)d_in[0];
    const float* keys    = (const float*)d_in[1];
    const float* values  = (const float*)d_in[2];
    const float* Wq = (const float*)d_in[3];
    const float* bq = (const float*)d_in[4];
    const float* Wk = (const float*)d_in[5];
    const float* bk = (const float*)d_in[6];
    const float* Wv = (const float*)d_in[7];
    const float* bv = (const float*)d_in[8];
    const float* Wo = (const float*)d_in[9];
    const float* bo = (const float*)d_in[10];
    const int* index_sample = (const int*)d_in[11];

    int U = in_sizes[11] / Lc;   // 40 for this bench
    if (U > UMAX) U = UMAX;

    float *qp, *kp, *vp;
    cudaGetSymbolAddress((void**)&qp,  g_Q);
    cudaGetSymbolAddress((void**)&kp,  g_K);
    cudaGetSymbolAddress((void**)&vp,  g_V);
    uint32_t *hiX, *loX, *hiW, *loW;
    cudaGetSymbolAddress((void**)&hiX, g_hiX);
    cudaGetSymbolAddress((void**)&loX, g_loX);
    cudaGetSymbolAddress((void**)&hiW, g_hiW);
    cudaGetSymbolAddress((void**)&loW, g_loW);

    cudaFuncSetAttribute(bf16x2_gemm_kernel,
                         cudaFuncAttributeMaxDynamicSharedMemorySize,
                         G_SMEM_BYTES);

    const int WSZ2 = Dc * Dc / 2;          // packed u32 per W plane
    dim3 ggrid3(Dc / GBN, (Bc * Lc) / GBM, 3);  // (4, 64, 3)
    dim3 ggrid1(Dc / GBN, (Bc * Lc) / GBM, 1);
    dim3 wgrid(Dc * Dc / 4 / 256, 2);
    int warps = Bc * Hc * Lc;
    int n4x = NX / 4;

    // launch idx 3 (the ncu-captured launch) is the merged QKV GEMM.
    presplit_w2_kernel<<<wgrid, 256>>>(Wq, Wk, 0);                            // 0
    presplit_w2_kernel<<<wgrid, 256>>>(Wv, Wo, 2);                            // 1
    presplit_x3_kernel<<<dim3((n4x + 255) / 256, 3), 256>>>(queries, keys, values); // 2

    bf16x2_gemm_kernel<<<ggrid3, 256, G_SMEM_BYTES>>>(hiX, loX, hiW, loW,     // 3 <- profiled
                                                      bq, bk, bv, qp, kp, vp, 1);

    if (U == 40)                                                              // 4
        qk_sample_kernel_u<40><<<(warps * 32) / 256, 256>>>(index_sample);
    else if (U > 32 && U <= 64)
        qk_sample_kernel_u<64><<<(warps * 32) / 256, 256>>>(index_sample);
    else
        qk_sample_kernel<<<(warps * 32) / 256, 256>>>(index_sample, U);

    vmean1_kernel<<<Bc * Hc * 8, 256>>>();                                    // 5
    vmean2_kernel<<<Bc * Hc, 64>>>();                                         // 6

    topk_kernel<<<Bc * Hc, 256>>>(U);                                         // 7

    fill_ctx_plane_kernel<<<NX / 2 / 256, 256>>>();                           // 8

    sparse_attn2_kernel<<<dim3(Bc * Hc, (U + 7) / 8), 256>>>(U);              // 9

    bf16x2_gemm_kernel<<<ggrid1, 256, G_SMEM_BYTES>>>(hiX, loX, hiW + 3 * WSZ2, // 10
                                                      loW + 3 * WSZ2, bo, bo, bo,
                                                      (float*)d_out, nullptr, nullptr, 0);
}

// round 15
// speedup vs baseline: 1.6561x; 1.0736x over previous
#include <cuda_runtime.h>
#include <cuda_bf16.h>
#include <math.h>
#include <stdint.h>

// Problem constants (fixed shapes for this bench)
constexpr int Bc  = 4;
constexpr int Lc  = 2048;
constexpr int Dc  = 512;
constexpr int Hc  = 8;
constexpr int DKc = 64;
constexpr int UMAX = 64;   // safety cap for top-k storage (actual U = 40)
constexpr int NX  = Bc * Lc * Dc;     // elements in one (B,L,D) tensor

// ---------------- scratch (device globals; no allocation allowed) ------------
__device__ float g_Q[Bc*Hc*Lc*DKc];      // (b,h,l,d)  16 MB
__device__ float g_K[Bc*Hc*Lc*DKc];      // 16 MB
__device__ float g_V[Bc*Hc*Lc*DKc];      // 16 MB
__device__ float g_M[Bc*Hc*Lc];          // sparsity measure
__device__ int   g_top[Bc*Hc*UMAX];      // top-u indices per (b,h)
__device__ float g_vmean[Bc*Hc*DKc];     // V mean over L
__device__ float g_vpart[Bc*Hc*8*DKc];   // partial V sums

// bf16 hi/lo planes, packed 2 consecutive-k bf16 per u32 (low half = even k)
// slot 0 doubles as the ctx planes for the output GEMM.
__device__ uint32_t g_hiX[3*NX/2], g_loX[3*NX/2];
__device__ uint32_t g_hiW[4*Dc*Dc/2], g_loW[4*Dc*Dc/2];

// ---------------- bf16 split helpers ------------------------------------------
__device__ __forceinline__ void split_pack2(float a, float b,
                                            uint32_t& hi, uint32_t& lo) {
    __nv_bfloat16 ha = __float2bfloat16_rn(a);
    __nv_bfloat16 hb = __float2bfloat16_rn(b);
    float ra = a - __bfloat162float(ha);
    float rb = b - __bfloat162float(hb);
    __nv_bfloat162 hv = __floats2bfloat162_rn(__bfloat162float(ha), __bfloat162float(hb));
    __nv_bfloat162 lv = __floats2bfloat162_rn(ra, rb);
    hi = *reinterpret_cast<uint32_t*>(&hv);
    lo = *reinterpret_cast<uint32_t*>(&lv);
}

__device__ __forceinline__ void mma_bf16(float (&d)[4], const uint32_t (&a)[4],
                                         const uint32_t (&b)[2]) {
    asm volatile(
        "mma.sync.aligned.m16n8k16.row.col.f32.bf16.bf16.f32 "
        "{%0,%1,%2,%3}, {%4,%5,%6,%7}, {%8,%9}, {%0,%1,%2,%3};"
        : "+f"(d[0]), "+f"(d[1]), "+f"(d[2]), "+f"(d[3])
        : "r"(a[0]), "r"(a[1]), "r"(a[2]), "r"(a[3]), "r"(b[0]), "r"(b[1]));
}

__device__ __forceinline__ void cp16(void* smem, const void* gmem) {
    uint32_t s = (uint32_t)__cvta_generic_to_shared(smem);
    asm volatile("cp.async.cg.shared.global [%0], [%1], 16;" :: "r"(s), "l"(gmem));
}
__device__ __forceinline__ void cp_commit() {
    asm volatile("cp.async.commit_group;" ::: "memory");
}
template<int N>
__device__ __forceinline__ void cp_wait() {
    asm volatile("cp.async.wait_group %0;" :: "n"(N) : "memory");
}

// ---------------- merged pre-split kernel --------------------------------------
// blocks [0, 1024): W planes (4 slots x 256 blocks over Dc*Dc/4 float4s)
// blocks [1024, 1024+3*4096): X planes (3 tensors x 4096 blocks over NX/4 float4s)
__global__ __launch_bounds__(256) void presplit_all_kernel(
    const float* __restrict__ w0, const float* __restrict__ w1,
    const float* __restrict__ w2, const float* __restrict__ w3,
    const float* __restrict__ x0, const float* __restrict__ x1,
    const float* __restrict__ x2)
{
    int bid = blockIdx.x;
    if (bid < 1024) {
        const float* srcs[4] = {w0, w1, w2, w3};
        int wsel = bid >> 8;
        int i = (bid & 255) * 256 + threadIdx.x;
        float4 v = reinterpret_cast<const float4*>(srcs[wsel])[i];
        uint32_t h0, l0, h1, l1;
        split_pack2(v.x, v.y, h0, l0);
        split_pack2(v.z, v.w, h1, l1);
        size_t o = (size_t)wsel * (Dc * Dc / 2) + (size_t)i * 2;
        g_hiW[o] = h0; g_hiW[o + 1] = h1;
        g_loW[o] = l0; g_loW[o + 1] = l1;
    } else {
        const float* srcs[3] = {x0, x1, x2};
        int rb = bid - 1024;
        int z = rb >> 12;            // /4096
        int i = (rb & 4095) * 256 + threadIdx.x;
        float4 v = reinterpret_cast<const float4*>(srcs[z])[i];
        uint32_t h0, l0, h1, l1;
        split_pack2(v.x, v.y, h0, l0);
        split_pack2(v.z, v.w, h1, l1);
        size_t o = (size_t)z * (NX / 2) + (size_t)i * 2;
        g_hiX[o] = h0; g_hiX[o + 1] = h1;
        g_loX[o] = l0; g_loX[o + 1] = l1;
    }
}

// ---------------- Split-bf16 GEMM, 128x128 block (R12 best) -------------------
// out_z = X_z[M,512] @ W_z[512,512]^T + bias_z    (z = blockIdx.z)
// acc += aL*bH + aH*bL + aH*bH (3 bf16 m16n8k16 MMAs).
// BM=128, BN=128, BK=16, 256 threads (8 warps, 4m x 2n), warp tile 32x64.
constexpr int GK  = 512;
constexpr int KW  = GK / 2;                    // 256 u32 per row (packed)
constexpr int GBM = 128, GBN = 128, GBK = 16;
constexpr int TW  = GBK / 2;                   // 8 u32 per row per tile
constexpr int LDW = 12;                        // padded row stride (conflict-free)
constexpr int A_SZ = GBM * LDW;                // 1536 u32
constexpr int W_SZ = GBN * LDW;                // 1536 u32

__global__ __launch_bounds__(256) void bf16x2_gemm_kernel(
    const uint32_t* __restrict__ hiX, const uint32_t* __restrict__ loX,
    const uint32_t* __restrict__ hiW, const uint32_t* __restrict__ loW,
    const float* __restrict__ b0, const float* __restrict__ b1,
    const float* __restrict__ b2,
    float* __restrict__ o0, float* __restrict__ o1, float* __restrict__ o2,
    int permute)
{
    __shared__ uint32_t AsH[2][A_SZ];
    __shared__ uint32_t AsL[2][A_SZ];
    __shared__ uint32_t WsH[2][W_SZ];
    __shared__ uint32_t WsL[2][W_SZ];

    const int z = blockIdx.z;
    const float* bias = (z == 0) ? b0 : (z == 1) ? b1 : b2;
    float* out = (z == 0) ? o0 : (z == 1) ? o1 : o2;

    const int tid  = threadIdx.x;
    const int warp = tid >> 5, lane = tid & 31;
    const int wm = warp & 3;        // 0..3 -> m offset (x32)
    const int wn = warp >> 2;       // 0..1 -> n offset (x64)
    const int m0 = blockIdx.y * GBM;
    const int n0 = blockIdx.x * GBN;
    const int gr = lane >> 2, gc = lane & 3;

    float acc[2][8][4];
    #pragma unroll
    for (int i = 0; i < 2; i++)
        #pragma unroll
        for (int j = 0; j < 8; j++)
            #pragma unroll
            for (int q = 0; q < 4; q++) acc[i][j][q] = 0.0f;

    // per-thread staging coords (packed u32 units); 2 cp16 each for A and W
    const int srow = tid >> 1, soff = (tid & 1) * 4;
    const uint32_t* AhP = hiX + (size_t)z * (NX / 2) + (size_t)(m0 + srow) * KW + soff;
    const uint32_t* AlP = loX + (size_t)z * (NX / 2) + (size_t)(m0 + srow) * KW + soff;
    const uint32_t* WhP = hiW + (size_t)z * (Dc * Dc / 2) + (size_t)(n0 + srow) * KW + soff;
    const uint32_t* WlP = loW + (size_t)z * (Dc * Dc / 2) + (size_t)(n0 + srow) * KW + soff;
    const int sidx = srow * LDW + soff;

    // stage tile 0 into buffer 0
    cp16(&AsH[0][sidx], AhP);
    cp16(&AsL[0][sidx], AlP);
    cp16(&WsH[0][sidx], WhP);
    cp16(&WsL[0][sidx], WlP);
    cp_commit();

    constexpr int NT = GK / GBK;   // 32 tiles
    for (int t = 0; t < NT; ++t) {
        const int buf = t & 1;
        if (t + 1 < NT) {
            const int o = (t + 1) * TW;
            cp16(&AsH[1 - buf][sidx], AhP + o);
            cp16(&AsL[1 - buf][sidx], AlP + o);
            cp16(&WsH[1 - buf][sidx], WhP + o);
            cp16(&WsL[1 - buf][sidx], WlP + o);
            cp_commit();
            cp_wait<1>();   // tile t landed; t+1 still streaming
        } else {
            cp_wait<0>();
        }
        __syncthreads();

        const uint32_t* aHs = AsH[buf];
        const uint32_t* aLs = AsL[buf];
        const uint32_t* wHs = WsH[buf];
        const uint32_t* wLs = WsL[buf];

        uint32_t aH[2][4], aL[2][4];
        #pragma unroll
        for (int ti = 0; ti < 2; ti++) {
            int mb = wm * 32 + ti * 16;
            int i0 = (mb + gr)     * LDW + gc;
            int i1 = (mb + gr + 8) * LDW + gc;
            aH[ti][0] = aHs[i0];     aH[ti][1] = aHs[i1];
            aH[ti][2] = aHs[i0 + 4]; aH[ti][3] = aHs[i1 + 4];
            aL[ti][0] = aLs[i0];     aL[ti][1] = aLs[i1];
            aL[ti][2] = aLs[i0 + 4]; aL[ti][3] = aLs[i1 + 4];
        }
        // tj processed in two halves of 4 to cap register pressure
        #pragma unroll
        for (int half = 0; half < 2; half++) {
            uint32_t bH[4][2], bL[4][2];
            #pragma unroll
            for (int tj = 0; tj < 4; tj++) {
                int nb = (wn * 64 + (half * 4 + tj) * 8 + gr) * LDW + gc;
                bH[tj][0] = wHs[nb]; bH[tj][1] = wHs[nb + 4];
                bL[tj][0] = wLs[nb]; bL[tj][1] = wLs[nb + 4];
            }
            #pragma unroll
            for (int ti = 0; ti < 2; ti++)
                #pragma unroll
                for (int tj = 0; tj < 4; tj++) {
                    mma_bf16(acc[ti][half * 4 + tj], aL[ti], bH[tj]);
                    mma_bf16(acc[ti][half * 4 + tj], aH[ti], bL[tj]);
                    mma_bf16(acc[ti][half * 4 + tj], aH[ti], bH[tj]);
                }
        }
        __syncthreads();
    }

    // ---- epilogue: bias + (optional) head permute, float2 stores ----
    #pragma unroll
    for (int ti = 0; ti < 2; ti++) {
        #pragma unroll
        for (int tj = 0; tj < 8; tj++) {
            int n = n0 + wn * 64 + tj * 8 + gc * 2;
            float bb0 = bias[n], bb1 = bias[n + 1];
            #pragma unroll
            for (int half = 0; half < 2; half++) {   // rows gr and gr+8
                int m = m0 + wm * 32 + ti * 16 + gr + half * 8;
                float2 v;
                v.x = acc[ti][tj][half * 2 + 0] + bb0;
                v.y = acc[ti][tj][half * 2 + 1] + bb1;
                if (!permute) {
                    *reinterpret_cast<float2*>(out + (size_t)m * Dc + n) = v;
                } else {
                    int b = m >> 11, l = m & 2047;
                    int h = n >> 6, d = n & 63;
                    *reinterpret_cast<float2*>(
                        out + (((size_t)(b * Hc + h)) * Lc + l) * DKc + d) = v;
                }
            }
        }
    }
}

// ---------------- merged QK_sample + vmean1 ------------------------------------
// blocks [0, 8192): qk_sample (warp per query, butterfly multi-reduce)
// blocks [8192, 8448): vmean1 (partial V sums)
template<int UT>
__global__ __launch_bounds__(256) void qk_vmean_kernel(const int* __restrict__ idxs)
{
    static_assert(UT > 32 && UT <= 64, "expects 32 < UT <= 64");
    const int bid = blockIdx.x;
    const int tid = threadIdx.x;

    if (bid >= 8192) {
        // ---- vmean1: partial sums over 256-row segments ----
        int blk = bid - 8192;             // 0..255
        int bh = blk >> 3, seg = blk & 7;
        int d = tid & 63, part = tid >> 6;
        const float* Vb = g_V + ((size_t)bh * Lc + seg * 256 + part * 64) * DKc;
        float acc = 0.0f;
        for (int l = 0; l < 64; ++l) acc += Vb[(size_t)l * 64 + d];
        __shared__ float red[256];
        red[tid] = acc;
        __syncthreads();
        if (part == 0)
            g_vpart[(bh * 8 + seg) * 64 + d] =
                red[d] + red[d + 64] + red[d + 128] + red[d + 192];
        return;
    }

    // ---- qk_sample ----
    int warp = (bid * 256 + tid) >> 5;
    int lane = tid & 31;
    int q  = warp % Lc;
    int bh = warp / Lc;

    const float* Qr = g_Q + ((size_t)bh * Lc + q) * 64;
    float q0 = Qr[lane], q1 = Qr[lane + 32];

    const int* ip = idxs + (size_t)q * UT;
    int idx0 = ip[lane];                                      // j = lane
    int idx1 = (lane < UT - 32) ? ip[32 + lane] : ip[UT - 1]; // pad dups last row

    const float* Kb = g_K + (size_t)bh * Lc * 64;

    float tot0, tot1;
    #pragma unroll
    for (int batch = 0; batch < 2; batch++) {
        int src = batch ? idx1 : idx0;
        float p[32];
        #pragma unroll
        for (int j = 0; j < 32; j++) {
            int ki = __shfl_sync(0xFFFFFFFFu, src, j);
            const float* Kr = Kb + (size_t)ki * 64;
            p[j] = fmaf(q0, Kr[lane], q1 * Kr[lane + 32]);
        }
        // xor-butterfly multi-reduce: lane ends with full sum of p[lane]
        #pragma unroll
        for (int o = 16; o >= 1; o >>= 1) {
            bool hi = (lane & o) != 0;
            #pragma unroll
            for (int j = 0; j < o; j++) {
                float a = p[j], b = p[j + o];
                float mine = hi ? b : a;
                float send = hi ? a : b;
                float theirs = __shfl_xor_sync(0xFFFFFFFFu, send, o);
                p[j] = mine + theirs;
            }
        }
        if (batch == 0) tot0 = p[0]; else tot1 = p[0];
    }

    bool v1 = (lane < UT - 32);
    float mx = fmaxf(tot0, v1 ? tot1 : -1e30f);
    float sm = tot0 + (v1 ? tot1 : 0.0f);
    #pragma unroll
    for (int o = 16; o > 0; o >>= 1) {
        mx = fmaxf(mx, __shfl_xor_sync(0xFFFFFFFFu, mx, o));
        sm += __shfl_xor_sync(0xFFFFFFFFu, sm, o);
    }
    if (lane == 0) g_M[(size_t)bh * Lc + q] = mx - sm * (1.0f / (float)Lc);
}

// generic fallback (runtime U) — qk only, vmean launched separately via same kernel
__global__ __launch_bounds__(256) void qk_sample_kernel(const int* __restrict__ idxs, int U)
{
    int warp = (blockIdx.x * blockDim.x + threadIdx.x) >> 5;
    int lane = threadIdx.x & 31;
    if (warp >= Bc * Hc * Lc) return;
    int q  = warp % Lc;
    int bh = warp / Lc;

    const float* Qr = g_Q + ((size_t)bh * Lc + q) * 64;
    float q0 = Qr[lane], q1 = Qr[lane + 32];

    float mx = -1e30f, sm = 0.0f;
    for (int j = 0; j < U; j++) {
        int ki = idxs[q * U + j];
        const float* Kr = g_K + ((size_t)bh * Lc + ki) * 64;
        float p = q0 * Kr[lane] + q1 * Kr[lane + 32];
        #pragma unroll
        for (int o = 16; o > 0; o >>= 1) p += __shfl_xor_sync(0xFFFFFFFFu, p, o);
        mx = fmaxf(mx, p);
        sm += p;
    }
    if (lane == 0) g_M[(size_t)bh * Lc + q] = mx - sm * (1.0f / (float)Lc);
}

__global__ __launch_bounds__(256) void vmean1_kernel()
{
    int blk = blockIdx.x;
    int bh = blk >> 3, seg = blk & 7;
    int tid = threadIdx.x;
    int d = tid & 63, part = tid >> 6;
    const float* Vb = g_V + ((size_t)bh * Lc + seg * 256 + part * 64) * DKc;
    float acc = 0.0f;
    for (int l = 0; l < 64; ++l) acc += Vb[(size_t)l * 64 + d];
    __shared__ float red[256];
    red[tid] = acc;
    __syncthreads();
    if (part == 0)
        g_vpart[(bh * 8 + seg) * 64 + d] =
            red[d] + red[d + 64] + red[d + 128] + red[d + 192];
}

// ---------------- merged vmean2 + top-U ----------------------------------------
// blocks [0, 32): topk per (b,h) — warp-shuffle argmax, 2 syncs/iteration
// blocks [32, 64): vmean2 (final V mean; threads < 64 active)
__global__ __launch_bounds__(256) void vmean2_topk_kernel(int U)
{
    const int bid = blockIdx.x;
    const int tid = threadIdx.x;

    if (bid >= 32) {
        int bh = bid - 32;
        if (tid < 64) {
            float s = 0.0f;
            #pragma unroll
            for (int i = 0; i < 8; i++) s += g_vpart[(bh * 8 + i) * 64 + tid];
            g_vmean[bh * 64 + tid] = s * (1.0f / Lc);
        }
        return;
    }

    const int bh = bid;
    const int warp = tid >> 5, lane = tid & 31;
    __shared__ float vals[Lc];
    __shared__ float wv[8];
    __shared__ int   wi[8];

    for (int i = tid; i < Lc; i += 256) vals[i] = g_M[(size_t)bh * Lc + i];
    __syncthreads();

    for (int it = 0; it < U; it++) {
        // per-thread scan of 8 strided elements
        float bv = -1e30f; int bi = Lc;
        #pragma unroll
        for (int c = 0; c < 8; c++) {
            int i = tid + c * 256;
            float v = vals[i];
            if (v > bv) { bv = v; bi = i; }
        }
        // warp argmax (tie: smaller index)
        #pragma unroll
        for (int o = 16; o > 0; o >>= 1) {
            float ov = __shfl_down_sync(0xFFFFFFFFu, bv, o);
            int   oi = __shfl_down_sync(0xFFFFFFFFu, bi, o);
            if (ov > bv || (ov == bv && oi < bi)) { bv = ov; bi = oi; }
        }
        if (lane == 0) { wv[warp] = bv; wi[warp] = bi; }
        __syncthreads();
        if (warp == 0) {
            float fv = (lane < 8) ? wv[lane] : -1e30f;
            int   fi = (lane < 8) ? wi[lane] : Lc;
            #pragma unroll
            for (int o = 4; o > 0; o >>= 1) {
                float ov = __shfl_down_sync(0xFFFFFFFFu, fv, o);
                int   oi = __shfl_down_sync(0xFFFFFFFFu, fi, o);
                if (ov > fv || (ov == fv && oi < fi)) { fv = ov; fi = oi; }
            }
            if (lane == 0) {
                g_top[bh * UMAX + it] = fi;
                vals[fi] = -1e30f;
            }
        }
        __syncthreads();
    }
}

// ---------------- fill ctx planes with bf16-split V-mean broadcast -----------
__global__ __launch_bounds__(256) void fill_ctx_plane_kernel()
{
    int p = blockIdx.x * 256 + threadIdx.x;   // over NX/2 packed units
    int m = p >> 8;            // row (256 u32 per row)
    int j = p & 255;           // packed col
    int b = m >> 11;
    int h = j >> 5;
    int d0 = (j & 31) * 2;
    const float* vm = g_vmean + (b * Hc + h) * 64;
    uint32_t hi, lo;
    split_pack2(vm[d0], vm[d0 + 1], hi, lo);
    g_hiX[p] = hi;
    g_loX[p] = lo;
}

// ---------------- flash-style attention for top-u queries (8 per block) ------
// writes results straight into the ctx bf16 planes (slot 0)
__global__ __launch_bounds__(256) void sparse_attn2_kernel(int U)
{
    int bh = blockIdx.x;
    int b  = bh >> 3, h = bh & 7;
    int tid = threadIdx.x, w = tid >> 5, lane = tid & 31;
    int ui = blockIdx.y * 8 + w;
    bool active = ui < U;
    int lq = active ? g_top[bh * UMAX + ui] : 0;

    __shared__ float qv[8][64];
    __shared__ float Ks[64][65];
    __shared__ float Vs[64][65];

    const float* Qr = g_Q + ((size_t)bh * Lc + lq) * 64;
    qv[w][lane]      = Qr[lane]      * 0.125f;   // 1/sqrt(64)
    qv[w][lane + 32] = Qr[lane + 32] * 0.125f;
    __syncthreads();

    float m = -1e30f, l = 0.0f, acc0 = 0.0f, acc1 = 0.0f;

    const float* Kb = g_K + (size_t)bh * Lc * 64;
    const float* Vb = g_V + (size_t)bh * Lc * 64;
    const int row = tid >> 2;           // 0..63
    const int cb  = (tid & 3) * 4;      // col base; strided +16

    for (int kc = 0; kc < Lc / 64; ++kc) {
        #pragma unroll
        for (int s = 0; s < 4; ++s) {
            int c = cb + s * 16;
            const float* kp = Kb + ((size_t)(kc * 64 + row)) * 64 + c;
            const float* vp = Vb + ((size_t)(kc * 64 + row)) * 64 + c;
            float4 kv = *reinterpret_cast<const float4*>(kp);
            float4 vv = *reinterpret_cast<const float4*>(vp);
            Ks[row][c] = kv.x; Ks[row][c+1] = kv.y; Ks[row][c+2] = kv.z; Ks[row][c+3] = kv.w;
            Vs[row][c] = vv.x; Vs[row][c+1] = vv.y; Vs[row][c+2] = vv.z; Vs[row][c+3] = vv.w;
        }
        __syncthreads();

        float s0 = 0.0f, s1 = 0.0f;
        #pragma unroll 16
        for (int c = 0; c < 64; ++c) {
            float qc = qv[w][c];
            s0 = fmaf(qc, Ks[lane][c],      s0);
            s1 = fmaf(qc, Ks[lane + 32][c], s1);
        }

        float cm = fmaxf(s0, s1);
        #pragma unroll
        for (int o = 16; o > 0; o >>= 1)
            cm = fmaxf(cm, __shfl_xor_sync(0xFFFFFFFFu, cm, o));
        float mn = fmaxf(m, cm);
        float corr = expf(m - mn);
        l *= corr; acc0 *= corr; acc1 *= corr;
        float p0 = expf(s0 - mn), p1 = expf(s1 - mn);
        float ps = p0 + p1;
        #pragma unroll
        for (int o = 16; o > 0; o >>= 1)
            ps += __shfl_xor_sync(0xFFFFFFFFu, ps, o);
        l += ps;
        m = mn;

        #pragma unroll 8
        for (int r = 0; r < 32; ++r) {
            float pa = __shfl_sync(0xFFFFFFFFu, p0, r);
            float pb = __shfl_sync(0xFFFFFFFFu, p1, r);
            acc0 = fmaf(pa, Vs[r][lane],           acc0);
            acc1 = fmaf(pa, Vs[r][lane + 32],      acc1);
            acc0 = fmaf(pb, Vs[r + 32][lane],      acc0);
            acc1 = fmaf(pb, Vs[r + 32][lane + 32], acc1);
        }
        __syncthreads();
    }

    if (active) {
        float inv = 1.0f / l;
        int srcA = (lane & 15) * 2, srcB = srcA + 1;
        float a0a = __shfl_sync(0xFFFFFFFFu, acc0, srcA);
        float a0b = __shfl_sync(0xFFFFFFFFu, acc0, srcB);
        float a1a = __shfl_sync(0xFFFFFFFFu, acc1, srcA);
        float a1b = __shfl_sync(0xFFFFFFFFu, acc1, srcB);
        float va = (lane < 16 ? a0a : a1a) * inv;
        float vb = (lane < 16 ? a0b : a1b) * inv;
        uint32_t hi, lo;
        split_pack2(va, vb, hi, lo);
        size_t idx = ((size_t)b * Lc + lq) * 256 + h * 32 + lane;
        g_hiX[idx] = hi;
        g_loX[idx] = lo;
    }
}

// ---------------- launch ------------------------------------------------------
extern "C" void kernel_launch(void* const* d_in, const int* in_sizes, int n_in,
                              void* d_out, int out_size)
{
    const float* queries = (const float*)d_in[0];
    const float* keys    = (const float*)d_in[1];
    const float* values  = (const float*)d_in[2];
    const float* Wq = (const float*)d_in[3];
    const float* bq = (const float*)d_in[4];
    const float* Wk = (const float*)d_in[5];
    const float* bk = (const float*)d_in[6];
    const float* Wv = (const float*)d_in[7];
    const float* bv = (const float*)d_in[8];
    const float* Wo = (const float*)d_in[9];
    const float* bo = (const float*)d_in[10];
    const int* index_sample = (const int*)d_in[11];

    int U = in_sizes[11] / Lc;   // 40 for this bench
    if (U > UMAX) U = UMAX;

    float *qp, *kp, *vp;
    cudaGetSymbolAddress((void**)&qp,  g_Q);
    cudaGetSymbolAddress((void**)&kp,  g_K);
    cudaGetSymbolAddress((void**)&vp,  g_V);
    uint32_t *hiX, *loX, *hiW, *loW;
    cudaGetSymbolAddress((void**)&hiX, g_hiX);
    cudaGetSymbolAddress((void**)&loX, g_loX);
    cudaGetSymbolAddress((void**)&hiW, g_hiW);
    cudaGetSymbolAddress((void**)&loW, g_loW);

    const int WSZ2 = Dc * Dc / 2;          // packed u32 per W plane
    dim3 ggrid3(Dc / GBN, (Bc * Lc) / GBM, 3);  // (4, 64, 3)
    dim3 ggrid1(Dc / GBN, (Bc * Lc) / GBM, 1);
    int warps = Bc * Hc * Lc;

    // 0: merged presplit (4 W slices + 3 X tensors)
    presplit_all_kernel<<<1024 + 3 * 4096, 256>>>(Wq, Wk, Wv, Wo,
                                                  queries, keys, values);

    // 1: merged QKV projection GEMM
    bf16x2_gemm_kernel<<<ggrid3, 256>>>(hiX, loX, hiW, loW,
                                        bq, bk, bv, qp, kp, vp, 1);

    // 2: qk_sample + vmean1 (independent, overlapped in one launch)
    if (U == 40) {
        qk_vmean_kernel<40><<<8192 + 256, 256>>>(index_sample);
    } else {
        qk_sample_kernel<<<(warps * 32) / 256, 256>>>(index_sample, U);
        vmean1_kernel<<<256, 256>>>();
    }

    // 3 <- profiled: vmean2 + topk merged
    vmean2_topk_kernel<<<64, 256>>>(U);

    // 4: fill ctx planes with vmean broadcast
    fill_ctx_plane_kernel<<<NX / 2 / 256, 256>>>();

    // 5: sparse attention, scatter into ctx planes
    sparse_attn2_kernel<<<dim3(Bc * Hc, (U + 7) / 8), 256>>>(U);

    // 6: output projection
    bf16x2_gemm_kernel<<<ggrid1, 256>>>(hiX, loX, hiW + 3 * WSZ2,
                                        loW + 3 * WSZ2, bo, bo, bo,
                                        (float*)d_out, nullptr, nullptr, 0);
}

// round 16
// speedup vs baseline: 1.6593x; 1.0019x over previous
#include <cuda_runtime.h>
#include <cuda_bf16.h>
#include <math.h>
#include <stdint.h>

// Problem constants (fixed shapes for this bench)
constexpr int Bc  = 4;
constexpr int Lc  = 2048;
constexpr int Dc  = 512;
constexpr int Hc  = 8;
constexpr int DKc = 64;
constexpr int UMAX = 64;   // safety cap for top-k storage (actual U = 40)
constexpr int NX  = Bc * Lc * Dc;     // elements in one (B,L,D) tensor

// ---------------- scratch (device globals; no allocation allowed) ------------
__device__ float g_Q[Bc*Hc*Lc*DKc];      // (b,h,l,d)  16 MB
__device__ float g_K[Bc*Hc*Lc*DKc];      // 16 MB
__device__ float g_V[Bc*Hc*Lc*DKc];      // 16 MB
__device__ float g_M[Bc*Hc*Lc];          // sparsity measure
__device__ int   g_top[Bc*Hc*UMAX];      // top-u indices per (b,h)
__device__ float g_vmean[Bc*Hc*DKc];     // V mean over L
__device__ float g_vpart[Bc*Hc*8*DKc];   // partial V sums

// bf16 hi/lo planes, packed 2 consecutive-k bf16 per u32 (low half = even k)
// slot 0 doubles as the ctx planes for the output GEMM.
__device__ uint32_t g_hiX[3*NX/2], g_loX[3*NX/2];
__device__ uint32_t g_hiW[4*Dc*Dc/2], g_loW[4*Dc*Dc/2];

// ---------------- bf16 split helpers ------------------------------------------
__device__ __forceinline__ void split_pack2(float a, float b,
                                            uint32_t& hi, uint32_t& lo) {
    __nv_bfloat16 ha = __float2bfloat16_rn(a);
    __nv_bfloat16 hb = __float2bfloat16_rn(b);
    float ra = a - __bfloat162float(ha);
    float rb = b - __bfloat162float(hb);
    __nv_bfloat162 hv = __floats2bfloat162_rn(__bfloat162float(ha), __bfloat162float(hb));
    __nv_bfloat162 lv = __floats2bfloat162_rn(ra, rb);
    hi = *reinterpret_cast<uint32_t*>(&hv);
    lo = *reinterpret_cast<uint32_t*>(&lv);
}

__device__ __forceinline__ void mma_bf16(float (&d)[4], const uint32_t (&a)[4],
                                         const uint32_t (&b)[2]) {
    asm volatile(
        "mma.sync.aligned.m16n8k16.row.col.f32.bf16.bf16.f32 "
        "{%0,%1,%2,%3}, {%4,%5,%6,%7}, {%8,%9}, {%0,%1,%2,%3};"
        : "+f"(d[0]), "+f"(d[1]), "+f"(d[2]), "+f"(d[3])
        : "r"(a[0]), "r"(a[1]), "r"(a[2]), "r"(a[3]), "r"(b[0]), "r"(b[1]));
}

__device__ __forceinline__ void cp16(void* smem, const void* gmem) {
    uint32_t s = (uint32_t)__cvta_generic_to_shared(smem);
    asm volatile("cp.async.cg.shared.global [%0], [%1], 16;" :: "r"(s), "l"(gmem));
}
__device__ __forceinline__ void cp_commit() {
    asm volatile("cp.async.commit_group;" ::: "memory");
}
template<int N>
__device__ __forceinline__ void cp_wait() {
    asm volatile("cp.async.wait_group %0;" :: "n"(N) : "memory");
}

// ---------------- merged pre-split kernel --------------------------------------
// blocks [0, 1024): W planes (4 slots x 256 blocks over Dc*Dc/4 float4s)
// blocks [1024, 1024+3*4096): X planes (3 tensors x 4096 blocks over NX/4 float4s)
__global__ __launch_bounds__(256) void presplit_all_kernel(
    const float* __restrict__ w0, const float* __restrict__ w1,
    const float* __restrict__ w2, const float* __restrict__ w3,
    const float* __restrict__ x0, const float* __restrict__ x1,
    const float* __restrict__ x2)
{
    int bid = blockIdx.x;
    if (bid < 1024) {
        const float* srcs[4] = {w0, w1, w2, w3};
        int wsel = bid >> 8;
        int i = (bid & 255) * 256 + threadIdx.x;
        float4 v = reinterpret_cast<const float4*>(srcs[wsel])[i];
        uint32_t h0, l0, h1, l1;
        split_pack2(v.x, v.y, h0, l0);
        split_pack2(v.z, v.w, h1, l1);
        size_t o = (size_t)wsel * (Dc * Dc / 2) + (size_t)i * 2;
        g_hiW[o] = h0; g_hiW[o + 1] = h1;
        g_loW[o] = l0; g_loW[o + 1] = l1;
    } else {
        const float* srcs[3] = {x0, x1, x2};
        int rb = bid - 1024;
        int z = rb >> 12;            // /4096
        int i = (rb & 4095) * 256 + threadIdx.x;
        float4 v = reinterpret_cast<const float4*>(srcs[z])[i];
        uint32_t h0, l0, h1, l1;
        split_pack2(v.x, v.y, h0, l0);
        split_pack2(v.z, v.w, h1, l1);
        size_t o = (size_t)z * (NX / 2) + (size_t)i * 2;
        g_hiX[o] = h0; g_hiX[o + 1] = h1;
        g_loX[o] = l0; g_loX[o + 1] = l1;
    }
}

// ---------------- Split-bf16 GEMM, 128x128 block (R12 best) -------------------
// out_z = X_z[M,512] @ W_z[512,512]^T + bias_z    (z = blockIdx.z)
// acc += aL*bH + aH*bL + aH*bH (3 bf16 m16n8k16 MMAs).
// BM=128, BN=128, BK=16, 256 threads (8 warps, 4m x 2n), warp tile 32x64.
constexpr int GK  = 512;
constexpr int KW  = GK / 2;                    // 256 u32 per row (packed)
constexpr int GBM = 128, GBN = 128, GBK = 16;
constexpr int TW  = GBK / 2;                   // 8 u32 per row per tile
constexpr int LDW = 12;                        // padded row stride (conflict-free)
constexpr int A_SZ = GBM * LDW;                // 1536 u32
constexpr int W_SZ = GBN * LDW;                // 1536 u32

__global__ __launch_bounds__(256) void bf16x2_gemm_kernel(
    const uint32_t* __restrict__ hiX, const uint32_t* __restrict__ loX,
    const uint32_t* __restrict__ hiW, const uint32_t* __restrict__ loW,
    const float* __restrict__ b0, const float* __restrict__ b1,
    const float* __restrict__ b2,
    float* __restrict__ o0, float* __restrict__ o1, float* __restrict__ o2,
    int permute)
{
    __shared__ uint32_t AsH[2][A_SZ];
    __shared__ uint32_t AsL[2][A_SZ];
    __shared__ uint32_t WsH[2][W_SZ];
    __shared__ uint32_t WsL[2][W_SZ];

    const int z = blockIdx.z;
    const float* bias = (z == 0) ? b0 : (z == 1) ? b1 : b2;
    float* out = (z == 0) ? o0 : (z == 1) ? o1 : o2;

    const int tid  = threadIdx.x;
    const int warp = tid >> 5, lane = tid & 31;
    const int wm = warp & 3;        // 0..3 -> m offset (x32)
    const int wn = warp >> 2;       // 0..1 -> n offset (x64)
    const int m0 = blockIdx.y * GBM;
    const int n0 = blockIdx.x * GBN;
    const int gr = lane >> 2, gc = lane & 3;

    float acc[2][8][4];
    #pragma unroll
    for (int i = 0; i < 2; i++)
        #pragma unroll
        for (int j = 0; j < 8; j++)
            #pragma unroll
            for (int q = 0; q < 4; q++) acc[i][j][q] = 0.0f;

    // per-thread staging coords (packed u32 units); 2 cp16 each for A and W
    const int srow = tid >> 1, soff = (tid & 1) * 4;
    const uint32_t* AhP = hiX + (size_t)z * (NX / 2) + (size_t)(m0 + srow) * KW + soff;
    const uint32_t* AlP = loX + (size_t)z * (NX / 2) + (size_t)(m0 + srow) * KW + soff;
    const uint32_t* WhP = hiW + (size_t)z * (Dc * Dc / 2) + (size_t)(n0 + srow) * KW + soff;
    const uint32_t* WlP = loW + (size_t)z * (Dc * Dc / 2) + (size_t)(n0 + srow) * KW + soff;
    const int sidx = srow * LDW + soff;

    // stage tile 0 into buffer 0
    cp16(&AsH[0][sidx], AhP);
    cp16(&AsL[0][sidx], AlP);
    cp16(&WsH[0][sidx], WhP);
    cp16(&WsL[0][sidx], WlP);
    cp_commit();

    constexpr int NT = GK / GBK;   // 32 tiles
    for (int t = 0; t < NT; ++t) {
        const int buf = t & 1;
        if (t + 1 < NT) {
            const int o = (t + 1) * TW;
            cp16(&AsH[1 - buf][sidx], AhP + o);
            cp16(&AsL[1 - buf][sidx], AlP + o);
            cp16(&WsH[1 - buf][sidx], WhP + o);
            cp16(&WsL[1 - buf][sidx], WlP + o);
            cp_commit();
            cp_wait<1>();   // tile t landed; t+1 still streaming
        } else {
            cp_wait<0>();
        }
        __syncthreads();

        const uint32_t* aHs = AsH[buf];
        const uint32_t* aLs = AsL[buf];
        const uint32_t* wHs = WsH[buf];
        const uint32_t* wLs = WsL[buf];

        uint32_t aH[2][4], aL[2][4];
        #pragma unroll
        for (int ti = 0; ti < 2; ti++) {
            int mb = wm * 32 + ti * 16;
            int i0 = (mb + gr)     * LDW + gc;
            int i1 = (mb + gr + 8) * LDW + gc;
            aH[ti][0] = aHs[i0];     aH[ti][1] = aHs[i1];
            aH[ti][2] = aHs[i0 + 4]; aH[ti][3] = aHs[i1 + 4];
            aL[ti][0] = aLs[i0];     aL[ti][1] = aLs[i1];
            aL[ti][2] = aLs[i0 + 4]; aL[ti][3] = aLs[i1 + 4];
        }
        // tj processed in two halves of 4 to cap register pressure
        #pragma unroll
        for (int half = 0; half < 2; half++) {
            uint32_t bH[4][2], bL[4][2];
            #pragma unroll
            for (int tj = 0; tj < 4; tj++) {
                int nb = (wn * 64 + (half * 4 + tj) * 8 + gr) * LDW + gc;
                bH[tj][0] = wHs[nb]; bH[tj][1] = wHs[nb + 4];
                bL[tj][0] = wLs[nb]; bL[tj][1] = wLs[nb + 4];
            }
            #pragma unroll
            for (int ti = 0; ti < 2; ti++)
                #pragma unroll
                for (int tj = 0; tj < 4; tj++) {
                    mma_bf16(acc[ti][half * 4 + tj], aL[ti], bH[tj]);
                    mma_bf16(acc[ti][half * 4 + tj], aH[ti], bL[tj]);
                    mma_bf16(acc[ti][half * 4 + tj], aH[ti], bH[tj]);
                }
        }
        __syncthreads();
    }

    // ---- epilogue: bias + (optional) head permute, float2 stores ----
    #pragma unroll
    for (int ti = 0; ti < 2; ti++) {
        #pragma unroll
        for (int tj = 0; tj < 8; tj++) {
            int n = n0 + wn * 64 + tj * 8 + gc * 2;
            float bb0 = bias[n], bb1 = bias[n + 1];
            #pragma unroll
            for (int half = 0; half < 2; half++) {   // rows gr and gr+8
                int m = m0 + wm * 32 + ti * 16 + gr + half * 8;
                float2 v;
                v.x = acc[ti][tj][half * 2 + 0] + bb0;
                v.y = acc[ti][tj][half * 2 + 1] + bb1;
                if (!permute) {
                    *reinterpret_cast<float2*>(out + (size_t)m * Dc + n) = v;
                } else {
                    int b = m >> 11, l = m & 2047;
                    int h = n >> 6, d = n & 63;
                    *reinterpret_cast<float2*>(
                        out + (((size_t)(b * Hc + h)) * Lc + l) * DKc + d) = v;
                }
            }
        }
    }
}

// ---------------- merged QK_sample + vmean1 ------------------------------------
// blocks [0, 8192): qk_sample (warp per query, butterfly multi-reduce)
// blocks [8192, 8448): vmean1 (partial V sums)
template<int UT>
__global__ __launch_bounds__(256) void qk_vmean_kernel(const int* __restrict__ idxs)
{
    static_assert(UT > 32 && UT <= 64, "expects 32 < UT <= 64");
    const int bid = blockIdx.x;
    const int tid = threadIdx.x;

    if (bid >= 8192) {
        // ---- vmean1: partial sums over 256-row segments ----
        int blk = bid - 8192;             // 0..255
        int bh = blk >> 3, seg = blk & 7;
        int d = tid & 63, part = tid >> 6;
        const float* Vb = g_V + ((size_t)bh * Lc + seg * 256 + part * 64) * DKc;
        float acc = 0.0f;
        for (int l = 0; l < 64; ++l) acc += Vb[(size_t)l * 64 + d];
        __shared__ float red[256];
        red[tid] = acc;
        __syncthreads();
        if (part == 0)
            g_vpart[(bh * 8 + seg) * 64 + d] =
                red[d] + red[d + 64] + red[d + 128] + red[d + 192];
        return;
    }

    // ---- qk_sample ----
    int warp = (bid * 256 + tid) >> 5;
    int lane = tid & 31;
    int q  = warp % Lc;
    int bh = warp / Lc;

    const float* Qr = g_Q + ((size_t)bh * Lc + q) * 64;
    float q0 = Qr[lane], q1 = Qr[lane + 32];

    const int* ip = idxs + (size_t)q * UT;
    int idx0 = ip[lane];                                      // j = lane
    int idx1 = (lane < UT - 32) ? ip[32 + lane] : ip[UT - 1]; // pad dups last row

    const float* Kb = g_K + (size_t)bh * Lc * 64;

    float tot0, tot1;
    #pragma unroll
    for (int batch = 0; batch < 2; batch++) {
        int src = batch ? idx1 : idx0;
        float p[32];
        #pragma unroll
        for (int j = 0; j < 32; j++) {
            int ki = __shfl_sync(0xFFFFFFFFu, src, j);
            const float* Kr = Kb + (size_t)ki * 64;
            p[j] = fmaf(q0, Kr[lane], q1 * Kr[lane + 32]);
        }
        // xor-butterfly multi-reduce: lane ends with full sum of p[lane]
        #pragma unroll
        for (int o = 16; o >= 1; o >>= 1) {
            bool hi = (lane & o) != 0;
            #pragma unroll
            for (int j = 0; j < o; j++) {
                float a = p[j], b = p[j + o];
                float mine = hi ? b : a;
                float send = hi ? a : b;
                float theirs = __shfl_xor_sync(0xFFFFFFFFu, send, o);
                p[j] = mine + theirs;
            }
        }
        if (batch == 0) tot0 = p[0]; else tot1 = p[0];
    }

    bool v1 = (lane < UT - 32);
    float mx = fmaxf(tot0, v1 ? tot1 : -1e30f);
    float sm = tot0 + (v1 ? tot1 : 0.0f);
    #pragma unroll
    for (int o = 16; o > 0; o >>= 1) {
        mx = fmaxf(mx, __shfl_xor_sync(0xFFFFFFFFu, mx, o));
        sm += __shfl_xor_sync(0xFFFFFFFFu, sm, o);
    }
    if (lane == 0) g_M[(size_t)bh * Lc + q] = mx - sm * (1.0f / (float)Lc);
}

// generic fallback (runtime U) — qk only, vmean launched separately via same kernel
__global__ __launch_bounds__(256) void qk_sample_kernel(const int* __restrict__ idxs, int U)
{
    int warp = (blockIdx.x * blockDim.x + threadIdx.x) >> 5;
    int lane = threadIdx.x & 31;
    if (warp >= Bc * Hc * Lc) return;
    int q  = warp % Lc;
    int bh = warp / Lc;

    const float* Qr = g_Q + ((size_t)bh * Lc + q) * 64;
    float q0 = Qr[lane], q1 = Qr[lane + 32];

    float mx = -1e30f, sm = 0.0f;
    for (int j = 0; j < U; j++) {
        int ki = idxs[q * U + j];
        const float* Kr = g_K + ((size_t)bh * Lc + ki) * 64;
        float p = q0 * Kr[lane] + q1 * Kr[lane + 32];
        #pragma unroll
        for (int o = 16; o > 0; o >>= 1) p += __shfl_xor_sync(0xFFFFFFFFu, p, o);
        mx = fmaxf(mx, p);
        sm += p;
    }
    if (lane == 0) g_M[(size_t)bh * Lc + q] = mx - sm * (1.0f / (float)Lc);
}

__global__ __launch_bounds__(256) void vmean1_kernel()
{
    int blk = blockIdx.x;
    int bh = blk >> 3, seg = blk & 7;
    int tid = threadIdx.x;
    int d = tid & 63, part = tid >> 6;
    const float* Vb = g_V + ((size_t)bh * Lc + seg * 256 + part * 64) * DKc;
    float acc = 0.0f;
    for (int l = 0; l < 64; ++l) acc += Vb[(size_t)l * 64 + d];
    __shared__ float red[256];
    red[tid] = acc;
    __syncthreads();
    if (part == 0)
        g_vpart[(bh * 8 + seg) * 64 + d] =
            red[d] + red[d + 64] + red[d + 128] + red[d + 192];
}

// ---------------- merged vmean2 + top-U ----------------------------------------
// blocks [0, 32): topk per (b,h) — warp-shuffle argmax, 2 syncs/iteration
// blocks [32, 64): vmean2 (final V mean; threads < 64 active)
__global__ __launch_bounds__(256) void vmean2_topk_kernel(int U)
{
    const int bid = blockIdx.x;
    const int tid = threadIdx.x;

    if (bid >= 32) {
        int bh = bid - 32;
        if (tid < 64) {
            float s = 0.0f;
            #pragma unroll
            for (int i = 0; i < 8; i++) s += g_vpart[(bh * 8 + i) * 64 + tid];
            g_vmean[bh * 64 + tid] = s * (1.0f / Lc);
        }
        return;
    }

    const int bh = bid;
    const int warp = tid >> 5, lane = tid & 31;
    __shared__ float vals[Lc];
    __shared__ float wv[8];
    __shared__ int   wi[8];

    for (int i = tid; i < Lc; i += 256) vals[i] = g_M[(size_t)bh * Lc + i];
    __syncthreads();

    for (int it = 0; it < U; it++) {
        // per-thread scan of 8 strided elements
        float bv = -1e30f; int bi = Lc;
        #pragma unroll
        for (int c = 0; c < 8; c++) {
            int i = tid + c * 256;
            float v = vals[i];
            if (v > bv) { bv = v; bi = i; }
        }
        // warp argmax (tie: smaller index)
        #pragma unroll
        for (int o = 16; o > 0; o >>= 1) {
            float ov = __shfl_down_sync(0xFFFFFFFFu, bv, o);
            int   oi = __shfl_down_sync(0xFFFFFFFFu, bi, o);
            if (ov > bv || (ov == bv && oi < bi)) { bv = ov; bi = oi; }
        }
        if (lane == 0) { wv[warp] = bv; wi[warp] = bi; }
        __syncthreads();
        if (warp == 0) {
            float fv = (lane < 8) ? wv[lane] : -1e30f;
            int   fi = (lane < 8) ? wi[lane] : Lc;
            #pragma unroll
            for (int o = 4; o > 0; o >>= 1) {
                float ov = __shfl_down_sync(0xFFFFFFFFu, fv, o);
                int   oi = __shfl_down_sync(0xFFFFFFFFu, fi, o);
                if (ov > fv || (ov == fv && oi < fi)) { fv = ov; fi = oi; }
            }
            if (lane == 0) {
                g_top[bh * UMAX + it] = fi;
                vals[fi] = -1e30f;
            }
        }
        __syncthreads();
    }
}

// ---------------- fill ctx planes with bf16-split V-mean broadcast -----------
__global__ __launch_bounds__(256) void fill_ctx_plane_kernel()
{
    int p = blockIdx.x * 256 + threadIdx.x;   // over NX/2 packed units
    int m = p >> 8;            // row (256 u32 per row)
    int j = p & 255;           // packed col
    int b = m >> 11;
    int h = j >> 5;
    int d0 = (j & 31) * 2;
    const float* vm = g_vmean + (b * Hc + h) * 64;
    uint32_t hi, lo;
    split_pack2(vm[d0], vm[d0 + 1], hi, lo);
    g_hiX[p] = hi;
    g_loX[p] = lo;
}

// ---------------- flash-style attention for top-u queries (8 per block) ------
// writes results straight into the ctx bf16 planes (slot 0)
__global__ __launch_bounds__(256) void sparse_attn2_kernel(int U)
{
    int bh = blockIdx.x;
    int b  = bh >> 3, h = bh & 7;
    int tid = threadIdx.x, w = tid >> 5, lane = tid & 31;
    int ui = blockIdx.y * 8 + w;
    bool active = ui < U;
    int lq = active ? g_top[bh * UMAX + ui] : 0;

    __shared__ float qv[8][64];
    __shared__ float Ks[64][65];
    __shared__ float Vs[64][65];

    const float* Qr = g_Q + ((size_t)bh * Lc + lq) * 64;
    qv[w][lane]      = Qr[lane]      * 0.125f;   // 1/sqrt(64)
    qv[w][lane + 32] = Qr[lane + 32] * 0.125f;
    __syncthreads();

    float m = -1e30f, l = 0.0f, acc0 = 0.0f, acc1 = 0.0f;

    const float* Kb = g_K + (size_t)bh * Lc * 64;
    const float* Vb = g_V + (size_t)bh * Lc * 64;
    const int row = tid >> 2;           // 0..63
    const int cb  = (tid & 3) * 4;      // col base; strided +16

    for (int kc = 0; kc < Lc / 64; ++kc) {
        #pragma unroll
        for (int s = 0; s < 4; ++s) {
            int c = cb + s * 16;
            const float* kp = Kb + ((size_t)(kc * 64 + row)) * 64 + c;
            const float* vp = Vb + ((size_t)(kc * 64 + row)) * 64 + c;
            float4 kv = *reinterpret_cast<const float4*>(kp);
            float4 vv = *reinterpret_cast<const float4*>(vp);
            Ks[row][c] = kv.x; Ks[row][c+1] = kv.y; Ks[row][c+2] = kv.z; Ks[row][c+3] = kv.w;
            Vs[row][c] = vv.x; Vs[row][c+1] = vv.y; Vs[row][c+2] = vv.z; Vs[row][c+3] = vv.w;
        }
        __syncthreads();

        float s0 = 0.0f, s1 = 0.0f;
        #pragma unroll 16
        for (int c = 0; c < 64; ++c) {
            float qc = qv[w][c];
            s0 = fmaf(qc, Ks[lane][c],      s0);
            s1 = fmaf(qc, Ks[lane + 32][c], s1);
        }

        float cm = fmaxf(s0, s1);
        #pragma unroll
        for (int o = 16; o > 0; o >>= 1)
            cm = fmaxf(cm, __shfl_xor_sync(0xFFFFFFFFu, cm, o));
        float mn = fmaxf(m, cm);
        float corr = expf(m - mn);
        l *= corr; acc0 *= corr; acc1 *= corr;
        float p0 = expf(s0 - mn), p1 = expf(s1 - mn);
        float ps = p0 + p1;
        #pragma unroll
        for (int o = 16; o > 0; o >>= 1)
            ps += __shfl_xor_sync(0xFFFFFFFFu, ps, o);
        l += ps;
        m = mn;

        #pragma unroll 8
        for (int r = 0; r < 32; ++r) {
            float pa = __shfl_sync(0xFFFFFFFFu, p0, r);
            float pb = __shfl_sync(0xFFFFFFFFu, p1, r);
            acc0 = fmaf(pa, Vs[r][lane],           acc0);
            acc1 = fmaf(pa, Vs[r][lane + 32],      acc1);
            acc0 = fmaf(pb, Vs[r + 32][lane],      acc0);
            acc1 = fmaf(pb, Vs[r + 32][lane + 32], acc1);
        }
        __syncthreads();
    }

    if (active) {
        float inv = 1.0f / l;
        int srcA = (lane & 15) * 2, srcB = srcA + 1;
        float a0a = __shfl_sync(0xFFFFFFFFu, acc0, srcA);
        float a0b = __shfl_sync(0xFFFFFFFFu, acc0, srcB);
        float a1a = __shfl_sync(0xFFFFFFFFu, acc1, srcA);
        float a1b = __shfl_sync(0xFFFFFFFFu, acc1, srcB);
        float va = (lane < 16 ? a0a : a1a) * inv;
        float vb = (lane < 16 ? a0b : a1b) * inv;
        uint32_t hi, lo;
        split_pack2(va, vb, hi, lo);
        size_t idx = ((size_t)b * Lc + lq) * 256 + h * 32 + lane;
        g_hiX[idx] = hi;
        g_loX[idx] = lo;
    }
}

// ---------------- launch ------------------------------------------------------
extern "C" void kernel_launch(void* const* d_in, const int* in_sizes, int n_in,
                              void* d_out, int out_size)
{
    const float* queries = (const float*)d_in[0];
    const float* keys    = (const float*)d_in[1];
    const float* values  = (const float*)d_in[2];
    const float* Wq = (const float*)d_in[3];
    const float* bq = (const float*)d_in[4];
    const float* Wk = (const float*)d_in[5];
    const float* bk = (const float*)d_in[6];
    const float* Wv = (const float*)d_in[7];
    const float* bv = (const float*)d_in[8];
    const float* Wo = (const float*)d_in[9];
    const float* bo = (const float*)d_in[10];
    const int* index_sample = (const int*)d_in[11];

    int U = in_sizes[11] / Lc;   // 40 for this bench
    if (U > UMAX) U = UMAX;

    float *qp, *kp, *vp;
    cudaGetSymbolAddress((void**)&qp,  g_Q);
    cudaGetSymbolAddress((void**)&kp,  g_K);
    cudaGetSymbolAddress((void**)&vp,  g_V);
    uint32_t *hiX, *loX, *hiW, *loW;
    cudaGetSymbolAddress((void**)&hiX, g_hiX);
    cudaGetSymbolAddress((void**)&loX, g_loX);
    cudaGetSymbolAddress((void**)&hiW, g_hiW);
    cudaGetSymbolAddress((void**)&loW, g_loW);

    const int WSZ2 = Dc * Dc / 2;          // packed u32 per W plane
    dim3 ggrid3(Dc / GBN, (Bc * Lc) / GBM, 3);  // (4, 64, 3)
    dim3 ggrid1(Dc / GBN, (Bc * Lc) / GBM, 1);
    int warps = Bc * Hc * Lc;

    // 0: merged presplit (4 W slices + 3 X tensors)
    presplit_all_kernel<<<1024 + 3 * 4096, 256>>>(Wq, Wk, Wv, Wo,
                                                  queries, keys, values);

    // 1: merged QKV projection GEMM
    bf16x2_gemm_kernel<<<ggrid3, 256>>>(hiX, loX, hiW, loW,
                                        bq, bk, bv, qp, kp, vp, 1);

    // 2: qk_sample + vmean1 (independent, overlapped in one launch)
    if (U == 40) {
        qk_vmean_kernel<40><<<8192 + 256, 256>>>(index_sample);
    } else {
        qk_sample_kernel<<<(warps * 32) / 256, 256>>>(index_sample, U);
        vmean1_kernel<<<256, 256>>>();
    }

    // 3 <- profiled: vmean2 + topk merged
    vmean2_topk_kernel<<<64, 256>>>(U);

    // 4: fill ctx planes with vmean broadcast
    fill_ctx_plane_kernel<<<NX / 2 / 256, 256>>>();

    // 5: sparse attention, scatter into ctx planes
    sparse_attn2_kernel<<<dim3(Bc * Hc, (U + 7) / 8), 256>>>(U);

    // 6: output projection
    bf16x2_gemm_kernel<<<ggrid1, 256>>>(hiX, loX, hiW + 3 * WSZ2,
                                        loW + 3 * WSZ2, bo, bo, bo,
                                        (float*)d_out, nullptr, nullptr, 0);
}

// round 17
// speedup vs baseline: 1.6600x; 1.0004x over previous
#include <cuda_runtime.h>
#include <cuda_bf16.h>
#include <math.h>
#include <stdint.h>

// Problem constants (fixed shapes for this bench)
constexpr int Bc  = 4;
constexpr int Lc  = 2048;
constexpr int Dc  = 512;
constexpr int Hc  = 8;
constexpr int DKc = 64;
constexpr int UMAX = 64;   // safety cap for top-k storage (actual U = 40)
constexpr int NX  = Bc * Lc * Dc;     // elements in one (B,L,D) tensor

// ---------------- scratch (device globals; no allocation allowed) ------------
__device__ float g_Q[Bc*Hc*Lc*DKc];      // (b,h,l,d)  16 MB
__device__ float g_K[Bc*Hc*Lc*DKc];      // 16 MB
__device__ float g_V[Bc*Hc*Lc*DKc];      // 16 MB
__device__ float g_M[Bc*Hc*Lc];          // sparsity measure
__device__ int   g_top[Bc*Hc*UMAX];      // top-u indices per (b,h)
__device__ float g_vmean[Bc*Hc*DKc];     // V mean over L
__device__ float g_vpart[Bc*Hc*8*DKc];   // partial V sums

// bf16 hi/lo planes, packed 2 consecutive-k bf16 per u32 (low half = even k)
// slot 0 doubles as the ctx planes for the output GEMM.
__device__ uint32_t g_hiX[3*NX/2], g_loX[3*NX/2];
__device__ uint32_t g_hiW[4*Dc*Dc/2], g_loW[4*Dc*Dc/2];

// ---------------- bf16 split helpers ------------------------------------------
__device__ __forceinline__ void split_pack2(float a, float b,
                                            uint32_t& hi, uint32_t& lo) {
    __nv_bfloat16 ha = __float2bfloat16_rn(a);
    __nv_bfloat16 hb = __float2bfloat16_rn(b);
    float ra = a - __bfloat162float(ha);
    float rb = b - __bfloat162float(hb);
    __nv_bfloat162 hv = __floats2bfloat162_rn(__bfloat162float(ha), __bfloat162float(hb));
    __nv_bfloat162 lv = __floats2bfloat162_rn(ra, rb);
    hi = *reinterpret_cast<uint32_t*>(&hv);
    lo = *reinterpret_cast<uint32_t*>(&lv);
}

__device__ __forceinline__ void mma_bf16(float (&d)[4], const uint32_t (&a)[4],
                                         const uint32_t (&b)[2]) {
    asm volatile(
        "mma.sync.aligned.m16n8k16.row.col.f32.bf16.bf16.f32 "
        "{%0,%1,%2,%3}, {%4,%5,%6,%7}, {%8,%9}, {%0,%1,%2,%3};"
        : "+f"(d[0]), "+f"(d[1]), "+f"(d[2]), "+f"(d[3])
        : "r"(a[0]), "r"(a[1]), "r"(a[2]), "r"(a[3]), "r"(b[0]), "r"(b[1]));
}

__device__ __forceinline__ void cp16(void* smem, const void* gmem) {
    uint32_t s = (uint32_t)__cvta_generic_to_shared(smem);
    asm volatile("cp.async.cg.shared.global [%0], [%1], 16;" :: "r"(s), "l"(gmem));
}
__device__ __forceinline__ void cp_commit() {
    asm volatile("cp.async.commit_group;" ::: "memory");
}
template<int N>
__device__ __forceinline__ void cp_wait() {
    asm volatile("cp.async.wait_group %0;" :: "n"(N) : "memory");
}

// ---------------- merged pre-split kernel --------------------------------------
// blocks [0, 1024): W planes (4 slots x 256 blocks over Dc*Dc/4 float4s)
// blocks [1024, 1024+3*4096): X planes (3 tensors x 4096 blocks over NX/4 float4s)
__global__ __launch_bounds__(256) void presplit_all_kernel(
    const float* __restrict__ w0, const float* __restrict__ w1,
    const float* __restrict__ w2, const float* __restrict__ w3,
    const float* __restrict__ x0, const float* __restrict__ x1,
    const float* __restrict__ x2)
{
    int bid = blockIdx.x;
    if (bid < 1024) {
        const float* srcs[4] = {w0, w1, w2, w3};
        int wsel = bid >> 8;
        int i = (bid & 255) * 256 + threadIdx.x;
        float4 v = reinterpret_cast<const float4*>(srcs[wsel])[i];
        uint32_t h0, l0, h1, l1;
        split_pack2(v.x, v.y, h0, l0);
        split_pack2(v.z, v.w, h1, l1);
        size_t o = (size_t)wsel * (Dc * Dc / 2) + (size_t)i * 2;
        g_hiW[o] = h0; g_hiW[o + 1] = h1;
        g_loW[o] = l0; g_loW[o + 1] = l1;
    } else {
        const float* srcs[3] = {x0, x1, x2};
        int rb = bid - 1024;
        int z = rb >> 12;            // /4096
        int i = (rb & 4095) * 256 + threadIdx.x;
        float4 v = reinterpret_cast<const float4*>(srcs[z])[i];
        uint32_t h0, l0, h1, l1;
        split_pack2(v.x, v.y, h0, l0);
        split_pack2(v.z, v.w, h1, l1);
        size_t o = (size_t)z * (NX / 2) + (size_t)i * 2;
        g_hiX[o] = h0; g_hiX[o + 1] = h1;
        g_loX[o] = l0; g_loX[o + 1] = l1;
    }
}

// ---------------- Split-bf16 GEMM, 128x128 block (R12 best) -------------------
// out_z = X_z[M,512] @ W_z[512,512]^T + bias_z    (z = blockIdx.z)
// acc += aL*bH + aH*bL + aH*bH (3 bf16 m16n8k16 MMAs).
// BM=128, BN=128, BK=16, 256 threads (8 warps, 4m x 2n), warp tile 32x64.
constexpr int GK  = 512;
constexpr int KW  = GK / 2;                    // 256 u32 per row (packed)
constexpr int GBM = 128, GBN = 128, GBK = 16;
constexpr int TW  = GBK / 2;                   // 8 u32 per row per tile
constexpr int LDW = 12;                        // padded row stride (conflict-free)
constexpr int A_SZ = GBM * LDW;                // 1536 u32
constexpr int W_SZ = GBN * LDW;                // 1536 u32

__global__ __launch_bounds__(256) void bf16x2_gemm_kernel(
    const uint32_t* __restrict__ hiX, const uint32_t* __restrict__ loX,
    const uint32_t* __restrict__ hiW, const uint32_t* __restrict__ loW,
    const float* __restrict__ b0, const float* __restrict__ b1,
    const float* __restrict__ b2,
    float* __restrict__ o0, float* __restrict__ o1, float* __restrict__ o2,
    int permute)
{
    __shared__ uint32_t AsH[2][A_SZ];
    __shared__ uint32_t AsL[2][A_SZ];
    __shared__ uint32_t WsH[2][W_SZ];
    __shared__ uint32_t WsL[2][W_SZ];

    const int z = blockIdx.z;
    const float* bias = (z == 0) ? b0 : (z == 1) ? b1 : b2;
    float* out = (z == 0) ? o0 : (z == 1) ? o1 : o2;

    const int tid  = threadIdx.x;
    const int warp = tid >> 5, lane = tid & 31;
    const int wm = warp & 3;        // 0..3 -> m offset (x32)
    const int wn = warp >> 2;       // 0..1 -> n offset (x64)
    const int m0 = blockIdx.y * GBM;
    const int n0 = blockIdx.x * GBN;
    const int gr = lane >> 2, gc = lane & 3;

    float acc[2][8][4];
    #pragma unroll
    for (int i = 0; i < 2; i++)
        #pragma unroll
        for (int j = 0; j < 8; j++)
            #pragma unroll
            for (int q = 0; q < 4; q++) acc[i][j][q] = 0.0f;

    // per-thread staging coords (packed u32 units); 2 cp16 each for A and W
    const int srow = tid >> 1, soff = (tid & 1) * 4;
    const uint32_t* AhP = hiX + (size_t)z * (NX / 2) + (size_t)(m0 + srow) * KW + soff;
    const uint32_t* AlP = loX + (size_t)z * (NX / 2) + (size_t)(m0 + srow) * KW + soff;
    const uint32_t* WhP = hiW + (size_t)z * (Dc * Dc / 2) + (size_t)(n0 + srow) * KW + soff;
    const uint32_t* WlP = loW + (size_t)z * (Dc * Dc / 2) + (size_t)(n0 + srow) * KW + soff;
    const int sidx = srow * LDW + soff;

    // stage tile 0 into buffer 0
    cp16(&AsH[0][sidx], AhP);
    cp16(&AsL[0][sidx], AlP);
    cp16(&WsH[0][sidx], WhP);
    cp16(&WsL[0][sidx], WlP);
    cp_commit();

    constexpr int NT = GK / GBK;   // 32 tiles
    for (int t = 0; t < NT; ++t) {
        const int buf = t & 1;
        if (t + 1 < NT) {
            const int o = (t + 1) * TW;
            cp16(&AsH[1 - buf][sidx], AhP + o);
            cp16(&AsL[1 - buf][sidx], AlP + o);
            cp16(&WsH[1 - buf][sidx], WhP + o);
            cp16(&WsL[1 - buf][sidx], WlP + o);
            cp_commit();
            cp_wait<1>();   // tile t landed; t+1 still streaming
        } else {
            cp_wait<0>();
        }
        __syncthreads();

        const uint32_t* aHs = AsH[buf];
        const uint32_t* aLs = AsL[buf];
        const uint32_t* wHs = WsH[buf];
        const uint32_t* wLs = WsL[buf];

        uint32_t aH[2][4], aL[2][4];
        #pragma unroll
        for (int ti = 0; ti < 2; ti++) {
            int mb = wm * 32 + ti * 16;
            int i0 = (mb + gr)     * LDW + gc;
            int i1 = (mb + gr + 8) * LDW + gc;
            aH[ti][0] = aHs[i0];     aH[ti][1] = aHs[i1];
            aH[ti][2] = aHs[i0 + 4]; aH[ti][3] = aHs[i1 + 4];
            aL[ti][0] = aLs[i0];     aL[ti][1] = aLs[i1];
            aL[ti][2] = aLs[i0 + 4]; aL[ti][3] = aLs[i1 + 4];
        }
        // tj processed in two halves of 4 to cap register pressure
        #pragma unroll
        for (int half = 0; half < 2; half++) {
            uint32_t bH[4][2], bL[4][2];
            #pragma unroll
            for (int tj = 0; tj < 4; tj++) {
                int nb = (wn * 64 + (half * 4 + tj) * 8 + gr) * LDW + gc;
                bH[tj][0] = wHs[nb]; bH[tj][1] = wHs[nb + 4];
                bL[tj][0] = wLs[nb]; bL[tj][1] = wLs[nb + 4];
            }
            #pragma unroll
            for (int ti = 0; ti < 2; ti++)
                #pragma unroll
                for (int tj = 0; tj < 4; tj++) {
                    mma_bf16(acc[ti][half * 4 + tj], aL[ti], bH[tj]);
                    mma_bf16(acc[ti][half * 4 + tj], aH[ti], bL[tj]);
                    mma_bf16(acc[ti][half * 4 + tj], aH[ti], bH[tj]);
                }
        }
        __syncthreads();
    }

    // ---- epilogue: bias + (optional) head permute, float2 stores ----
    #pragma unroll
    for (int ti = 0; ti < 2; ti++) {
        #pragma unroll
        for (int tj = 0; tj < 8; tj++) {
            int n = n0 + wn * 64 + tj * 8 + gc * 2;
            float bb0 = bias[n], bb1 = bias[n + 1];
            #pragma unroll
            for (int half = 0; half < 2; half++) {   // rows gr and gr+8
                int m = m0 + wm * 32 + ti * 16 + gr + half * 8;
                float2 v;
                v.x = acc[ti][tj][half * 2 + 0] + bb0;
                v.y = acc[ti][tj][half * 2 + 1] + bb1;
                if (!permute) {
                    *reinterpret_cast<float2*>(out + (size_t)m * Dc + n) = v;
                } else {
                    int b = m >> 11, l = m & 2047;
                    int h = n >> 6, d = n & 63;
                    *reinterpret_cast<float2*>(
                        out + (((size_t)(b * Hc + h)) * Lc + l) * DKc + d) = v;
                }
            }
        }
    }
}

// ---------------- merged QK_sample + vmean1 ------------------------------------
// blocks [0, 8192): qk_sample (warp per query, butterfly multi-reduce)
// blocks [8192, 8448): vmean1 (partial V sums)
template<int UT>
__global__ __launch_bounds__(256) void qk_vmean_kernel(const int* __restrict__ idxs)
{
    static_assert(UT > 32 && UT <= 64, "expects 32 < UT <= 64");
    const int bid = blockIdx.x;
    const int tid = threadIdx.x;

    if (bid >= 8192) {
        // ---- vmean1: partial sums over 256-row segments ----
        int blk = bid - 8192;             // 0..255
        int bh = blk >> 3, seg = blk & 7;
        int d = tid & 63, part = tid >> 6;
        const float* Vb = g_V + ((size_t)bh * Lc + seg * 256 + part * 64) * DKc;
        float acc = 0.0f;
        for (int l = 0; l < 64; ++l) acc += Vb[(size_t)l * 64 + d];
        __shared__ float red[256];
        red[tid] = acc;
        __syncthreads();
        if (part == 0)
            g_vpart[(bh * 8 + seg) * 64 + d] =
                red[d] + red[d + 64] + red[d + 128] + red[d + 192];
        return;
    }

    // ---- qk_sample ----
    int warp = (bid * 256 + tid) >> 5;
    int lane = tid & 31;
    int q  = warp % Lc;
    int bh = warp / Lc;

    const float* Qr = g_Q + ((size_t)bh * Lc + q) * 64;
    float q0 = Qr[lane], q1 = Qr[lane + 32];

    const int* ip = idxs + (size_t)q * UT;
    int idx0 = ip[lane];                                      // j = lane
    int idx1 = (lane < UT - 32) ? ip[32 + lane] : ip[UT - 1]; // pad dups last row

    const float* Kb = g_K + (size_t)bh * Lc * 64;

    float tot0, tot1;
    #pragma unroll
    for (int batch = 0; batch < 2; batch++) {
        int src = batch ? idx1 : idx0;
        float p[32];
        #pragma unroll
        for (int j = 0; j < 32; j++) {
            int ki = __shfl_sync(0xFFFFFFFFu, src, j);
            const float* Kr = Kb + (size_t)ki * 64;
            p[j] = fmaf(q0, Kr[lane], q1 * Kr[lane + 32]);
        }
        // xor-butterfly multi-reduce: lane ends with full sum of p[lane]
        #pragma unroll
        for (int o = 16; o >= 1; o >>= 1) {
            bool hi = (lane & o) != 0;
            #pragma unroll
            for (int j = 0; j < o; j++) {
                float a = p[j], b = p[j + o];
                float mine = hi ? b : a;
                float send = hi ? a : b;
                float theirs = __shfl_xor_sync(0xFFFFFFFFu, send, o);
                p[j] = mine + theirs;
            }
        }
        if (batch == 0) tot0 = p[0]; else tot1 = p[0];
    }

    bool v1 = (lane < UT - 32);
    float mx = fmaxf(tot0, v1 ? tot1 : -1e30f);
    float sm = tot0 + (v1 ? tot1 : 0.0f);
    #pragma unroll
    for (int o = 16; o > 0; o >>= 1) {
        mx = fmaxf(mx, __shfl_xor_sync(0xFFFFFFFFu, mx, o));
        sm += __shfl_xor_sync(0xFFFFFFFFu, sm, o);
    }
    if (lane == 0) g_M[(size_t)bh * Lc + q] = mx - sm * (1.0f / (float)Lc);
}

// generic fallback (runtime U) — qk only, vmean launched separately via same kernel
__global__ __launch_bounds__(256) void qk_sample_kernel(const int* __restrict__ idxs, int U)
{
    int warp = (blockIdx.x * blockDim.x + threadIdx.x) >> 5;
    int lane = threadIdx.x & 31;
    if (warp >= Bc * Hc * Lc) return;
    int q  = warp % Lc;
    int bh = warp / Lc;

    const float* Qr = g_Q + ((size_t)bh * Lc + q) * 64;
    float q0 = Qr[lane], q1 = Qr[lane + 32];

    float mx = -1e30f, sm = 0.0f;
    for (int j = 0; j < U; j++) {
        int ki = idxs[q * U + j];
        const float* Kr = g_K + ((size_t)bh * Lc + ki) * 64;
        float p = q0 * Kr[lane] + q1 * Kr[lane + 32];
        #pragma unroll
        for (int o = 16; o > 0; o >>= 1) p += __shfl_xor_sync(0xFFFFFFFFu, p, o);
        mx = fmaxf(mx, p);
        sm += p;
    }
    if (lane == 0) g_M[(size_t)bh * Lc + q] = mx - sm * (1.0f / (float)Lc);
}

__global__ __launch_bounds__(256) void vmean1_kernel()
{
    int blk = blockIdx.x;
    int bh = blk >> 3, seg = blk & 7;
    int tid = threadIdx.x;
    int d = tid & 63, part = tid >> 6;
    const float* Vb = g_V + ((size_t)bh * Lc + seg * 256 + part * 64) * DKc;
    float acc = 0.0f;
    for (int l = 0; l < 64; ++l) acc += Vb[(size_t)l * 64 + d];
    __shared__ float red[256];
    red[tid] = acc;
    __syncthreads();
    if (part == 0)
        g_vpart[(bh * 8 + seg) * 64 + d] =
            red[d] + red[d + 64] + red[d + 128] + red[d + 192];
}

// ---------------- merged vmean2 + top-U ----------------------------------------
// blocks [0, 32): topk per (b,h) — warp-shuffle argmax, 2 syncs/iteration
// blocks [32, 64): vmean2 (final V mean; threads < 64 active)
__global__ __launch_bounds__(256) void vmean2_topk_kernel(int U)
{
    const int bid = blockIdx.x;
    const int tid = threadIdx.x;

    if (bid >= 32) {
        int bh = bid - 32;
        if (tid < 64) {
            float s = 0.0f;
            #pragma unroll
            for (int i = 0; i < 8; i++) s += g_vpart[(bh * 8 + i) * 64 + tid];
            g_vmean[bh * 64 + tid] = s * (1.0f / Lc);
        }
        return;
    }

    const int bh = bid;
    const int warp = tid >> 5, lane = tid & 31;
    __shared__ float vals[Lc];
    __shared__ float wv[8];
    __shared__ int   wi[8];

    for (int i = tid; i < Lc; i += 256) vals[i] = g_M[(size_t)bh * Lc + i];
    __syncthreads();

    for (int it = 0; it < U; it++) {
        // per-thread scan of 8 strided elements
        float bv = -1e30f; int bi = Lc;
        #pragma unroll
        for (int c = 0; c < 8; c++) {
            int i = tid + c * 256;
            float v = vals[i];
            if (v > bv) { bv = v; bi = i; }
        }
        // warp argmax (tie: smaller index)
        #pragma unroll
        for (int o = 16; o > 0; o >>= 1) {
            float ov = __shfl_down_sync(0xFFFFFFFFu, bv, o);
            int   oi = __shfl_down_sync(0xFFFFFFFFu, bi, o);
            if (ov > bv || (ov == bv && oi < bi)) { bv = ov; bi = oi; }
        }
        if (lane == 0) { wv[warp] = bv; wi[warp] = bi; }
        __syncthreads();
        if (warp == 0) {
            float fv = (lane < 8) ? wv[lane] : -1e30f;
            int   fi = (lane < 8) ? wi[lane] : Lc;
            #pragma unroll
            for (int o = 4; o > 0; o >>= 1) {
                float ov = __shfl_down_sync(0xFFFFFFFFu, fv, o);
                int   oi = __shfl_down_sync(0xFFFFFFFFu, fi, o);
                if (ov > fv || (ov == fv && oi < fi)) { fv = ov; fi = oi; }
            }
            if (lane == 0) {
                g_top[bh * UMAX + it] = fi;
                vals[fi] = -1e30f;
            }
        }
        __syncthreads();
    }
}

// ---------------- fill ctx planes with bf16-split V-mean broadcast -----------
__global__ __launch_bounds__(256) void fill_ctx_plane_kernel()
{
    int p = blockIdx.x * 256 + threadIdx.x;   // over NX/2 packed units
    int m = p >> 8;            // row (256 u32 per row)
    int j = p & 255;           // packed col
    int b = m >> 11;
    int h = j >> 5;
    int d0 = (j & 31) * 2;
    const float* vm = g_vmean + (b * Hc + h) * 64;
    uint32_t hi, lo;
    split_pack2(vm[d0], vm[d0 + 1], hi, lo);
    g_hiX[p] = hi;
    g_loX[p] = lo;
}

// ---------------- flash-style attention for top-u queries (8 per block) ------
// writes results straight into the ctx bf16 planes (slot 0)
__global__ __launch_bounds__(256) void sparse_attn2_kernel(int U)
{
    int bh = blockIdx.x;
    int b  = bh >> 3, h = bh & 7;
    int tid = threadIdx.x, w = tid >> 5, lane = tid & 31;
    int ui = blockIdx.y * 8 + w;
    bool active = ui < U;
    int lq = active ? g_top[bh * UMAX + ui] : 0;

    __shared__ float qv[8][64];
    __shared__ float Ks[64][65];
    __shared__ float Vs[64][65];

    const float* Qr = g_Q + ((size_t)bh * Lc + lq) * 64;
    qv[w][lane]      = Qr[lane]      * 0.125f;   // 1/sqrt(64)
    qv[w][lane + 32] = Qr[lane + 32] * 0.125f;
    __syncthreads();

    float m = -1e30f, l = 0.0f, acc0 = 0.0f, acc1 = 0.0f;

    const float* Kb = g_K + (size_t)bh * Lc * 64;
    const float* Vb = g_V + (size_t)bh * Lc * 64;
    const int row = tid >> 2;           // 0..63
    const int cb  = (tid & 3) * 4;      // col base; strided +16

    for (int kc = 0; kc < Lc / 64; ++kc) {
        #pragma unroll
        for (int s = 0; s < 4; ++s) {
            int c = cb + s * 16;
            const float* kp = Kb + ((size_t)(kc * 64 + row)) * 64 + c;
            const float* vp = Vb + ((size_t)(kc * 64 + row)) * 64 + c;
            float4 kv = *reinterpret_cast<const float4*>(kp);
            float4 vv = *reinterpret_cast<const float4*>(vp);
            Ks[row][c] = kv.x; Ks[row][c+1] = kv.y; Ks[row][c+2] = kv.z; Ks[row][c+3] = kv.w;
            Vs[row][c] = vv.x; Vs[row][c+1] = vv.y; Vs[row][c+2] = vv.z; Vs[row][c+3] = vv.w;
        }
        __syncthreads();

        float s0 = 0.0f, s1 = 0.0f;
        #pragma unroll 16
        for (int c = 0; c < 64; ++c) {
            float qc = qv[w][c];
            s0 = fmaf(qc, Ks[lane][c],      s0);
            s1 = fmaf(qc, Ks[lane + 32][c], s1);
        }

        float cm = fmaxf(s0, s1);
        #pragma unroll
        for (int o = 16; o > 0; o >>= 1)
            cm = fmaxf(cm, __shfl_xor_sync(0xFFFFFFFFu, cm, o));
        float mn = fmaxf(m, cm);
        float corr = expf(m - mn);
        l *= corr; acc0 *= corr; acc1 *= corr;
        float p0 = expf(s0 - mn), p1 = expf(s1 - mn);
        float ps = p0 + p1;
        #pragma unroll
        for (int o = 16; o > 0; o >>= 1)
            ps += __shfl_xor_sync(0xFFFFFFFFu, ps, o);
        l += ps;
        m = mn;

        #pragma unroll 8
        for (int r = 0; r < 32; ++r) {
            float pa = __shfl_sync(0xFFFFFFFFu, p0, r);
            float pb = __shfl_sync(0xFFFFFFFFu, p1, r);
            acc0 = fmaf(pa, Vs[r][lane],           acc0);
            acc1 = fmaf(pa, Vs[r][lane + 32],      acc1);
            acc0 = fmaf(pb, Vs[r + 32][lane],      acc0);
            acc1 = fmaf(pb, Vs[r + 32][lane + 32], acc1);
        }
        __syncthreads();
    }

    if (active) {
        float inv = 1.0f / l;
        int srcA = (lane & 15) * 2, srcB = srcA + 1;
        float a0a = __shfl_sync(0xFFFFFFFFu, acc0, srcA);
        float a0b = __shfl_sync(0xFFFFFFFFu, acc0, srcB);
        float a1a = __shfl_sync(0xFFFFFFFFu, acc1, srcA);
        float a1b = __shfl_sync(0xFFFFFFFFu, acc1, srcB);
        float va = (lane < 16 ? a0a : a1a) * inv;
        float vb = (lane < 16 ? a0b : a1b) * inv;
        uint32_t hi, lo;
        split_pack2(va, vb, hi, lo);
        size_t idx = ((size_t)b * Lc + lq) * 256 + h * 32 + lane;
        g_hiX[idx] = hi;
        g_loX[idx] = lo;
    }
}

// ---------------- launch ------------------------------------------------------
extern "C" void kernel_launch(void* const* d_in, const int* in_sizes, int n_in,
                              void* d_out, int out_size)
{
    const float* queries = (const float*)d_in[0];
    const float* keys    = (const float*)d_in[1];
    const float* values  = (const float*)d_in[2];
    const float* Wq = (const float*)d_in[3];
    const float* bq = (const float*)d_in[4];
    const float* Wk = (const float*)d_in[5];
    const float* bk = (const float*)d_in[6];
    const float* Wv = (const float*)d_in[7];
    const float* bv = (const float*)d_in[8];
    const float* Wo = (const float*)d_in[9];
    const float* bo = (const float*)d_in[10];
    const int* index_sample = (const int*)d_in[11];

    int U = in_sizes[11] / Lc;   // 40 for this bench
    if (U > UMAX) U = UMAX;

    float *qp, *kp, *vp;
    cudaGetSymbolAddress((void**)&qp,  g_Q);
    cudaGetSymbolAddress((void**)&kp,  g_K);
    cudaGetSymbolAddress((void**)&vp,  g_V);
    uint32_t *hiX, *loX, *hiW, *loW;
    cudaGetSymbolAddress((void**)&hiX, g_hiX);
    cudaGetSymbolAddress((void**)&loX, g_loX);
    cudaGetSymbolAddress((void**)&hiW, g_hiW);
    cudaGetSymbolAddress((void**)&loW, g_loW);

    const int WSZ2 = Dc * Dc / 2;          // packed u32 per W plane
    dim3 ggrid3(Dc / GBN, (Bc * Lc) / GBM, 3);  // (4, 64, 3)
    dim3 ggrid1(Dc / GBN, (Bc * Lc) / GBM, 1);
    int warps = Bc * Hc * Lc;

    // 0: merged presplit (4 W slices + 3 X tensors)
    presplit_all_kernel<<<1024 + 3 * 4096, 256>>>(Wq, Wk, Wv, Wo,
                                                  queries, keys, values);

    // 1: merged QKV projection GEMM
    bf16x2_gemm_kernel<<<ggrid3, 256>>>(hiX, loX, hiW, loW,
                                        bq, bk, bv, qp, kp, vp, 1);

    // 2: qk_sample + vmean1 (independent, overlapped in one launch)
    if (U == 40) {
        qk_vmean_kernel<40><<<8192 + 256, 256>>>(index_sample);
    } else {
        qk_sample_kernel<<<(warps * 32) / 256, 256>>>(index_sample, U);
        vmean1_kernel<<<256, 256>>>();
    }

    // 3 <- profiled: vmean2 + topk merged
    vmean2_topk_kernel<<<64, 256>>>(U);

    // 4: fill ctx planes with vmean broadcast
    fill_ctx_plane_kernel<<<NX / 2 / 256, 256>>>();

    // 5: sparse attention, scatter into ctx planes
    sparse_attn2_kernel<<<dim3(Bc * Hc, (U + 7) / 8), 256>>>(U);

    // 6: output projection
    bf16x2_gemm_kernel<<<ggrid1, 256>>>(hiX, loX, hiW + 3 * WSZ2,
                                        loW + 3 * WSZ2, bo, bo, bo,
                                        (float*)d_out, nullptr, nullptr, 0);
}